// round 6
// baseline (speedup 1.0000x reference)
#include <cuda_runtime.h>
#include <cuda_bf16.h>
#include <cstdint>

// ---------------------------------------------------------------------------
// Problem constants
// ---------------------------------------------------------------------------
namespace {
constexpr int kB = 16;
constexpr int kT = 2048;
constexpr int kC = 1024;
constexpr int kH = 64;
constexpr int kRows = kB * kT;     // 32768
constexpr int kQT2 = kT / 128;     // 16 q-tiles (BM=128) per batch

// QKV GEMM smem (bytes): 144B-padded rows, K-chunk 64, double buffer
constexpr int G_AH = 0;            // 128 x 144
constexpr int G_AL = 18432;
constexpr int G_BH = 36864;        // 192 x 144
constexpr int G_BL = 64512;
constexpr int G_BUF = 92160;
constexpr int QKV_SMEM = 2 * G_BUF;          // 184320

// Attention smem (bytes): BM=128, 144B-padded rows
constexpr int APAD  = 144;
constexpr int A_QH  = 0;           // 128 x 144
constexpr int A_QL  = 18432;
constexpr int A_BUF = 36864;       // double-buffered K/V tiles (64 rows each)
constexpr int BK_KH = 0;
constexpr int BK_KL = 9216;
constexpr int BK_VH = 18432;
constexpr int BK_VL = 27648;
constexpr int ABUFSZ = 36864;
constexpr int ATTN_SMEM = A_BUF + 2 * ABUFSZ;  // 110592
}

// Scratch (__device__ globals: allocation-free)
__device__ float g_V[kRows * kH];
__device__ __nv_bfloat16 g_Qh[kRows * kH], g_Ql[kRows * kH];
__device__ __nv_bfloat16 g_Kh[kRows * kH], g_Kl[kRows * kH];
__device__ __nv_bfloat16 g_VTh[kB * kH * kT], g_VTl[kB * kH * kT];
__device__ __nv_bfloat16 g_Wt_hi[192 * 1024];
__device__ __nv_bfloat16 g_Wt_lo[192 * 1024];

// ---------------------------------------------------------------------------
// PTX helpers (baseline sm_80+ — survive compute_103 lowering)
// ---------------------------------------------------------------------------
__device__ __forceinline__ void mma16816(float* d, const uint32_t* a,
                                         const uint32_t* b) {
    asm volatile(
        "mma.sync.aligned.m16n8k16.row.col.f32.bf16.bf16.f32 "
        "{%0,%1,%2,%3}, {%4,%5,%6,%7}, {%8,%9}, {%0,%1,%2,%3};"
        : "+f"(d[0]), "+f"(d[1]), "+f"(d[2]), "+f"(d[3])
        : "r"(a[0]), "r"(a[1]), "r"(a[2]), "r"(a[3]), "r"(b[0]), "r"(b[1]));
}
// pack {lo, hi} floats into bf16x2 in ONE instruction (RN, same as before)
__device__ __forceinline__ uint32_t bf2pack(float lo, float hi) {
    uint32_t r;
    asm("cvt.rn.bf16x2.f32 %0, %1, %2;" : "=r"(r) : "f"(hi), "f"(lo));
    return r;
}
// residual pair given originals and their hi-pack (exact reconstruction)
__device__ __forceinline__ uint32_t bf2pack_lo(float lo, float hi, uint32_t hp) {
    const float rl = lo - __uint_as_float(hp << 16);
    const float rh = hi - __uint_as_float(hp & 0xffff0000u);
    return bf2pack(rl, rh);
}
__device__ __forceinline__ uint32_t smem_addr(const void* p) {
    return (uint32_t)__cvta_generic_to_shared(p);
}
#define CP_ASYNC16(dst, src) \
    asm volatile("cp.async.cg.shared.global [%0], [%1], 16;" \
                 :: "r"(dst), "l"(src))
#define CP_COMMIT() asm volatile("cp.async.commit_group;" ::: "memory")
#define CP_WAIT0()  asm volatile("cp.async.wait_group 0;" ::: "memory")
#define CP_WAIT1()  asm volatile("cp.async.wait_group 1;" ::: "memory")

// ---------------------------------------------------------------------------
// Prep: W[k][n] fp32 -> Wt[n'][k] bf16 hi/lo
// ---------------------------------------------------------------------------
__global__ void wprep_kernel(const float* __restrict__ Wq,
                             const float* __restrict__ Wk,
                             const float* __restrict__ Wv) {
    const int idx = blockIdx.x * 256 + threadIdx.x;
    const int np = idx >> 10, k = idx & 1023;
    const int mat = np >> 6, n = np & 63;
    const float* W = (mat == 0) ? Wq : (mat == 1) ? Wk : Wv;
    const float v = W[k * 64 + n];
    const __nv_bfloat16 h = __float2bfloat16(v);
    g_Wt_hi[idx] = h;
    g_Wt_lo[idx] = __float2bfloat16(v - __bfloat162float(h));
}

// ---------------------------------------------------------------------------
// QKV GEMM: 3-term bf16 split HMMA. CTA 128x192, 512 threads (16 warps,
// warp tile 32x48). K-chunk 64, double buffer; W staged via cp.async,
// X staged LDG->convert->STS. Epilogue writes Q(bf16,hi/lo, pre-scaled 1/8),
// K(bf16 hi/lo), V(fp32).
// ---------------------------------------------------------------------------
__global__ __launch_bounds__(512, 1)
void qkv_mma_kernel(const float* __restrict__ x,
                    const float* __restrict__ bq,
                    const float* __restrict__ bk,
                    const float* __restrict__ bv) {
    extern __shared__ __align__(16) char sm[];
    const int tid  = threadIdx.x;
    const int lane = tid & 31;
    const int w    = tid >> 5;
    const int m0   = (w >> 2) * 32;
    const int n0   = (w & 3) * 48;
    const int r1   = lane >> 2;
    const int kq   = lane & 3;
    const int row0 = blockIdx.x * 128;

    float acc[2][6][4];
#pragma unroll
    for (int mf = 0; mf < 2; ++mf)
#pragma unroll
        for (int nf = 0; nf < 6; ++nf)
#pragma unroll
            for (int i = 0; i < 4; ++i) acc[mf][nf][i] = 0.f;

    float4 xr[4];

    auto ldg_x = [&](int k0) {
#pragma unroll
        for (int it = 0; it < 4; ++it) {
            const int e4 = tid + it * 512;          // 2048 float4 = 128 x 16
            const int m = e4 >> 4, k4 = (e4 & 15) * 4;
            xr[it] = *reinterpret_cast<const float4*>(
                &x[(size_t)(row0 + m) * kC + k0 + k4]);
        }
    };
    auto cp_w = [&](int k0, char* buf) {
#pragma unroll
        for (int it = 0; it < 3; ++it) {
            const int g = tid + it * 512;           // 1536 x 16B per matrix
            const int n = g >> 3, c = g & 7;
            CP_ASYNC16(smem_addr(buf + G_BH + n * 144 + c * 16),
                       (const char*)(g_Wt_hi + n * 1024 + k0) + c * 16);
            CP_ASYNC16(smem_addr(buf + G_BL + n * 144 + c * 16),
                       (const char*)(g_Wt_lo + n * 1024 + k0) + c * 16);
        }
    };
    auto sts_x = [&](char* buf) {
#pragma unroll
        for (int it = 0; it < 4; ++it) {
            const int e4 = tid + it * 512;
            const int m = e4 >> 4, k4 = (e4 & 15) * 4;
            const float4 v = xr[it];
            uint2 hv, lv;
            hv.x = bf2pack(v.x, v.y);
            hv.y = bf2pack(v.z, v.w);
            lv.x = bf2pack_lo(v.x, v.y, hv.x);
            lv.y = bf2pack_lo(v.z, v.w, hv.y);
            *reinterpret_cast<uint2*>(buf + G_AH + m * 144 + k4 * 2) = hv;
            *reinterpret_cast<uint2*>(buf + G_AL + m * 144 + k4 * 2) = lv;
        }
    };

    ldg_x(0);
    cp_w(0, sm);
    CP_COMMIT();
    sts_x(sm);
    CP_WAIT0();
    __syncthreads();

    for (int ch = 0; ch < 16; ++ch) {
        char* buf = sm + (ch & 1) * G_BUF;
        if (ch + 1 < 16) {
            ldg_x((ch + 1) * 64);
            cp_w((ch + 1) * 64, sm + ((ch + 1) & 1) * G_BUF);
        }
        CP_COMMIT();

#pragma unroll
        for (int ks = 0; ks < 4; ++ks) {
            const int kko = ks * 32;
            uint32_t ah[2][4], al[2][4];
#pragma unroll
            for (int mf = 0; mf < 2; ++mf) {
                const int base = (m0 + mf * 16 + r1) * 144 + kko + kq * 4;
                const char* A = buf + G_AH;
                ah[mf][0] = *reinterpret_cast<const uint32_t*>(A + base);
                ah[mf][1] = *reinterpret_cast<const uint32_t*>(A + base + 8 * 144);
                ah[mf][2] = *reinterpret_cast<const uint32_t*>(A + base + 16);
                ah[mf][3] = *reinterpret_cast<const uint32_t*>(A + base + 8 * 144 + 16);
                const char* L = buf + G_AL;
                al[mf][0] = *reinterpret_cast<const uint32_t*>(L + base);
                al[mf][1] = *reinterpret_cast<const uint32_t*>(L + base + 8 * 144);
                al[mf][2] = *reinterpret_cast<const uint32_t*>(L + base + 16);
                al[mf][3] = *reinterpret_cast<const uint32_t*>(L + base + 8 * 144 + 16);
            }
#pragma unroll
            for (int half = 0; half < 2; ++half) {
                uint32_t bh[3][2], bl[3][2];
#pragma unroll
                for (int i = 0; i < 3; ++i) {
                    const int nf = half * 3 + i;
                    const int bb = (n0 + nf * 8 + r1) * 144 + kko + kq * 4;
                    bh[i][0] = *reinterpret_cast<const uint32_t*>(buf + G_BH + bb);
                    bh[i][1] = *reinterpret_cast<const uint32_t*>(buf + G_BH + bb + 16);
                    bl[i][0] = *reinterpret_cast<const uint32_t*>(buf + G_BL + bb);
                    bl[i][1] = *reinterpret_cast<const uint32_t*>(buf + G_BL + bb + 16);
                }
#pragma unroll
                for (int mf = 0; mf < 2; ++mf)
#pragma unroll
                    for (int i = 0; i < 3; ++i) {
                        const int nf = half * 3 + i;
                        mma16816(acc[mf][nf], ah[mf], bh[i]);
                        mma16816(acc[mf][nf], ah[mf], bl[i]);
                        mma16816(acc[mf][nf], al[mf], bh[i]);
                    }
            }
        }

        if (ch + 1 < 16) {
            __syncthreads();
            sts_x(sm + ((ch + 1) & 1) * G_BUF);
            CP_WAIT0();
            __syncthreads();
        }
    }

    // ---- epilogue ----
#pragma unroll
    for (int mf = 0; mf < 2; ++mf) {
        const int rg = row0 + m0 + mf * 16 + r1;
#pragma unroll
        for (int nf = 0; nf < 6; ++nf) {
            const int col = n0 + nf * 8 + kq * 2;
            const int mat = col >> 6, h = col & 63;
            const float* bias = (mat == 0) ? bq : (mat == 1) ? bk : bv;
            const float b0 = bias[h], b1 = bias[h + 1];
            const float v00 = acc[mf][nf][0] + b0;
            const float v01 = acc[mf][nf][1] + b1;
            const float v10 = acc[mf][nf][2] + b0;
            const float v11 = acc[mf][nf][3] + b1;
            if (mat == 2) {
                float2 a = {v00, v01}, bvv = {v10, v11};
                *reinterpret_cast<float2*>(g_V + (size_t)rg * kH + h) = a;
                *reinterpret_cast<float2*>(g_V + (size_t)(rg + 8) * kH + h) = bvv;
            } else {
                const float scl = (mat == 0) ? 0.125f : 1.0f;  // fold softmax scale
                __nv_bfloat16* Ah = (mat == 0) ? g_Qh : g_Kh;
                __nv_bfloat16* Al = (mat == 0) ? g_Ql : g_Kl;
                const uint32_t h0 = bf2pack(v00 * scl, v01 * scl);
                const uint32_t h1 = bf2pack(v10 * scl, v11 * scl);
                *reinterpret_cast<uint32_t*>(Ah + (size_t)rg * kH + h) = h0;
                *reinterpret_cast<uint32_t*>(Al + (size_t)rg * kH + h) =
                    bf2pack_lo(v00 * scl, v01 * scl, h0);
                *reinterpret_cast<uint32_t*>(Ah + (size_t)(rg + 8) * kH + h) = h1;
                *reinterpret_cast<uint32_t*>(Al + (size_t)(rg + 8) * kH + h) =
                    bf2pack_lo(v10 * scl, v11 * scl, h1);
            }
        }
    }
}

// ---------------------------------------------------------------------------
// V transpose + bf16 split: g_V [b][t][h] fp32 -> g_VTh/g_VTl [b][h][t]
// ---------------------------------------------------------------------------
__global__ __launch_bounds__(256)
void vtrans_kernel() {
    __shared__ float tile[64][65];
    const int blk = blockIdx.x;            // kB * 32
    const int b = blk >> 5, t0 = (blk & 31) * 64;
    const int tid = threadIdx.x;
    const float* src = g_V + ((size_t)b * kT + t0) * kH;
#pragma unroll
    for (int i = 0; i < 16; ++i) {
        const int idx = tid + i * 256;
        tile[idx >> 6][idx & 63] = src[idx];
    }
    __syncthreads();
#pragma unroll
    for (int i = 0; i < 8; ++i) {
        const int idx = tid + i * 256;     // 2048 bf16x2 pairs
        const int h = idx >> 5, tp = (idx & 31) * 2;
        const float v0 = tile[tp][h], v1 = tile[tp + 1][h];
        const size_t off = ((size_t)b * kH + h) * kT + t0 + tp;
        const uint32_t hp = bf2pack(v0, v1);
        *reinterpret_cast<uint32_t*>(g_VTh + off) = hp;
        *reinterpret_cast<uint32_t*>(g_VTl + off) = bf2pack_lo(v0, v1, hp);
    }
}

// ---------------------------------------------------------------------------
// Causal flash attention: BM=128, 128 threads = 4 warps, warp tile m32 x n64.
// 3-term bf16-split HMMA, cp.async double-buffered K/V (64-row tiles),
// P packed register-direct from accumulator frags.
// ---------------------------------------------------------------------------
__global__ __launch_bounds__(128, 2)
void attn_mma_kernel(float* __restrict__ out) {
    extern __shared__ __align__(16) char sma[];
    char* Qh = sma + A_QH;
    char* Ql = sma + A_QL;

    const int tid  = threadIdx.x;
    const int lane = tid & 31;
    const int w    = tid >> 5;
    const int b    = blockIdx.x & 15;
    const int qtile = (kQT2 - 1) - (blockIdx.x >> 4);   // heaviest first
    const int q0   = qtile * 128;
    const int jmax = 2 * qtile + 1;
    const int m0w  = w * 32;
    const int r1   = lane >> 2;
    const int kq   = lane & 3;

    // ---- load Q tile once (pre-converted, pre-scaled bf16 hi/lo) ----
    {
        const char* qh = (const char*)(g_Qh + ((size_t)b * kT + q0) * kH);
        const char* ql = (const char*)(g_Ql + ((size_t)b * kT + q0) * kH);
#pragma unroll
        for (int i = 0; i < 8; ++i) {
            const int idx = tid + i * 128;         // 1024 x 16B per matrix
            const int r = idx >> 3, c = (idx & 7) * 16;
            *reinterpret_cast<uint4*>(Qh + r * APAD + c) =
                *reinterpret_cast<const uint4*>(qh + idx * 16);
            *reinterpret_cast<uint4*>(Ql + r * APAD + c) =
                *reinterpret_cast<const uint4*>(ql + idx * 16);
        }
    }

    auto stage = [&](int jt, char* buf) {
        const int j0 = jt * 64;
        const char* kh = (const char*)(g_Kh + ((size_t)b * kT + j0) * kH);
        const char* kl = (const char*)(g_Kl + ((size_t)b * kT + j0) * kH);
#pragma unroll
        for (int i = 0; i < 4; ++i) {
            const int idx = tid + i * 128;         // 512 x 16B per matrix
            const int r = idx >> 3, c = (idx & 7) * 16;
            CP_ASYNC16(smem_addr(buf + BK_KH + r * APAD + c), kh + idx * 16);
            CP_ASYNC16(smem_addr(buf + BK_KL + r * APAD + c), kl + idx * 16);
        }
        const char* vh = (const char*)(g_VTh + (size_t)b * kH * kT + j0);
        const char* vl = (const char*)(g_VTl + (size_t)b * kH * kT + j0);
#pragma unroll
        for (int i = 0; i < 4; ++i) {
            const int idx = tid + i * 128;
            const int r = idx >> 3, c = (idx & 7) * 16;  // r = h row
            CP_ASYNC16(smem_addr(buf + BK_VH + r * APAD + c),
                       vh + (size_t)r * kT * 2 + c);
            CP_ASYNC16(smem_addr(buf + BK_VL + r * APAD + c),
                       vl + (size_t)r * kT * 2 + c);
        }
    };

    float o[2][8][4];
#pragma unroll
    for (int mf = 0; mf < 2; ++mf)
#pragma unroll
        for (int nf = 0; nf < 8; ++nf)
#pragma unroll
            for (int c = 0; c < 4; ++c) o[mf][nf][c] = 0.f;
    float mrow[2][2] = {{-1e30f, -1e30f}, {-1e30f, -1e30f}};
    float lrow[2][2] = {{0.f, 0.f}, {0.f, 0.f}};

    stage(0, sma + A_BUF);
    CP_COMMIT();

    for (int jt = 0; jt <= jmax; ++jt) {
        if (jt + 1 <= jmax) stage(jt + 1, sma + A_BUF + ((jt + 1) & 1) * ABUFSZ);
        CP_COMMIT();
        CP_WAIT1();
        __syncthreads();

        char* buf = sma + A_BUF + (jt & 1) * ABUFSZ;
        char* Kh = buf + BK_KH;
        char* Kl = buf + BK_KL;
        char* Vh = buf + BK_VH;
        char* Vl = buf + BK_VL;
        const int j0 = jt * 64;

        // ---- S = Q K^T (Q pre-scaled; 3-term split) ----
        float s[2][8][4];
#pragma unroll
        for (int mf = 0; mf < 2; ++mf)
#pragma unroll
            for (int nf = 0; nf < 8; ++nf)
#pragma unroll
                for (int c = 0; c < 4; ++c) s[mf][nf][c] = 0.f;

#pragma unroll
        for (int ks = 0; ks < 4; ++ks) {
            const int kko = ks * 32;
            uint32_t ah[2][4], al[2][4];
#pragma unroll
            for (int mf = 0; mf < 2; ++mf) {
                const int abase = (m0w + mf * 16 + r1) * APAD + kko + kq * 4;
                ah[mf][0] = *reinterpret_cast<const uint32_t*>(Qh + abase);
                ah[mf][1] = *reinterpret_cast<const uint32_t*>(Qh + abase + 8 * APAD);
                ah[mf][2] = *reinterpret_cast<const uint32_t*>(Qh + abase + 16);
                ah[mf][3] = *reinterpret_cast<const uint32_t*>(Qh + abase + 8 * APAD + 16);
                al[mf][0] = *reinterpret_cast<const uint32_t*>(Ql + abase);
                al[mf][1] = *reinterpret_cast<const uint32_t*>(Ql + abase + 8 * APAD);
                al[mf][2] = *reinterpret_cast<const uint32_t*>(Ql + abase + 16);
                al[mf][3] = *reinterpret_cast<const uint32_t*>(Ql + abase + 8 * APAD + 16);
            }
#pragma unroll
            for (int nf = 0; nf < 8; ++nf) {
                const int bbase = (nf * 8 + r1) * APAD + kko + kq * 4;
                uint32_t bh[2], bl[2];
                bh[0] = *reinterpret_cast<const uint32_t*>(Kh + bbase);
                bh[1] = *reinterpret_cast<const uint32_t*>(Kh + bbase + 16);
                bl[0] = *reinterpret_cast<const uint32_t*>(Kl + bbase);
                bl[1] = *reinterpret_cast<const uint32_t*>(Kl + bbase + 16);
#pragma unroll
                for (int mf = 0; mf < 2; ++mf) {
                    mma16816(s[mf][nf], ah[mf], bh);
                    mma16816(s[mf][nf], ah[mf], bl);
                    mma16816(s[mf][nf], al[mf], bh);
                }
            }
        }

        // ---- causal mask + online softmax (per m-frag, independent chains) ----
#pragma unroll
        for (int mf = 0; mf < 2; ++mf) {
            const int qg1 = q0 + m0w + mf * 16 + r1;
            const int qg2 = qg1 + 8;
            if (j0 + 63 > q0 + m0w + mf * 16) {   // tile can cross this frag's diagonal
#pragma unroll
                for (int nf = 0; nf < 8; ++nf) {
                    const int kg0 = j0 + nf * 8 + kq * 2;
                    s[mf][nf][0] = (kg0     <= qg1) ? s[mf][nf][0] : -1e30f;
                    s[mf][nf][1] = (kg0 + 1 <= qg1) ? s[mf][nf][1] : -1e30f;
                    s[mf][nf][2] = (kg0     <= qg2) ? s[mf][nf][2] : -1e30f;
                    s[mf][nf][3] = (kg0 + 1 <= qg2) ? s[mf][nf][3] : -1e30f;
                }
            }
            float mx1 = -1e30f, mx2 = -1e30f;
#pragma unroll
            for (int nf = 0; nf < 8; ++nf) {
                mx1 = fmaxf(mx1, fmaxf(s[mf][nf][0], s[mf][nf][1]));
                mx2 = fmaxf(mx2, fmaxf(s[mf][nf][2], s[mf][nf][3]));
            }
            mx1 = fmaxf(mx1, __shfl_xor_sync(0xffffffffu, mx1, 1));
            mx1 = fmaxf(mx1, __shfl_xor_sync(0xffffffffu, mx1, 2));
            mx2 = fmaxf(mx2, __shfl_xor_sync(0xffffffffu, mx2, 1));
            mx2 = fmaxf(mx2, __shfl_xor_sync(0xffffffffu, mx2, 2));

            const float mn1 = fmaxf(mrow[mf][0], mx1);
            const float mn2 = fmaxf(mrow[mf][1], mx2);
            const float a1 = __expf(mrow[mf][0] - mn1);
            const float a2 = __expf(mrow[mf][1] - mn2);
            mrow[mf][0] = mn1; mrow[mf][1] = mn2;

            float rs1 = 0.f, rs2 = 0.f;
#pragma unroll
            for (int nf = 0; nf < 8; ++nf) {
                s[mf][nf][0] = __expf(s[mf][nf][0] - mn1);
                s[mf][nf][1] = __expf(s[mf][nf][1] - mn1);
                s[mf][nf][2] = __expf(s[mf][nf][2] - mn2);
                s[mf][nf][3] = __expf(s[mf][nf][3] - mn2);
                rs1 += s[mf][nf][0] + s[mf][nf][1];
                rs2 += s[mf][nf][2] + s[mf][nf][3];
            }
            rs1 += __shfl_xor_sync(0xffffffffu, rs1, 1);
            rs1 += __shfl_xor_sync(0xffffffffu, rs1, 2);
            rs2 += __shfl_xor_sync(0xffffffffu, rs2, 1);
            rs2 += __shfl_xor_sync(0xffffffffu, rs2, 2);
            lrow[mf][0] = lrow[mf][0] * a1 + rs1;
            lrow[mf][1] = lrow[mf][1] * a2 + rs2;
#pragma unroll
            for (int nf = 0; nf < 8; ++nf) {
                o[mf][nf][0] *= a1; o[mf][nf][1] *= a1;
                o[mf][nf][2] *= a2; o[mf][nf][3] *= a2;
            }
        }

        // ---- O += P V (P packed register-direct) ----
#pragma unroll
        for (int ks = 0; ks < 4; ++ks) {
            uint32_t pah[2][4], pal[2][4];
#pragma unroll
            for (int mf = 0; mf < 2; ++mf) {
                const float* s0 = s[mf][2 * ks];
                const float* s1 = s[mf][2 * ks + 1];
                pah[mf][0] = bf2pack(s0[0], s0[1]);
                pah[mf][1] = bf2pack(s0[2], s0[3]);
                pah[mf][2] = bf2pack(s1[0], s1[1]);
                pah[mf][3] = bf2pack(s1[2], s1[3]);
                pal[mf][0] = bf2pack_lo(s0[0], s0[1], pah[mf][0]);
                pal[mf][1] = bf2pack_lo(s0[2], s0[3], pah[mf][1]);
                pal[mf][2] = bf2pack_lo(s1[0], s1[1], pah[mf][2]);
                pal[mf][3] = bf2pack_lo(s1[2], s1[3], pah[mf][3]);
            }
#pragma unroll
            for (int nf = 0; nf < 8; ++nf) {
                const int bbase = (nf * 8 + r1) * APAD + ks * 32 + kq * 4;
                uint32_t vh2[2], vl2[2];
                vh2[0] = *reinterpret_cast<const uint32_t*>(Vh + bbase);
                vh2[1] = *reinterpret_cast<const uint32_t*>(Vh + bbase + 16);
                vl2[0] = *reinterpret_cast<const uint32_t*>(Vl + bbase);
                vl2[1] = *reinterpret_cast<const uint32_t*>(Vl + bbase + 16);
#pragma unroll
                for (int mf = 0; mf < 2; ++mf) {
                    mma16816(o[mf][nf], pah[mf], vh2);
                    mma16816(o[mf][nf], pah[mf], vl2);
                    mma16816(o[mf][nf], pal[mf], vh2);
                }
            }
        }
        __syncthreads();   // readers of this buffer done before it is re-staged
    }

    // ---- epilogue: normalize + store ----
#pragma unroll
    for (int mf = 0; mf < 2; ++mf) {
        const float inv1 = 1.0f / lrow[mf][0];
        const float inv2 = 1.0f / lrow[mf][1];
        float* og = out + ((size_t)b * kT + q0 + m0w + mf * 16) * kH;
#pragma unroll
        for (int nf = 0; nf < 8; ++nf) {
            const int col = nf * 8 + kq * 2;
            float2 v0, v1;
            v0.x = o[mf][nf][0] * inv1; v0.y = o[mf][nf][1] * inv1;
            v1.x = o[mf][nf][2] * inv2; v1.y = o[mf][nf][3] * inv2;
            *reinterpret_cast<float2*>(&og[r1 * kH + col]) = v0;
            *reinterpret_cast<float2*>(&og[(r1 + 8) * kH + col]) = v1;
        }
    }
}

// ---------------------------------------------------------------------------
extern "C" void kernel_launch(void* const* d_in, const int* in_sizes, int n_in,
                              void* d_out, int out_size) {
    (void)in_sizes; (void)n_in; (void)out_size;
    const float* x  = (const float*)d_in[0];
    const float* Wq = (const float*)d_in[1];
    const float* bq = (const float*)d_in[2];
    const float* Wk = (const float*)d_in[3];
    const float* bk = (const float*)d_in[4];
    const float* Wv = (const float*)d_in[5];
    const float* bv = (const float*)d_in[6];
    float* out = (float*)d_out;

    wprep_kernel<<<(192 * 1024) / 256, 256>>>(Wq, Wk, Wv);

    cudaFuncSetAttribute(qkv_mma_kernel, cudaFuncAttributeMaxDynamicSharedMemorySize,
                         QKV_SMEM);
    qkv_mma_kernel<<<kRows / 128, 512, QKV_SMEM>>>(x, bq, bk, bv);

    vtrans_kernel<<<kB * 32, 256>>>();

    cudaFuncSetAttribute(attn_mma_kernel, cudaFuncAttributeMaxDynamicSharedMemorySize,
                         ATTN_SMEM);
    attn_mma_kernel<<<kB * kQT2, 128, ATTN_SMEM>>>(out);
}

// round 7
// speedup vs baseline: 1.1338x; 1.1338x over previous
#include <cuda_runtime.h>
#include <cuda_bf16.h>
#include <cstdint>

// ---------------------------------------------------------------------------
// Problem constants
// ---------------------------------------------------------------------------
namespace {
constexpr int kB = 16;
constexpr int kT = 2048;
constexpr int kC = 1024;
constexpr int kH = 64;
constexpr int kRows = kB * kT;     // 32768
constexpr int kQT = kT / 64;       // 32 q-tiles per batch

// QKV GEMM smem (bytes): 144B-padded rows, K-chunk 64, double buffer
constexpr int G_AH = 0;            // 128 x 144
constexpr int G_AL = 18432;
constexpr int G_BH = 36864;        // 192 x 144
constexpr int G_BL = 64512;
constexpr int G_BUF = 92160;
constexpr int QKV_SMEM = 2 * G_BUF;          // 184320

// Attention smem (bytes): swizzled 128B rows, BM=64
constexpr int A_QH  = 0;           // 64 x 128 (Q hi only; Q lo in regs)
constexpr int A_BUF = 8192;        // double-buffered K/V tiles
constexpr int BK_KH = 0;
constexpr int BK_KL = 8192;
constexpr int BK_VH = 16384;
constexpr int BK_VL = 24576;
constexpr int ABUFSZ = 32768;
constexpr int ATTN_SMEM = A_BUF + 2 * ABUFSZ;  // 73728 -> 3 CTAs/SM
}

// Scratch (__device__ globals: allocation-free)
__device__ float g_V[kRows * kH];
__device__ __nv_bfloat16 g_Qh[kRows * kH], g_Ql[kRows * kH];
__device__ __nv_bfloat16 g_Kh[kRows * kH], g_Kl[kRows * kH];
__device__ __nv_bfloat16 g_VTh[kB * kH * kT], g_VTl[kB * kH * kT];
__device__ __nv_bfloat16 g_Wt_hi[192 * 1024];
__device__ __nv_bfloat16 g_Wt_lo[192 * 1024];

// ---------------------------------------------------------------------------
// PTX helpers (baseline sm_80+ — survive compute_103 lowering)
// ---------------------------------------------------------------------------
__device__ __forceinline__ void mma16816(float* d, const uint32_t* a,
                                         const uint32_t* b) {
    asm volatile(
        "mma.sync.aligned.m16n8k16.row.col.f32.bf16.bf16.f32 "
        "{%0,%1,%2,%3}, {%4,%5,%6,%7}, {%8,%9}, {%0,%1,%2,%3};"
        : "+f"(d[0]), "+f"(d[1]), "+f"(d[2]), "+f"(d[3])
        : "r"(a[0]), "r"(a[1]), "r"(a[2]), "r"(a[3]), "r"(b[0]), "r"(b[1]));
}
__device__ __forceinline__ uint32_t bf2pack(float lo, float hi) {
    uint32_t r;
    asm("cvt.rn.bf16x2.f32 %0, %1, %2;" : "=r"(r) : "f"(hi), "f"(lo));
    return r;
}
__device__ __forceinline__ uint32_t bf2pack_lo(float lo, float hi, uint32_t hp) {
    const float rl = lo - __uint_as_float(hp << 16);
    const float rh = hi - __uint_as_float(hp & 0xffff0000u);
    return bf2pack(rl, rh);
}
__device__ __forceinline__ uint32_t smem_addr(const void* p) {
    return (uint32_t)__cvta_generic_to_shared(p);
}
#define CP_ASYNC16(dst, src) \
    asm volatile("cp.async.cg.shared.global [%0], [%1], 16;" \
                 :: "r"(dst), "l"(src))
#define CP_COMMIT() asm volatile("cp.async.commit_group;" ::: "memory")
#define CP_WAIT0()  asm volatile("cp.async.wait_group 0;" ::: "memory")
#define CP_WAIT1()  asm volatile("cp.async.wait_group 1;" ::: "memory")

// swizzled 128B-row address: (row, 16B-chunk, byte-within-chunk)
__device__ __forceinline__ uint32_t swz(int row, int chunk, int within) {
    return row * 128 + ((chunk ^ (row & 7)) * 16) + within;
}

// ---------------------------------------------------------------------------
// Prep: W[k][n] fp32 -> Wt[n'][k] bf16 hi/lo
// ---------------------------------------------------------------------------
__global__ void wprep_kernel(const float* __restrict__ Wq,
                             const float* __restrict__ Wk,
                             const float* __restrict__ Wv) {
    const int idx = blockIdx.x * 256 + threadIdx.x;
    const int np = idx >> 10, k = idx & 1023;
    const int mat = np >> 6, n = np & 63;
    const float* W = (mat == 0) ? Wq : (mat == 1) ? Wk : Wv;
    const float v = W[k * 64 + n];
    const __nv_bfloat16 h = __float2bfloat16(v);
    g_Wt_hi[idx] = h;
    g_Wt_lo[idx] = __float2bfloat16(v - __bfloat162float(h));
}

// ---------------------------------------------------------------------------
// QKV GEMM (R6-validated, ~105us). Q pre-scaled by 0.125*log2(e) for the
// exp2-domain softmax.
// ---------------------------------------------------------------------------
__global__ __launch_bounds__(512, 1)
void qkv_mma_kernel(const float* __restrict__ x,
                    const float* __restrict__ bq,
                    const float* __restrict__ bk,
                    const float* __restrict__ bv) {
    extern __shared__ __align__(16) char sm[];
    const int tid  = threadIdx.x;
    const int lane = tid & 31;
    const int w    = tid >> 5;
    const int m0   = (w >> 2) * 32;
    const int n0   = (w & 3) * 48;
    const int r1   = lane >> 2;
    const int kq   = lane & 3;
    const int row0 = blockIdx.x * 128;

    float acc[2][6][4];
#pragma unroll
    for (int mf = 0; mf < 2; ++mf)
#pragma unroll
        for (int nf = 0; nf < 6; ++nf)
#pragma unroll
            for (int i = 0; i < 4; ++i) acc[mf][nf][i] = 0.f;

    float4 xr[4];

    auto ldg_x = [&](int k0) {
#pragma unroll
        for (int it = 0; it < 4; ++it) {
            const int e4 = tid + it * 512;
            const int m = e4 >> 4, k4 = (e4 & 15) * 4;
            xr[it] = *reinterpret_cast<const float4*>(
                &x[(size_t)(row0 + m) * kC + k0 + k4]);
        }
    };
    auto cp_w = [&](int k0, char* buf) {
#pragma unroll
        for (int it = 0; it < 3; ++it) {
            const int g = tid + it * 512;
            const int n = g >> 3, c = g & 7;
            CP_ASYNC16(smem_addr(buf + G_BH + n * 144 + c * 16),
                       (const char*)(g_Wt_hi + n * 1024 + k0) + c * 16);
            CP_ASYNC16(smem_addr(buf + G_BL + n * 144 + c * 16),
                       (const char*)(g_Wt_lo + n * 1024 + k0) + c * 16);
        }
    };
    auto sts_x = [&](char* buf) {
#pragma unroll
        for (int it = 0; it < 4; ++it) {
            const int e4 = tid + it * 512;
            const int m = e4 >> 4, k4 = (e4 & 15) * 4;
            const float4 v = xr[it];
            uint2 hv, lv;
            hv.x = bf2pack(v.x, v.y);
            hv.y = bf2pack(v.z, v.w);
            lv.x = bf2pack_lo(v.x, v.y, hv.x);
            lv.y = bf2pack_lo(v.z, v.w, hv.y);
            *reinterpret_cast<uint2*>(buf + G_AH + m * 144 + k4 * 2) = hv;
            *reinterpret_cast<uint2*>(buf + G_AL + m * 144 + k4 * 2) = lv;
        }
    };

    ldg_x(0);
    cp_w(0, sm);
    CP_COMMIT();
    sts_x(sm);
    CP_WAIT0();
    __syncthreads();

    for (int ch = 0; ch < 16; ++ch) {
        char* buf = sm + (ch & 1) * G_BUF;
        if (ch + 1 < 16) {
            ldg_x((ch + 1) * 64);
            cp_w((ch + 1) * 64, sm + ((ch + 1) & 1) * G_BUF);
        }
        CP_COMMIT();

#pragma unroll
        for (int ks = 0; ks < 4; ++ks) {
            const int kko = ks * 32;
            uint32_t ah[2][4], al[2][4];
#pragma unroll
            for (int mf = 0; mf < 2; ++mf) {
                const int base = (m0 + mf * 16 + r1) * 144 + kko + kq * 4;
                const char* A = buf + G_AH;
                ah[mf][0] = *reinterpret_cast<const uint32_t*>(A + base);
                ah[mf][1] = *reinterpret_cast<const uint32_t*>(A + base + 8 * 144);
                ah[mf][2] = *reinterpret_cast<const uint32_t*>(A + base + 16);
                ah[mf][3] = *reinterpret_cast<const uint32_t*>(A + base + 8 * 144 + 16);
                const char* L = buf + G_AL;
                al[mf][0] = *reinterpret_cast<const uint32_t*>(L + base);
                al[mf][1] = *reinterpret_cast<const uint32_t*>(L + base + 8 * 144);
                al[mf][2] = *reinterpret_cast<const uint32_t*>(L + base + 16);
                al[mf][3] = *reinterpret_cast<const uint32_t*>(L + base + 8 * 144 + 16);
            }
#pragma unroll
            for (int half = 0; half < 2; ++half) {
                uint32_t bh[3][2], bl[3][2];
#pragma unroll
                for (int i = 0; i < 3; ++i) {
                    const int nf = half * 3 + i;
                    const int bb = (n0 + nf * 8 + r1) * 144 + kko + kq * 4;
                    bh[i][0] = *reinterpret_cast<const uint32_t*>(buf + G_BH + bb);
                    bh[i][1] = *reinterpret_cast<const uint32_t*>(buf + G_BH + bb + 16);
                    bl[i][0] = *reinterpret_cast<const uint32_t*>(buf + G_BL + bb);
                    bl[i][1] = *reinterpret_cast<const uint32_t*>(buf + G_BL + bb + 16);
                }
#pragma unroll
                for (int mf = 0; mf < 2; ++mf)
#pragma unroll
                    for (int i = 0; i < 3; ++i) {
                        const int nf = half * 3 + i;
                        mma16816(acc[mf][nf], ah[mf], bh[i]);
                        mma16816(acc[mf][nf], ah[mf], bl[i]);
                        mma16816(acc[mf][nf], al[mf], bh[i]);
                    }
            }
        }

        if (ch + 1 < 16) {
            __syncthreads();
            sts_x(sm + ((ch + 1) & 1) * G_BUF);
            CP_WAIT0();
            __syncthreads();
        }
    }

    // ---- epilogue ----
#pragma unroll
    for (int mf = 0; mf < 2; ++mf) {
        const int rg = row0 + m0 + mf * 16 + r1;
#pragma unroll
        for (int nf = 0; nf < 6; ++nf) {
            const int col = n0 + nf * 8 + kq * 2;
            const int mat = col >> 6, h = col & 63;
            const float* bias = (mat == 0) ? bq : (mat == 1) ? bk : bv;
            const float b0 = bias[h], b1 = bias[h + 1];
            const float v00 = acc[mf][nf][0] + b0;
            const float v01 = acc[mf][nf][1] + b1;
            const float v10 = acc[mf][nf][2] + b0;
            const float v11 = acc[mf][nf][3] + b1;
            if (mat == 2) {
                float2 a = {v00, v01}, bvv = {v10, v11};
                *reinterpret_cast<float2*>(g_V + (size_t)rg * kH + h) = a;
                *reinterpret_cast<float2*>(g_V + (size_t)(rg + 8) * kH + h) = bvv;
            } else {
                // Q: fold softmax scale AND log2(e) (exp2-domain softmax)
                const float scl = (mat == 0) ? 0.125f * 1.44269504f : 1.0f;
                __nv_bfloat16* Ah = (mat == 0) ? g_Qh : g_Kh;
                __nv_bfloat16* Al = (mat == 0) ? g_Ql : g_Kl;
                const uint32_t h0 = bf2pack(v00 * scl, v01 * scl);
                const uint32_t h1 = bf2pack(v10 * scl, v11 * scl);
                *reinterpret_cast<uint32_t*>(Ah + (size_t)rg * kH + h) = h0;
                *reinterpret_cast<uint32_t*>(Al + (size_t)rg * kH + h) =
                    bf2pack_lo(v00 * scl, v01 * scl, h0);
                *reinterpret_cast<uint32_t*>(Ah + (size_t)(rg + 8) * kH + h) = h1;
                *reinterpret_cast<uint32_t*>(Al + (size_t)(rg + 8) * kH + h) =
                    bf2pack_lo(v10 * scl, v11 * scl, h1);
            }
        }
    }
}

// ---------------------------------------------------------------------------
// V transpose + bf16 split
// ---------------------------------------------------------------------------
__global__ __launch_bounds__(256)
void vtrans_kernel() {
    __shared__ float tile[64][65];
    const int blk = blockIdx.x;
    const int b = blk >> 5, t0 = (blk & 31) * 64;
    const int tid = threadIdx.x;
    const float* src = g_V + ((size_t)b * kT + t0) * kH;
#pragma unroll
    for (int i = 0; i < 16; ++i) {
        const int idx = tid + i * 256;
        tile[idx >> 6][idx & 63] = src[idx];
    }
    __syncthreads();
#pragma unroll
    for (int i = 0; i < 8; ++i) {
        const int idx = tid + i * 256;
        const int h = idx >> 5, tp = (idx & 31) * 2;
        const float v0 = tile[tp][h], v1 = tile[tp + 1][h];
        const size_t off = ((size_t)b * kH + h) * kT + t0 + tp;
        const uint32_t hp = bf2pack(v0, v1);
        *reinterpret_cast<uint32_t*>(g_VTh + off) = hp;
        *reinterpret_cast<uint32_t*>(g_VTl + off) = bf2pack_lo(v0, v1, hp);
    }
}

// ---------------------------------------------------------------------------
// Causal flash attention: BM=64, 4 warps, occ-3 (swizzled smem, Q-lo in regs,
// exp2-domain softmax). 3-term bf16-split HMMA, cp.async double buffer.
// ---------------------------------------------------------------------------
__global__ __launch_bounds__(128, 3)
void attn_mma_kernel(float* __restrict__ out) {
    extern __shared__ __align__(16) char sma[];
    char* Qh = sma + A_QH;

    const int tid  = threadIdx.x;
    const int lane = tid & 31;
    const int w    = tid >> 5;
    const int b    = blockIdx.x & 15;
    const int qt   = (kQT - 1) - (blockIdx.x >> 4);   // heaviest first
    const int q0   = qt * 64;
    const int m0w  = w * 16;
    const int r1   = lane >> 2;
    const int kq   = lane & 3;

    // ---- Q-hi tile -> swizzled smem ----
    {
        const char* qh = (const char*)(g_Qh + ((size_t)b * kT + q0) * kH);
#pragma unroll
        for (int i = 0; i < 4; ++i) {
            const int idx = tid + i * 128;         // 512 x 16B
            const int r = idx >> 3, c = idx & 7;
            *reinterpret_cast<uint4*>(Qh + swz(r, c, 0)) =
                *reinterpret_cast<const uint4*>(qh + idx * 16);
        }
    }

    // ---- Q-lo fragments -> registers (loaded once from gmem) ----
    uint32_t qlo[4][4];
    {
        const __nv_bfloat16* ql = g_Ql + ((size_t)b * kT + q0) * kH;
        const int rowA = m0w + r1, rowB = rowA + 8;
#pragma unroll
        for (int ks = 0; ks < 4; ++ks) {
            const int k0 = ks * 16 + kq * 2;
            qlo[ks][0] = *reinterpret_cast<const uint32_t*>(ql + rowA * kH + k0);
            qlo[ks][1] = *reinterpret_cast<const uint32_t*>(ql + rowB * kH + k0);
            qlo[ks][2] = *reinterpret_cast<const uint32_t*>(ql + rowA * kH + k0 + 8);
            qlo[ks][3] = *reinterpret_cast<const uint32_t*>(ql + rowB * kH + k0 + 8);
        }
    }

    auto stage = [&](int jt, char* buf) {
        const int j0 = jt * 64;
        const char* kh = (const char*)(g_Kh + ((size_t)b * kT + j0) * kH);
        const char* kl = (const char*)(g_Kl + ((size_t)b * kT + j0) * kH);
#pragma unroll
        for (int i = 0; i < 4; ++i) {
            const int idx = tid + i * 128;
            const int r = idx >> 3, c = idx & 7;
            const uint32_t d = swz(r, c, 0);
            CP_ASYNC16(smem_addr(buf + BK_KH + d), kh + idx * 16);
            CP_ASYNC16(smem_addr(buf + BK_KL + d), kl + idx * 16);
        }
        const char* vh = (const char*)(g_VTh + (size_t)b * kH * kT + j0);
        const char* vl = (const char*)(g_VTl + (size_t)b * kH * kT + j0);
#pragma unroll
        for (int i = 0; i < 4; ++i) {
            const int idx = tid + i * 128;
            const int r = idx >> 3, c = idx & 7;      // r = h row
            const uint32_t d = swz(r, c, 0);
            CP_ASYNC16(smem_addr(buf + BK_VH + d), vh + (size_t)r * kT * 2 + c * 16);
            CP_ASYNC16(smem_addr(buf + BK_VL + d), vl + (size_t)r * kT * 2 + c * 16);
        }
    };

    float o[8][4];
#pragma unroll
    for (int nf = 0; nf < 8; ++nf)
#pragma unroll
        for (int c = 0; c < 4; ++c) o[nf][c] = 0.f;
    float mrow[2] = {-1e30f, -1e30f};
    float lrow[2] = {0.f, 0.f};

    stage(0, sma + A_BUF);
    CP_COMMIT();

    for (int jt = 0; jt <= qt; ++jt) {
        if (jt + 1 <= qt) stage(jt + 1, sma + A_BUF + ((jt + 1) & 1) * ABUFSZ);
        CP_COMMIT();
        CP_WAIT1();
        __syncthreads();

        char* buf = sma + A_BUF + (jt & 1) * ABUFSZ;
        char* Kh = buf + BK_KH;
        char* Kl = buf + BK_KL;
        char* Vh = buf + BK_VH;
        char* Vl = buf + BK_VL;

        // ---- S = Q K^T (Q pre-scaled by 0.125*log2e; 3-term split) ----
        float s[8][4];
#pragma unroll
        for (int nf = 0; nf < 8; ++nf)
#pragma unroll
            for (int c = 0; c < 4; ++c) s[nf][c] = 0.f;

#pragma unroll
        for (int ks = 0; ks < 4; ++ks) {
            uint32_t ah[4];
            ah[0] = *reinterpret_cast<const uint32_t*>(Qh + swz(m0w + r1,     ks * 2,     kq * 4));
            ah[1] = *reinterpret_cast<const uint32_t*>(Qh + swz(m0w + 8 + r1, ks * 2,     kq * 4));
            ah[2] = *reinterpret_cast<const uint32_t*>(Qh + swz(m0w + r1,     ks * 2 + 1, kq * 4));
            ah[3] = *reinterpret_cast<const uint32_t*>(Qh + swz(m0w + 8 + r1, ks * 2 + 1, kq * 4));
#pragma unroll
            for (int nf = 0; nf < 8; ++nf) {
                const int row = nf * 8 + r1;
                uint32_t bh[2], bl[2];
                bh[0] = *reinterpret_cast<const uint32_t*>(Kh + swz(row, ks * 2,     kq * 4));
                bh[1] = *reinterpret_cast<const uint32_t*>(Kh + swz(row, ks * 2 + 1, kq * 4));
                bl[0] = *reinterpret_cast<const uint32_t*>(Kl + swz(row, ks * 2,     kq * 4));
                bl[1] = *reinterpret_cast<const uint32_t*>(Kl + swz(row, ks * 2 + 1, kq * 4));
                mma16816(s[nf], ah, bh);
                mma16816(s[nf], ah, bl);
                mma16816(s[nf], qlo[ks], bh);
            }
        }

        // ---- causal mask (diagonal tile only) + online softmax (exp2) ----
        float mx1 = -1e30f, mx2 = -1e30f;
        if (jt == qt) {
            const int qg1 = q0 + m0w + r1;
            const int qg2 = qg1 + 8;
#pragma unroll
            for (int nf = 0; nf < 8; ++nf) {
                const int kg0 = jt * 64 + nf * 8 + kq * 2;
                s[nf][0] = (kg0     <= qg1) ? s[nf][0] : -1e30f;
                s[nf][1] = (kg0 + 1 <= qg1) ? s[nf][1] : -1e30f;
                s[nf][2] = (kg0     <= qg2) ? s[nf][2] : -1e30f;
                s[nf][3] = (kg0 + 1 <= qg2) ? s[nf][3] : -1e30f;
            }
        }
#pragma unroll
        for (int nf = 0; nf < 8; ++nf) {
            mx1 = fmaxf(mx1, fmaxf(s[nf][0], s[nf][1]));
            mx2 = fmaxf(mx2, fmaxf(s[nf][2], s[nf][3]));
        }
        mx1 = fmaxf(mx1, __shfl_xor_sync(0xffffffffu, mx1, 1));
        mx1 = fmaxf(mx1, __shfl_xor_sync(0xffffffffu, mx1, 2));
        mx2 = fmaxf(mx2, __shfl_xor_sync(0xffffffffu, mx2, 1));
        mx2 = fmaxf(mx2, __shfl_xor_sync(0xffffffffu, mx2, 2));

        const float mn1 = fmaxf(mrow[0], mx1);
        const float mn2 = fmaxf(mrow[1], mx2);
        const float a1 = exp2f(mrow[0] - mn1);
        const float a2 = exp2f(mrow[1] - mn2);
        mrow[0] = mn1; mrow[1] = mn2;

        float rs1 = 0.f, rs2 = 0.f;
#pragma unroll
        for (int nf = 0; nf < 8; ++nf) {
            s[nf][0] = exp2f(s[nf][0] - mn1);
            s[nf][1] = exp2f(s[nf][1] - mn1);
            s[nf][2] = exp2f(s[nf][2] - mn2);
            s[nf][3] = exp2f(s[nf][3] - mn2);
            rs1 += s[nf][0] + s[nf][1];
            rs2 += s[nf][2] + s[nf][3];
        }
        rs1 += __shfl_xor_sync(0xffffffffu, rs1, 1);
        rs1 += __shfl_xor_sync(0xffffffffu, rs1, 2);
        rs2 += __shfl_xor_sync(0xffffffffu, rs2, 1);
        rs2 += __shfl_xor_sync(0xffffffffu, rs2, 2);
        lrow[0] = lrow[0] * a1 + rs1;
        lrow[1] = lrow[1] * a2 + rs2;
#pragma unroll
        for (int nf = 0; nf < 8; ++nf) {
            o[nf][0] *= a1; o[nf][1] *= a1;
            o[nf][2] *= a2; o[nf][3] *= a2;
        }

        // ---- O += P V (P packed register-direct) ----
#pragma unroll
        for (int ks = 0; ks < 4; ++ks) {
            uint32_t pah[4], pal[4];
            const float* s0 = s[2 * ks];
            const float* s1 = s[2 * ks + 1];
            pah[0] = bf2pack(s0[0], s0[1]);
            pah[1] = bf2pack(s0[2], s0[3]);
            pah[2] = bf2pack(s1[0], s1[1]);
            pah[3] = bf2pack(s1[2], s1[3]);
            pal[0] = bf2pack_lo(s0[0], s0[1], pah[0]);
            pal[1] = bf2pack_lo(s0[2], s0[3], pah[1]);
            pal[2] = bf2pack_lo(s1[0], s1[1], pah[2]);
            pal[3] = bf2pack_lo(s1[2], s1[3], pah[3]);
#pragma unroll
            for (int nf = 0; nf < 8; ++nf) {
                const int row = nf * 8 + r1;
                uint32_t vh2[2], vl2[2];
                vh2[0] = *reinterpret_cast<const uint32_t*>(Vh + swz(row, ks * 2,     kq * 4));
                vh2[1] = *reinterpret_cast<const uint32_t*>(Vh + swz(row, ks * 2 + 1, kq * 4));
                vl2[0] = *reinterpret_cast<const uint32_t*>(Vl + swz(row, ks * 2,     kq * 4));
                vl2[1] = *reinterpret_cast<const uint32_t*>(Vl + swz(row, ks * 2 + 1, kq * 4));
                mma16816(o[nf], pah, vh2);
                mma16816(o[nf], pah, vl2);
                mma16816(o[nf], pal, vh2);
            }
        }
        __syncthreads();   // readers of this buffer done before it is re-staged
    }

    // ---- epilogue: normalize + store ----
    const float inv1 = 1.0f / lrow[0];
    const float inv2 = 1.0f / lrow[1];
    float* og = out + ((size_t)b * kT + q0 + m0w) * kH;
#pragma unroll
    for (int nf = 0; nf < 8; ++nf) {
        const int col = nf * 8 + kq * 2;
        float2 v0, v1;
        v0.x = o[nf][0] * inv1; v0.y = o[nf][1] * inv1;
        v1.x = o[nf][2] * inv2; v1.y = o[nf][3] * inv2;
        *reinterpret_cast<float2*>(&og[r1 * kH + col]) = v0;
        *reinterpret_cast<float2*>(&og[(r1 + 8) * kH + col]) = v1;
    }
}

// ---------------------------------------------------------------------------
extern "C" void kernel_launch(void* const* d_in, const int* in_sizes, int n_in,
                              void* d_out, int out_size) {
    (void)in_sizes; (void)n_in; (void)out_size;
    const float* x  = (const float*)d_in[0];
    const float* Wq = (const float*)d_in[1];
    const float* bq = (const float*)d_in[2];
    const float* Wk = (const float*)d_in[3];
    const float* bk = (const float*)d_in[4];
    const float* Wv = (const float*)d_in[5];
    const float* bv = (const float*)d_in[6];
    float* out = (float*)d_out;

    wprep_kernel<<<(192 * 1024) / 256, 256>>>(Wq, Wk, Wv);

    cudaFuncSetAttribute(qkv_mma_kernel, cudaFuncAttributeMaxDynamicSharedMemorySize,
                         QKV_SMEM);
    qkv_mma_kernel<<<kRows / 128, 512, QKV_SMEM>>>(x, bq, bk, bv);

    vtrans_kernel<<<kB * 32, 256>>>();

    cudaFuncSetAttribute(attn_mma_kernel, cudaFuncAttributeMaxDynamicSharedMemorySize,
                         ATTN_SMEM);
    attn_mma_kernel<<<kB * kQT, 128, ATTN_SMEM>>>(out);
}

// round 8
// speedup vs baseline: 1.1816x; 1.0422x over previous
#include <cuda_runtime.h>
#include <cuda_bf16.h>
#include <cstdint>

// ---------------------------------------------------------------------------
// Problem constants
// ---------------------------------------------------------------------------
namespace {
constexpr int kB = 16;
constexpr int kT = 2048;
constexpr int kC = 1024;
constexpr int kH = 64;
constexpr int kRows = kB * kT;     // 32768
constexpr int kQT = kT / 64;       // 32 q-tiles per batch

// QKV GEMM smem (bytes): 144B-padded rows, K-chunk 64, double buffer
constexpr int G_AH = 0;            // 128 x 144
constexpr int G_AL = 18432;
constexpr int G_BH = 36864;        // 192 x 144
constexpr int G_BL = 64512;
constexpr int G_BUF = 92160;
constexpr int QKV_SMEM = 2 * G_BUF;          // 184320

// Attention smem (bytes): fragment-major contiguous tiles, no Q in smem
constexpr int BK_KH = 0;
constexpr int BK_KL = 8192;
constexpr int BK_VH = 16384;
constexpr int BK_VL = 24576;
constexpr int ABUFSZ = 32768;
constexpr int ATTN_SMEM = 2 * ABUFSZ;        // 65536 -> 3 CTAs/SM
}

// Scratch (__device__ globals: allocation-free)
__device__ float g_V[kRows * kH];
__device__ __nv_bfloat16 g_Qh[kRows * kH], g_Ql[kRows * kH];
// K and V^T in FRAGMENT-MAJOR order: per (batch, jt-tile) an 8KB blob of
// 32 fragment blocks [(nf*4+ks)], each 256B = lane-ordered {b0,b1} u32 pairs.
__device__ __nv_bfloat16 g_KFh[kRows * kH], g_KFl[kRows * kH];
__device__ __nv_bfloat16 g_VFh[kRows * kH], g_VFl[kRows * kH];
__device__ __nv_bfloat16 g_Wt_hi[192 * 1024];
__device__ __nv_bfloat16 g_Wt_lo[192 * 1024];

// ---------------------------------------------------------------------------
// PTX helpers (baseline sm_80+ — survive compute_103 lowering)
// ---------------------------------------------------------------------------
__device__ __forceinline__ void mma16816(float* d, const uint32_t* a,
                                         const uint32_t* b) {
    asm volatile(
        "mma.sync.aligned.m16n8k16.row.col.f32.bf16.bf16.f32 "
        "{%0,%1,%2,%3}, {%4,%5,%6,%7}, {%8,%9}, {%0,%1,%2,%3};"
        : "+f"(d[0]), "+f"(d[1]), "+f"(d[2]), "+f"(d[3])
        : "r"(a[0]), "r"(a[1]), "r"(a[2]), "r"(a[3]), "r"(b[0]), "r"(b[1]));
}
__device__ __forceinline__ uint32_t bf2pack(float lo, float hi) {
    uint32_t r;
    asm("cvt.rn.bf16x2.f32 %0, %1, %2;" : "=r"(r) : "f"(hi), "f"(lo));
    return r;
}
__device__ __forceinline__ uint32_t bf2pack_lo(float lo, float hi, uint32_t hp) {
    const float rl = lo - __uint_as_float(hp << 16);
    const float rh = hi - __uint_as_float(hp & 0xffff0000u);
    return bf2pack(rl, rh);
}
__device__ __forceinline__ uint32_t smem_addr(const void* p) {
    return (uint32_t)__cvta_generic_to_shared(p);
}
#define CP_ASYNC16(dst, src) \
    asm volatile("cp.async.cg.shared.global [%0], [%1], 16;" \
                 :: "r"(dst), "l"(src))
#define CP_COMMIT() asm volatile("cp.async.commit_group;" ::: "memory")
#define CP_WAIT0()  asm volatile("cp.async.wait_group 0;" ::: "memory")
#define CP_WAIT1()  asm volatile("cp.async.wait_group 1;" ::: "memory")

// Fragment-major u32-word index for a (k,k+1) bf16 pair of matrix element
// [token tok (within batch), col h] viewed as an MMA B-operand.
__device__ __forceinline__ int bfrag_idx(int batch, int tok, int h) {
    const int jt = tok >> 6, nf = (tok >> 3) & 7, r = tok & 7;
    const int ks = h >> 4, sel = (h >> 3) & 1, q2 = (h >> 1) & 3;
    return (((batch * 32 + jt) * 32) + nf * 4 + ks) * 64 + (r * 4 + q2) * 2 + sel;
}

// ---------------------------------------------------------------------------
// Prep: W[k][n] fp32 -> Wt[n'][k] bf16 hi/lo
// ---------------------------------------------------------------------------
__global__ void wprep_kernel(const float* __restrict__ Wq,
                             const float* __restrict__ Wk,
                             const float* __restrict__ Wv) {
    const int idx = blockIdx.x * 256 + threadIdx.x;
    const int np = idx >> 10, k = idx & 1023;
    const int mat = np >> 6, n = np & 63;
    const float* W = (mat == 0) ? Wq : (mat == 1) ? Wk : Wv;
    const float v = W[k * 64 + n];
    const __nv_bfloat16 h = __float2bfloat16(v);
    g_Wt_hi[idx] = h;
    g_Wt_lo[idx] = __float2bfloat16(v - __bfloat162float(h));
}

// ---------------------------------------------------------------------------
// QKV GEMM (R6-validated mainloop, ~105us). Epilogue:
//   Q -> row-major bf16 hi/lo, pre-scaled by 0.125*log2(e)
//   K -> FRAGMENT-MAJOR bf16 hi/lo (g_KFh/g_KFl)
//   V -> fp32 row-major (vtrans permutes)
// ---------------------------------------------------------------------------
__global__ __launch_bounds__(512, 1)
void qkv_mma_kernel(const float* __restrict__ x,
                    const float* __restrict__ bq,
                    const float* __restrict__ bk,
                    const float* __restrict__ bv) {
    extern __shared__ __align__(16) char sm[];
    const int tid  = threadIdx.x;
    const int lane = tid & 31;
    const int w    = tid >> 5;
    const int m0   = (w >> 2) * 32;
    const int n0   = (w & 3) * 48;
    const int r1   = lane >> 2;
    const int kq   = lane & 3;
    const int row0 = blockIdx.x * 128;

    float acc[2][6][4];
#pragma unroll
    for (int mf = 0; mf < 2; ++mf)
#pragma unroll
        for (int nf = 0; nf < 6; ++nf)
#pragma unroll
            for (int i = 0; i < 4; ++i) acc[mf][nf][i] = 0.f;

    float4 xr[4];

    auto ldg_x = [&](int k0) {
#pragma unroll
        for (int it = 0; it < 4; ++it) {
            const int e4 = tid + it * 512;
            const int m = e4 >> 4, k4 = (e4 & 15) * 4;
            xr[it] = *reinterpret_cast<const float4*>(
                &x[(size_t)(row0 + m) * kC + k0 + k4]);
        }
    };
    auto cp_w = [&](int k0, char* buf) {
#pragma unroll
        for (int it = 0; it < 3; ++it) {
            const int g = tid + it * 512;
            const int n = g >> 3, c = g & 7;
            CP_ASYNC16(smem_addr(buf + G_BH + n * 144 + c * 16),
                       (const char*)(g_Wt_hi + n * 1024 + k0) + c * 16);
            CP_ASYNC16(smem_addr(buf + G_BL + n * 144 + c * 16),
                       (const char*)(g_Wt_lo + n * 1024 + k0) + c * 16);
        }
    };
    auto sts_x = [&](char* buf) {
#pragma unroll
        for (int it = 0; it < 4; ++it) {
            const int e4 = tid + it * 512;
            const int m = e4 >> 4, k4 = (e4 & 15) * 4;
            const float4 v = xr[it];
            uint2 hv, lv;
            hv.x = bf2pack(v.x, v.y);
            hv.y = bf2pack(v.z, v.w);
            lv.x = bf2pack_lo(v.x, v.y, hv.x);
            lv.y = bf2pack_lo(v.z, v.w, hv.y);
            *reinterpret_cast<uint2*>(buf + G_AH + m * 144 + k4 * 2) = hv;
            *reinterpret_cast<uint2*>(buf + G_AL + m * 144 + k4 * 2) = lv;
        }
    };

    ldg_x(0);
    cp_w(0, sm);
    CP_COMMIT();
    sts_x(sm);
    CP_WAIT0();
    __syncthreads();

    for (int ch = 0; ch < 16; ++ch) {
        char* buf = sm + (ch & 1) * G_BUF;
        if (ch + 1 < 16) {
            ldg_x((ch + 1) * 64);
            cp_w((ch + 1) * 64, sm + ((ch + 1) & 1) * G_BUF);
        }
        CP_COMMIT();

#pragma unroll
        for (int ks = 0; ks < 4; ++ks) {
            const int kko = ks * 32;
            uint32_t ah[2][4], al[2][4];
#pragma unroll
            for (int mf = 0; mf < 2; ++mf) {
                const int base = (m0 + mf * 16 + r1) * 144 + kko + kq * 4;
                const char* A = buf + G_AH;
                ah[mf][0] = *reinterpret_cast<const uint32_t*>(A + base);
                ah[mf][1] = *reinterpret_cast<const uint32_t*>(A + base + 8 * 144);
                ah[mf][2] = *reinterpret_cast<const uint32_t*>(A + base + 16);
                ah[mf][3] = *reinterpret_cast<const uint32_t*>(A + base + 8 * 144 + 16);
                const char* L = buf + G_AL;
                al[mf][0] = *reinterpret_cast<const uint32_t*>(L + base);
                al[mf][1] = *reinterpret_cast<const uint32_t*>(L + base + 8 * 144);
                al[mf][2] = *reinterpret_cast<const uint32_t*>(L + base + 16);
                al[mf][3] = *reinterpret_cast<const uint32_t*>(L + base + 8 * 144 + 16);
            }
#pragma unroll
            for (int half = 0; half < 2; ++half) {
                uint32_t bh[3][2], bl[3][2];
#pragma unroll
                for (int i = 0; i < 3; ++i) {
                    const int nf = half * 3 + i;
                    const int bb = (n0 + nf * 8 + r1) * 144 + kko + kq * 4;
                    bh[i][0] = *reinterpret_cast<const uint32_t*>(buf + G_BH + bb);
                    bh[i][1] = *reinterpret_cast<const uint32_t*>(buf + G_BH + bb + 16);
                    bl[i][0] = *reinterpret_cast<const uint32_t*>(buf + G_BL + bb);
                    bl[i][1] = *reinterpret_cast<const uint32_t*>(buf + G_BL + bb + 16);
                }
#pragma unroll
                for (int mf = 0; mf < 2; ++mf)
#pragma unroll
                    for (int i = 0; i < 3; ++i) {
                        const int nf = half * 3 + i;
                        mma16816(acc[mf][nf], ah[mf], bh[i]);
                        mma16816(acc[mf][nf], ah[mf], bl[i]);
                        mma16816(acc[mf][nf], al[mf], bh[i]);
                    }
            }
        }

        if (ch + 1 < 16) {
            __syncthreads();
            sts_x(sm + ((ch + 1) & 1) * G_BUF);
            CP_WAIT0();
            __syncthreads();
        }
    }

    // ---- epilogue ----
    uint32_t* KFh = reinterpret_cast<uint32_t*>(g_KFh);
    uint32_t* KFl = reinterpret_cast<uint32_t*>(g_KFl);
#pragma unroll
    for (int mf = 0; mf < 2; ++mf) {
        const int rg = row0 + m0 + mf * 16 + r1;
#pragma unroll
        for (int nf = 0; nf < 6; ++nf) {
            const int col = n0 + nf * 8 + kq * 2;
            const int mat = col >> 6, h = col & 63;
            const float* bias = (mat == 0) ? bq : (mat == 1) ? bk : bv;
            const float b0 = bias[h], b1 = bias[h + 1];
            const float v00 = acc[mf][nf][0] + b0;
            const float v01 = acc[mf][nf][1] + b1;
            const float v10 = acc[mf][nf][2] + b0;
            const float v11 = acc[mf][nf][3] + b1;
            if (mat == 2) {
                float2 a = {v00, v01}, bvv = {v10, v11};
                *reinterpret_cast<float2*>(g_V + (size_t)rg * kH + h) = a;
                *reinterpret_cast<float2*>(g_V + (size_t)(rg + 8) * kH + h) = bvv;
            } else if (mat == 1) {
                // K -> fragment-major
                const int batch = rg >> 11, tok = rg & 2047;
                const uint32_t p0 = bf2pack(v00, v01);
                const uint32_t p1 = bf2pack(v10, v11);
                const int i0 = bfrag_idx(batch, tok, h);
                const int i1 = bfrag_idx(batch, tok + 8, h);
                KFh[i0] = p0;
                KFl[i0] = bf2pack_lo(v00, v01, p0);
                KFh[i1] = p1;
                KFl[i1] = bf2pack_lo(v10, v11, p1);
            } else {
                // Q: fold softmax scale AND log2(e) (exp2-domain softmax)
                const float scl = 0.125f * 1.44269504f;
                const uint32_t h0 = bf2pack(v00 * scl, v01 * scl);
                const uint32_t h1 = bf2pack(v10 * scl, v11 * scl);
                *reinterpret_cast<uint32_t*>(g_Qh + (size_t)rg * kH + h) = h0;
                *reinterpret_cast<uint32_t*>(g_Ql + (size_t)rg * kH + h) =
                    bf2pack_lo(v00 * scl, v01 * scl, h0);
                *reinterpret_cast<uint32_t*>(g_Qh + (size_t)(rg + 8) * kH + h) = h1;
                *reinterpret_cast<uint32_t*>(g_Ql + (size_t)(rg + 8) * kH + h) =
                    bf2pack_lo(v10 * scl, v11 * scl, h1);
            }
        }
    }
}

// ---------------------------------------------------------------------------
// V transpose + bf16 split -> FRAGMENT-MAJOR g_VFh/g_VFl
// ---------------------------------------------------------------------------
__global__ __launch_bounds__(256)
void vtrans_kernel() {
    __shared__ float tile[64][65];
    const int blk = blockIdx.x;            // kB * 32
    const int b = blk >> 5, jt = blk & 31;
    const int t0 = jt * 64;
    const int tid = threadIdx.x;
    const float* src = g_V + ((size_t)b * kT + t0) * kH;
    uint32_t* VFh = reinterpret_cast<uint32_t*>(g_VFh);
    uint32_t* VFl = reinterpret_cast<uint32_t*>(g_VFl);
#pragma unroll
    for (int i = 0; i < 16; ++i) {
        const int idx = tid + i * 256;
        tile[idx >> 6][idx & 63] = src[idx];
    }
    __syncthreads();
#pragma unroll
    for (int i = 0; i < 8; ++i) {
        const int idx = tid + i * 256;     // 2048 pairs
        const int h = idx >> 5, tp = (idx & 31) * 2;
        const float v0 = tile[tp][h], v1 = tile[tp + 1][h];
        // B-frag for PV: row = h (n-dim), k = t
        const int ks = tp >> 4, sel = (tp >> 3) & 1;
        const int lane2 = (h & 7) * 4 + ((tp >> 1) & 3);
        const int widx = (((b * 32 + jt) * 32) + (h >> 3) * 4 + ks) * 64
                         + lane2 * 2 + sel;
        const uint32_t hp = bf2pack(v0, v1);
        VFh[widx] = hp;
        VFl[widx] = bf2pack_lo(v0, v1, hp);
    }
}

// ---------------------------------------------------------------------------
// Causal flash attention: BM=64, 4 warps, occ 3. Fragment-major smem tiles
// (zero address math, LDS.64 fragments), Q hi+lo entirely in registers,
// exp2-domain softmax, cp.async double buffer.
// ---------------------------------------------------------------------------
__global__ __launch_bounds__(128, 3)
void attn_mma_kernel(float* __restrict__ out) {
    extern __shared__ __align__(16) char sma[];

    const int tid  = threadIdx.x;
    const int lane = tid & 31;
    const int w    = tid >> 5;
    const int b    = blockIdx.x & 15;
    const int qt   = (kQT - 1) - (blockIdx.x >> 4);   // heaviest first
    const int q0   = qt * 64;
    const int m0w  = w * 16;
    const int r1   = lane >> 2;
    const int kq   = lane & 3;

    // ---- Q fragments (hi & lo) -> registers, loaded once ----
    uint32_t qhi[4][4], qlo[4][4];
    {
        const uint32_t* qh =
            reinterpret_cast<const uint32_t*>(g_Qh + ((size_t)b * kT + q0) * kH);
        const uint32_t* ql =
            reinterpret_cast<const uint32_t*>(g_Ql + ((size_t)b * kT + q0) * kH);
        const int rA = (m0w + r1) * 32, rB = rA + 8 * 32;   // rows in u32 words
#pragma unroll
        for (int ks = 0; ks < 4; ++ks) {
            const int c0 = ks * 8 + kq;
            qhi[ks][0] = qh[rA + c0];
            qhi[ks][1] = qh[rB + c0];
            qhi[ks][2] = qh[rA + c0 + 4];
            qhi[ks][3] = qh[rB + c0 + 4];
            qlo[ks][0] = ql[rA + c0];
            qlo[ks][1] = ql[rB + c0];
            qlo[ks][2] = ql[rA + c0 + 4];
            qlo[ks][3] = ql[rB + c0 + 4];
        }
    }

    auto stage = [&](int jt, char* buf) {
        const size_t base = ((size_t)b * 32 + jt) * 8192;
        const char* kh = (const char*)g_KFh + base;
        const char* kl = (const char*)g_KFl + base;
        const char* vh = (const char*)g_VFh + base;
        const char* vl = (const char*)g_VFl + base;
#pragma unroll
        for (int i = 0; i < 4; ++i) {
            const int off = (tid + i * 128) * 16;
            CP_ASYNC16(smem_addr(buf + BK_KH + off), kh + off);
            CP_ASYNC16(smem_addr(buf + BK_KL + off), kl + off);
            CP_ASYNC16(smem_addr(buf + BK_VH + off), vh + off);
            CP_ASYNC16(smem_addr(buf + BK_VL + off), vl + off);
        }
    };

    float o[8][4];
#pragma unroll
    for (int nf = 0; nf < 8; ++nf)
#pragma unroll
        for (int c = 0; c < 4; ++c) o[nf][c] = 0.f;
    float mrow[2] = {-1e30f, -1e30f};
    float lrow[2] = {0.f, 0.f};

    stage(0, sma);
    CP_COMMIT();

    for (int jt = 0; jt <= qt; ++jt) {
        if (jt + 1 <= qt) stage(jt + 1, sma + ((jt + 1) & 1) * ABUFSZ);
        CP_COMMIT();
        CP_WAIT1();
        __syncthreads();

        char* buf = sma + (jt & 1) * ABUFSZ;
        const char* Kh = buf + BK_KH + lane * 8;
        const char* Kl = buf + BK_KL + lane * 8;
        const char* Vh = buf + BK_VH + lane * 8;
        const char* Vl = buf + BK_VL + lane * 8;

        // ---- S = Q K^T (3-term split; pure immediate-offset LDS.64) ----
        float s[8][4];
#pragma unroll
        for (int nf = 0; nf < 8; ++nf)
#pragma unroll
            for (int c = 0; c < 4; ++c) s[nf][c] = 0.f;

#pragma unroll
        for (int ks = 0; ks < 4; ++ks) {
#pragma unroll
            for (int nf = 0; nf < 8; ++nf) {
                const int boff = (nf * 4 + ks) * 256;
                uint2 bh = *reinterpret_cast<const uint2*>(Kh + boff);
                uint2 bl = *reinterpret_cast<const uint2*>(Kl + boff);
                mma16816(s[nf], qhi[ks], reinterpret_cast<uint32_t*>(&bh));
                mma16816(s[nf], qhi[ks], reinterpret_cast<uint32_t*>(&bl));
                mma16816(s[nf], qlo[ks], reinterpret_cast<uint32_t*>(&bh));
            }
        }

        // ---- causal mask (diagonal tile only) + online softmax (exp2) ----
        float mx1 = -1e30f, mx2 = -1e30f;
        if (jt == qt) {
            const int qg1 = q0 + m0w + r1;
            const int qg2 = qg1 + 8;
#pragma unroll
            for (int nf = 0; nf < 8; ++nf) {
                const int kg0 = jt * 64 + nf * 8 + kq * 2;
                s[nf][0] = (kg0     <= qg1) ? s[nf][0] : -1e30f;
                s[nf][1] = (kg0 + 1 <= qg1) ? s[nf][1] : -1e30f;
                s[nf][2] = (kg0     <= qg2) ? s[nf][2] : -1e30f;
                s[nf][3] = (kg0 + 1 <= qg2) ? s[nf][3] : -1e30f;
            }
        }
#pragma unroll
        for (int nf = 0; nf < 8; ++nf) {
            mx1 = fmaxf(mx1, fmaxf(s[nf][0], s[nf][1]));
            mx2 = fmaxf(mx2, fmaxf(s[nf][2], s[nf][3]));
        }
        mx1 = fmaxf(mx1, __shfl_xor_sync(0xffffffffu, mx1, 1));
        mx1 = fmaxf(mx1, __shfl_xor_sync(0xffffffffu, mx1, 2));
        mx2 = fmaxf(mx2, __shfl_xor_sync(0xffffffffu, mx2, 1));
        mx2 = fmaxf(mx2, __shfl_xor_sync(0xffffffffu, mx2, 2));

        const float mn1 = fmaxf(mrow[0], mx1);
        const float mn2 = fmaxf(mrow[1], mx2);
        const float a1 = exp2f(mrow[0] - mn1);
        const float a2 = exp2f(mrow[1] - mn2);
        mrow[0] = mn1; mrow[1] = mn2;

        float rs1 = 0.f, rs2 = 0.f;
#pragma unroll
        for (int nf = 0; nf < 8; ++nf) {
            s[nf][0] = exp2f(s[nf][0] - mn1);
            s[nf][1] = exp2f(s[nf][1] - mn1);
            s[nf][2] = exp2f(s[nf][2] - mn2);
            s[nf][3] = exp2f(s[nf][3] - mn2);
            rs1 += s[nf][0] + s[nf][1];
            rs2 += s[nf][2] + s[nf][3];
        }
        rs1 += __shfl_xor_sync(0xffffffffu, rs1, 1);
        rs1 += __shfl_xor_sync(0xffffffffu, rs1, 2);
        rs2 += __shfl_xor_sync(0xffffffffu, rs2, 1);
        rs2 += __shfl_xor_sync(0xffffffffu, rs2, 2);
        lrow[0] = lrow[0] * a1 + rs1;
        lrow[1] = lrow[1] * a2 + rs2;
#pragma unroll
        for (int nf = 0; nf < 8; ++nf) {
            o[nf][0] *= a1; o[nf][1] *= a1;
            o[nf][2] *= a2; o[nf][3] *= a2;
        }

        // ---- O += P V (P packed register-direct) ----
#pragma unroll
        for (int ks = 0; ks < 4; ++ks) {
            uint32_t pah[4], pal[4];
            const float* s0 = s[2 * ks];
            const float* s1 = s[2 * ks + 1];
            pah[0] = bf2pack(s0[0], s0[1]);
            pah[1] = bf2pack(s0[2], s0[3]);
            pah[2] = bf2pack(s1[0], s1[1]);
            pah[3] = bf2pack(s1[2], s1[3]);
            pal[0] = bf2pack_lo(s0[0], s0[1], pah[0]);
            pal[1] = bf2pack_lo(s0[2], s0[3], pah[1]);
            pal[2] = bf2pack_lo(s1[0], s1[1], pah[2]);
            pal[3] = bf2pack_lo(s1[2], s1[3], pah[3]);
#pragma unroll
            for (int nf = 0; nf < 8; ++nf) {
                const int boff = (nf * 4 + ks) * 256;
                uint2 vh = *reinterpret_cast<const uint2*>(Vh + boff);
                uint2 vl = *reinterpret_cast<const uint2*>(Vl + boff);
                mma16816(o[nf], pah, reinterpret_cast<uint32_t*>(&vh));
                mma16816(o[nf], pah, reinterpret_cast<uint32_t*>(&vl));
                mma16816(o[nf], pal, reinterpret_cast<uint32_t*>(&vh));
            }
        }
        __syncthreads();   // readers of this buffer done before it is re-staged
    }

    // ---- epilogue: normalize + store ----
    const float inv1 = 1.0f / lrow[0];
    const float inv2 = 1.0f / lrow[1];
    float* og = out + ((size_t)b * kT + q0 + m0w) * kH;
#pragma unroll
    for (int nf = 0; nf < 8; ++nf) {
        const int col = nf * 8 + kq * 2;
        float2 v0, v1;
        v0.x = o[nf][0] * inv1; v0.y = o[nf][1] * inv1;
        v1.x = o[nf][2] * inv2; v1.y = o[nf][3] * inv2;
        *reinterpret_cast<float2*>(&og[r1 * kH + col]) = v0;
        *reinterpret_cast<float2*>(&og[(r1 + 8) * kH + col]) = v1;
    }
}

// ---------------------------------------------------------------------------
extern "C" void kernel_launch(void* const* d_in, const int* in_sizes, int n_in,
                              void* d_out, int out_size) {
    (void)in_sizes; (void)n_in; (void)out_size;
    const float* x  = (const float*)d_in[0];
    const float* Wq = (const float*)d_in[1];
    const float* bq = (const float*)d_in[2];
    const float* Wk = (const float*)d_in[3];
    const float* bk = (const float*)d_in[4];
    const float* Wv = (const float*)d_in[5];
    const float* bv = (const float*)d_in[6];
    float* out = (float*)d_out;

    wprep_kernel<<<(192 * 1024) / 256, 256>>>(Wq, Wk, Wv);

    cudaFuncSetAttribute(qkv_mma_kernel, cudaFuncAttributeMaxDynamicSharedMemorySize,
                         QKV_SMEM);
    qkv_mma_kernel<<<kRows / 128, 512, QKV_SMEM>>>(x, bq, bk, bv);

    vtrans_kernel<<<kB * 32, 256>>>();

    cudaFuncSetAttribute(attn_mma_kernel, cudaFuncAttributeMaxDynamicSharedMemorySize,
                         ATTN_SMEM);
    attn_mma_kernel<<<kB * kQT, 128, ATTN_SMEM>>>(out);
}

// round 9
// speedup vs baseline: 1.1931x; 1.0097x over previous
#include <cuda_runtime.h>
#include <cuda_bf16.h>
#include <cstdint>

// ---------------------------------------------------------------------------
// Problem constants
// ---------------------------------------------------------------------------
namespace {
constexpr int kB = 16;
constexpr int kT = 2048;
constexpr int kC = 1024;
constexpr int kH = 64;
constexpr int kRows = kB * kT;     // 32768
constexpr int kQT = kT / 64;       // 32 q-tiles per batch

// QKV GEMM smem (bytes): fragment-major, K-chunk 64, double buffer
constexpr int G_AH = 0;            // 32 A-frags x 512B
constexpr int G_AL = 16384;
constexpr int G_BH = 32768;        // 96 B-frags x 256B
constexpr int G_BL = 57344;
constexpr int G_BUF = 81920;
constexpr int QKV_SMEM = 2 * G_BUF;          // 163840

// Attention smem (bytes): fragment-major contiguous tiles, no Q in smem
constexpr int BK_KH = 0;
constexpr int BK_KL = 8192;
constexpr int BK_VH = 16384;
constexpr int BK_VL = 24576;
constexpr int ABUFSZ = 32768;
constexpr int ATTN_SMEM = 2 * ABUFSZ;        // 65536 -> 3 CTAs/SM
}

// Scratch (__device__ globals: allocation-free)
__device__ float g_V[kRows * kH];
__device__ __nv_bfloat16 g_Qh[kRows * kH], g_Ql[kRows * kH];
// K and V^T in FRAGMENT-MAJOR order (8KB blob per (batch, 64-token tile))
__device__ __nv_bfloat16 g_KFh[kRows * kH], g_KFl[kRows * kH];
__device__ __nv_bfloat16 g_VFh[kRows * kH], g_VFl[kRows * kH];
// W in FRAGMENT-MAJOR order: 32 chunks x 96 frags x 256B (chunk-contiguous)
__device__ __nv_bfloat16 g_WFh[192 * 1024], g_WFl[192 * 1024];

// ---------------------------------------------------------------------------
// PTX helpers (baseline sm_80+ — survive compute_103 lowering)
// ---------------------------------------------------------------------------
__device__ __forceinline__ void mma16816(float* d, const uint32_t* a,
                                         const uint32_t* b) {
    asm volatile(
        "mma.sync.aligned.m16n8k16.row.col.f32.bf16.bf16.f32 "
        "{%0,%1,%2,%3}, {%4,%5,%6,%7}, {%8,%9}, {%0,%1,%2,%3};"
        : "+f"(d[0]), "+f"(d[1]), "+f"(d[2]), "+f"(d[3])
        : "r"(a[0]), "r"(a[1]), "r"(a[2]), "r"(a[3]), "r"(b[0]), "r"(b[1]));
}
__device__ __forceinline__ uint32_t bf2pack(float lo, float hi) {
    uint32_t r;
    asm("cvt.rn.bf16x2.f32 %0, %1, %2;" : "=r"(r) : "f"(hi), "f"(lo));
    return r;
}
__device__ __forceinline__ uint32_t bf2pack_lo(float lo, float hi, uint32_t hp) {
    const float rl = lo - __uint_as_float(hp << 16);
    const float rh = hi - __uint_as_float(hp & 0xffff0000u);
    return bf2pack(rl, rh);
}
__device__ __forceinline__ uint32_t smem_addr(const void* p) {
    return (uint32_t)__cvta_generic_to_shared(p);
}
#define CP_ASYNC16(dst, src) \
    asm volatile("cp.async.cg.shared.global [%0], [%1], 16;" \
                 :: "r"(dst), "l"(src))
#define CP_COMMIT() asm volatile("cp.async.commit_group;" ::: "memory")
#define CP_WAIT0()  asm volatile("cp.async.wait_group 0;" ::: "memory")
#define CP_WAIT1()  asm volatile("cp.async.wait_group 1;" ::: "memory")

// Fragment-major u32-word index for attention K (B-operand view)
__device__ __forceinline__ int bfrag_idx(int batch, int tok, int h) {
    const int jt = tok >> 6, nf = (tok >> 3) & 7, r = tok & 7;
    const int ks = h >> 4, sel = (h >> 3) & 1, q2 = (h >> 1) & 3;
    return (((batch * 32 + jt) * 32) + nf * 4 + ks) * 64 + (r * 4 + q2) * 2 + sel;
}

// ---------------------------------------------------------------------------
// Prep: W -> fragment-major bf16 hi/lo.
// Word idx decomposes as: frag = idx>>6 (= ks_g*24 + nb), w = idx&63
// (= (r*4+q2)*2+sel). n = nb*8+r, k = ks_g*16+sel*8+q2*2.
// ---------------------------------------------------------------------------
__global__ void wprep_kernel(const float* __restrict__ Wq,
                             const float* __restrict__ Wk,
                             const float* __restrict__ Wv) {
    const int idx = blockIdx.x * 256 + threadIdx.x;   // < 98304
    const int frag = idx >> 6, ww = idx & 63;
    const int r = ww >> 3, q2 = (ww >> 1) & 3, sel = ww & 1;
    const int ks_g = frag / 24, nb = frag % 24;
    const int n = nb * 8 + r;
    const int k = ks_g * 16 + sel * 8 + q2 * 2;
    const int mat = n >> 6, col = n & 63;
    const float* W = (mat == 0) ? Wq : (mat == 1) ? Wk : Wv;
    const float v0 = W[k * 64 + col];
    const float v1 = W[(k + 1) * 64 + col];
    const uint32_t hp = bf2pack(v0, v1);
    reinterpret_cast<uint32_t*>(g_WFh)[idx] = hp;
    reinterpret_cast<uint32_t*>(g_WFl)[idx] = bf2pack_lo(v0, v1, hp);
}

// ---------------------------------------------------------------------------
// QKV GEMM: 3-term bf16-split HMMA, fragment-major smem (LDS.128 A-frags,
// LDS.64 B-frags, zero mainloop address math). K-chunk 64, double buffer,
// W via linear cp.async blobs. Epilogue: Q row-major bf16 hi/lo (pre-scaled
// 0.125*log2e), K fragment-major, V fp32.
// ---------------------------------------------------------------------------
__global__ __launch_bounds__(512, 1)
void qkv_mma_kernel(const float* __restrict__ x,
                    const float* __restrict__ bq,
                    const float* __restrict__ bk,
                    const float* __restrict__ bv) {
    extern __shared__ __align__(16) char sm[];
    const int tid  = threadIdx.x;
    const int lane = tid & 31;
    const int w    = tid >> 5;
    const int m0   = (w >> 2) * 32;
    const int n0   = (w & 3) * 48;
    const int mb0  = (w >> 2) * 2;    // A-frag block base (16-row blocks)
    const int nb0  = (w & 3) * 6;     // B-frag block base (8-col blocks)
    const int r1   = lane >> 2;
    const int kq   = lane & 3;
    const int row0 = blockIdx.x * 128;

    float acc[2][6][4];
#pragma unroll
    for (int mf = 0; mf < 2; ++mf)
#pragma unroll
        for (int nf = 0; nf < 6; ++nf)
#pragma unroll
            for (int i = 0; i < 4; ++i) acc[mf][nf][i] = 0.f;

    float4 xr[4];

    auto ldg_x = [&](int k0) {
#pragma unroll
        for (int it = 0; it < 4; ++it) {
            const int e4 = tid + it * 512;
            const int m = e4 >> 4, k4 = (e4 & 15) * 4;
            xr[it] = *reinterpret_cast<const float4*>(
                &x[(size_t)(row0 + m) * kC + k0 + k4]);
        }
    };
    auto cp_w = [&](int ch, char* buf) {
        const char* wh = (const char*)g_WFh + (size_t)ch * 24576;
        const char* wl = (const char*)g_WFl + (size_t)ch * 24576;
#pragma unroll
        for (int it = 0; it < 3; ++it) {
            const int off = (tid + it * 512) * 16;
            CP_ASYNC16(smem_addr(buf + G_BH + off), wh + off);
            CP_ASYNC16(smem_addr(buf + G_BL + off), wl + off);
        }
    };
    // X -> A-fragment-major smem: frag (mb, ks) of 512B; word = l*4 + j,
    // l = (m&7)*4 + q2, j = kh*2 + rh.
    auto sts_x = [&](char* buf) {
        uint32_t* A = reinterpret_cast<uint32_t*>(buf + G_AH);
        uint32_t* L = reinterpret_cast<uint32_t*>(buf + G_AL);
#pragma unroll
        for (int it = 0; it < 4; ++it) {
            const int e4 = tid + it * 512;
            const int m = e4 >> 4, k4 = (e4 & 15) * 4;
            const float4 v = xr[it];
            const int mb = m >> 4;
            const int ks = k4 >> 4;
            const int j  = ((k4 >> 3) & 1) * 2 + ((m >> 3) & 1);
            const int l0 = (m & 7) * 4 + ((k4 >> 1) & 3);
            const int base = (mb * 4 + ks) * 128 + j;
            const uint32_t h0 = bf2pack(v.x, v.y);
            const uint32_t h1 = bf2pack(v.z, v.w);
            A[base + l0 * 4]       = h0;
            A[base + (l0 + 1) * 4] = h1;
            L[base + l0 * 4]       = bf2pack_lo(v.x, v.y, h0);
            L[base + (l0 + 1) * 4] = bf2pack_lo(v.z, v.w, h1);
        }
    };

    ldg_x(0);
    cp_w(0, sm);
    CP_COMMIT();
    sts_x(sm);
    CP_WAIT0();
    __syncthreads();

    for (int ch = 0; ch < 16; ++ch) {
        char* buf = sm + (ch & 1) * G_BUF;
        if (ch + 1 < 16) {
            ldg_x((ch + 1) * 64);
            cp_w(ch + 1, sm + ((ch + 1) & 1) * G_BUF);
        }
        CP_COMMIT();

        const char* Ab = buf + G_AH + mb0 * 2048 + lane * 16;
        const char* Lb = buf + G_AL + mb0 * 2048 + lane * 16;
        const char* Bh = buf + G_BH + nb0 * 256 + lane * 8;
        const char* Bl = buf + G_BL + nb0 * 256 + lane * 8;

#pragma unroll
        for (int ks = 0; ks < 4; ++ks) {
            uint4 ah4[2], al4[2];
#pragma unroll
            for (int mf = 0; mf < 2; ++mf) {
                const int aoff = (mf * 4 + ks) * 512;
                ah4[mf] = *reinterpret_cast<const uint4*>(Ab + aoff);
                al4[mf] = *reinterpret_cast<const uint4*>(Lb + aoff);
            }
#pragma unroll
            for (int nf = 0; nf < 6; ++nf) {
                const int boff = (ks * 24 + nf) * 256;
                uint2 bh = *reinterpret_cast<const uint2*>(Bh + boff);
                uint2 bl = *reinterpret_cast<const uint2*>(Bl + boff);
#pragma unroll
                for (int mf = 0; mf < 2; ++mf) {
                    mma16816(acc[mf][nf], reinterpret_cast<uint32_t*>(&ah4[mf]),
                             reinterpret_cast<uint32_t*>(&bh));
                    mma16816(acc[mf][nf], reinterpret_cast<uint32_t*>(&ah4[mf]),
                             reinterpret_cast<uint32_t*>(&bl));
                    mma16816(acc[mf][nf], reinterpret_cast<uint32_t*>(&al4[mf]),
                             reinterpret_cast<uint32_t*>(&bh));
                }
            }
        }

        if (ch + 1 < 16) {
            __syncthreads();
            sts_x(sm + ((ch + 1) & 1) * G_BUF);
            CP_WAIT0();
            __syncthreads();
        }
    }

    // ---- epilogue ----
    uint32_t* KFh = reinterpret_cast<uint32_t*>(g_KFh);
    uint32_t* KFl = reinterpret_cast<uint32_t*>(g_KFl);
#pragma unroll
    for (int mf = 0; mf < 2; ++mf) {
        const int rg = row0 + m0 + mf * 16 + r1;
#pragma unroll
        for (int nf = 0; nf < 6; ++nf) {
            const int col = n0 + nf * 8 + kq * 2;
            const int mat = col >> 6, h = col & 63;
            const float* bias = (mat == 0) ? bq : (mat == 1) ? bk : bv;
            const float b0 = bias[h], b1 = bias[h + 1];
            const float v00 = acc[mf][nf][0] + b0;
            const float v01 = acc[mf][nf][1] + b1;
            const float v10 = acc[mf][nf][2] + b0;
            const float v11 = acc[mf][nf][3] + b1;
            if (mat == 2) {
                float2 a = {v00, v01}, bvv = {v10, v11};
                *reinterpret_cast<float2*>(g_V + (size_t)rg * kH + h) = a;
                *reinterpret_cast<float2*>(g_V + (size_t)(rg + 8) * kH + h) = bvv;
            } else if (mat == 1) {
                const int batch = rg >> 11, tok = rg & 2047;
                const uint32_t p0 = bf2pack(v00, v01);
                const uint32_t p1 = bf2pack(v10, v11);
                const int i0 = bfrag_idx(batch, tok, h);
                const int i1 = bfrag_idx(batch, tok + 8, h);
                KFh[i0] = p0;
                KFl[i0] = bf2pack_lo(v00, v01, p0);
                KFh[i1] = p1;
                KFl[i1] = bf2pack_lo(v10, v11, p1);
            } else {
                const float scl = 0.125f * 1.44269504f;
                const uint32_t h0 = bf2pack(v00 * scl, v01 * scl);
                const uint32_t h1 = bf2pack(v10 * scl, v11 * scl);
                *reinterpret_cast<uint32_t*>(g_Qh + (size_t)rg * kH + h) = h0;
                *reinterpret_cast<uint32_t*>(g_Ql + (size_t)rg * kH + h) =
                    bf2pack_lo(v00 * scl, v01 * scl, h0);
                *reinterpret_cast<uint32_t*>(g_Qh + (size_t)(rg + 8) * kH + h) = h1;
                *reinterpret_cast<uint32_t*>(g_Ql + (size_t)(rg + 8) * kH + h) =
                    bf2pack_lo(v10 * scl, v11 * scl, h1);
            }
        }
    }
}

// ---------------------------------------------------------------------------
// V transpose + bf16 split -> FRAGMENT-MAJOR g_VFh/g_VFl
// ---------------------------------------------------------------------------
__global__ __launch_bounds__(256)
void vtrans_kernel() {
    __shared__ float tile[64][65];
    const int blk = blockIdx.x;            // kB * 32
    const int b = blk >> 5, jt = blk & 31;
    const int t0 = jt * 64;
    const int tid = threadIdx.x;
    const float* src = g_V + ((size_t)b * kT + t0) * kH;
    uint32_t* VFh = reinterpret_cast<uint32_t*>(g_VFh);
    uint32_t* VFl = reinterpret_cast<uint32_t*>(g_VFl);
#pragma unroll
    for (int i = 0; i < 16; ++i) {
        const int idx = tid + i * 256;
        tile[idx >> 6][idx & 63] = src[idx];
    }
    __syncthreads();
#pragma unroll
    for (int i = 0; i < 8; ++i) {
        const int idx = tid + i * 256;     // 2048 pairs
        const int h = idx >> 5, tp = (idx & 31) * 2;
        const float v0 = tile[tp][h], v1 = tile[tp + 1][h];
        const int ks = tp >> 4, sel = (tp >> 3) & 1;
        const int lane2 = (h & 7) * 4 + ((tp >> 1) & 3);
        const int widx = (((b * 32 + jt) * 32) + (h >> 3) * 4 + ks) * 64
                         + lane2 * 2 + sel;
        const uint32_t hp = bf2pack(v0, v1);
        VFh[widx] = hp;
        VFl[widx] = bf2pack_lo(v0, v1, hp);
    }
}

// ---------------------------------------------------------------------------
// Causal flash attention (R8-validated, 93.7us): BM=64, 4 warps, occ 3,
// fragment-major smem, Q in registers, exp2 softmax, cp.async double buffer.
// ---------------------------------------------------------------------------
__global__ __launch_bounds__(128, 3)
void attn_mma_kernel(float* __restrict__ out) {
    extern __shared__ __align__(16) char sma[];

    const int tid  = threadIdx.x;
    const int lane = tid & 31;
    const int w    = tid >> 5;
    const int b    = blockIdx.x & 15;
    const int qt   = (kQT - 1) - (blockIdx.x >> 4);
    const int q0   = qt * 64;
    const int m0w  = w * 16;
    const int r1   = lane >> 2;
    const int kq   = lane & 3;

    uint32_t qhi[4][4], qlo[4][4];
    {
        const uint32_t* qh =
            reinterpret_cast<const uint32_t*>(g_Qh + ((size_t)b * kT + q0) * kH);
        const uint32_t* ql =
            reinterpret_cast<const uint32_t*>(g_Ql + ((size_t)b * kT + q0) * kH);
        const int rA = (m0w + r1) * 32, rB = rA + 8 * 32;
#pragma unroll
        for (int ks = 0; ks < 4; ++ks) {
            const int c0 = ks * 8 + kq;
            qhi[ks][0] = qh[rA + c0];
            qhi[ks][1] = qh[rB + c0];
            qhi[ks][2] = qh[rA + c0 + 4];
            qhi[ks][3] = qh[rB + c0 + 4];
            qlo[ks][0] = ql[rA + c0];
            qlo[ks][1] = ql[rB + c0];
            qlo[ks][2] = ql[rA + c0 + 4];
            qlo[ks][3] = ql[rB + c0 + 4];
        }
    }

    auto stage = [&](int jt, char* buf) {
        const size_t base = ((size_t)b * 32 + jt) * 8192;
        const char* kh = (const char*)g_KFh + base;
        const char* kl = (const char*)g_KFl + base;
        const char* vh = (const char*)g_VFh + base;
        const char* vl = (const char*)g_VFl + base;
#pragma unroll
        for (int i = 0; i < 4; ++i) {
            const int off = (tid + i * 128) * 16;
            CP_ASYNC16(smem_addr(buf + BK_KH + off), kh + off);
            CP_ASYNC16(smem_addr(buf + BK_KL + off), kl + off);
            CP_ASYNC16(smem_addr(buf + BK_VH + off), vh + off);
            CP_ASYNC16(smem_addr(buf + BK_VL + off), vl + off);
        }
    };

    float o[8][4];
#pragma unroll
    for (int nf = 0; nf < 8; ++nf)
#pragma unroll
        for (int c = 0; c < 4; ++c) o[nf][c] = 0.f;
    float mrow[2] = {-1e30f, -1e30f};
    float lrow[2] = {0.f, 0.f};

    stage(0, sma);
    CP_COMMIT();

    for (int jt = 0; jt <= qt; ++jt) {
        if (jt + 1 <= qt) stage(jt + 1, sma + ((jt + 1) & 1) * ABUFSZ);
        CP_COMMIT();
        CP_WAIT1();
        __syncthreads();

        char* buf = sma + (jt & 1) * ABUFSZ;
        const char* Kh = buf + BK_KH + lane * 8;
        const char* Kl = buf + BK_KL + lane * 8;
        const char* Vh = buf + BK_VH + lane * 8;
        const char* Vl = buf + BK_VL + lane * 8;

        float s[8][4];
#pragma unroll
        for (int nf = 0; nf < 8; ++nf)
#pragma unroll
            for (int c = 0; c < 4; ++c) s[nf][c] = 0.f;

#pragma unroll
        for (int ks = 0; ks < 4; ++ks) {
#pragma unroll
            for (int nf = 0; nf < 8; ++nf) {
                const int boff = (nf * 4 + ks) * 256;
                uint2 bh = *reinterpret_cast<const uint2*>(Kh + boff);
                uint2 bl = *reinterpret_cast<const uint2*>(Kl + boff);
                mma16816(s[nf], qhi[ks], reinterpret_cast<uint32_t*>(&bh));
                mma16816(s[nf], qhi[ks], reinterpret_cast<uint32_t*>(&bl));
                mma16816(s[nf], qlo[ks], reinterpret_cast<uint32_t*>(&bh));
            }
        }

        float mx1 = -1e30f, mx2 = -1e30f;
        if (jt == qt) {
            const int qg1 = q0 + m0w + r1;
            const int qg2 = qg1 + 8;
#pragma unroll
            for (int nf = 0; nf < 8; ++nf) {
                const int kg0 = jt * 64 + nf * 8 + kq * 2;
                s[nf][0] = (kg0     <= qg1) ? s[nf][0] : -1e30f;
                s[nf][1] = (kg0 + 1 <= qg1) ? s[nf][1] : -1e30f;
                s[nf][2] = (kg0     <= qg2) ? s[nf][2] : -1e30f;
                s[nf][3] = (kg0 + 1 <= qg2) ? s[nf][3] : -1e30f;
            }
        }
#pragma unroll
        for (int nf = 0; nf < 8; ++nf) {
            mx1 = fmaxf(mx1, fmaxf(s[nf][0], s[nf][1]));
            mx2 = fmaxf(mx2, fmaxf(s[nf][2], s[nf][3]));
        }
        mx1 = fmaxf(mx1, __shfl_xor_sync(0xffffffffu, mx1, 1));
        mx1 = fmaxf(mx1, __shfl_xor_sync(0xffffffffu, mx1, 2));
        mx2 = fmaxf(mx2, __shfl_xor_sync(0xffffffffu, mx2, 1));
        mx2 = fmaxf(mx2, __shfl_xor_sync(0xffffffffu, mx2, 2));

        const float mn1 = fmaxf(mrow[0], mx1);
        const float mn2 = fmaxf(mrow[1], mx2);
        const float a1 = exp2f(mrow[0] - mn1);
        const float a2 = exp2f(mrow[1] - mn2);
        mrow[0] = mn1; mrow[1] = mn2;

        float rs1 = 0.f, rs2 = 0.f;
#pragma unroll
        for (int nf = 0; nf < 8; ++nf) {
            s[nf][0] = exp2f(s[nf][0] - mn1);
            s[nf][1] = exp2f(s[nf][1] - mn1);
            s[nf][2] = exp2f(s[nf][2] - mn2);
            s[nf][3] = exp2f(s[nf][3] - mn2);
            rs1 += s[nf][0] + s[nf][1];
            rs2 += s[nf][2] + s[nf][3];
        }
        rs1 += __shfl_xor_sync(0xffffffffu, rs1, 1);
        rs1 += __shfl_xor_sync(0xffffffffu, rs1, 2);
        rs2 += __shfl_xor_sync(0xffffffffu, rs2, 1);
        rs2 += __shfl_xor_sync(0xffffffffu, rs2, 2);
        lrow[0] = lrow[0] * a1 + rs1;
        lrow[1] = lrow[1] * a2 + rs2;
#pragma unroll
        for (int nf = 0; nf < 8; ++nf) {
            o[nf][0] *= a1; o[nf][1] *= a1;
            o[nf][2] *= a2; o[nf][3] *= a2;
        }

#pragma unroll
        for (int ks = 0; ks < 4; ++ks) {
            uint32_t pah[4], pal[4];
            const float* s0 = s[2 * ks];
            const float* s1 = s[2 * ks + 1];
            pah[0] = bf2pack(s0[0], s0[1]);
            pah[1] = bf2pack(s0[2], s0[3]);
            pah[2] = bf2pack(s1[0], s1[1]);
            pah[3] = bf2pack(s1[2], s1[3]);
            pal[0] = bf2pack_lo(s0[0], s0[1], pah[0]);
            pal[1] = bf2pack_lo(s0[2], s0[3], pah[1]);
            pal[2] = bf2pack_lo(s1[0], s1[1], pah[2]);
            pal[3] = bf2pack_lo(s1[2], s1[3], pah[3]);
#pragma unroll
            for (int nf = 0; nf < 8; ++nf) {
                const int boff = (nf * 4 + ks) * 256;
                uint2 vh = *reinterpret_cast<const uint2*>(Vh + boff);
                uint2 vl = *reinterpret_cast<const uint2*>(Vl + boff);
                mma16816(o[nf], pah, reinterpret_cast<uint32_t*>(&vh));
                mma16816(o[nf], pah, reinterpret_cast<uint32_t*>(&vl));
                mma16816(o[nf], pal, reinterpret_cast<uint32_t*>(&vh));
            }
        }
        __syncthreads();
    }

    const float inv1 = 1.0f / lrow[0];
    const float inv2 = 1.0f / lrow[1];
    float* og = out + ((size_t)b * kT + q0 + m0w) * kH;
#pragma unroll
    for (int nf = 0; nf < 8; ++nf) {
        const int col = nf * 8 + kq * 2;
        float2 v0, v1;
        v0.x = o[nf][0] * inv1; v0.y = o[nf][1] * inv1;
        v1.x = o[nf][2] * inv2; v1.y = o[nf][3] * inv2;
        *reinterpret_cast<float2*>(&og[r1 * kH + col]) = v0;
        *reinterpret_cast<float2*>(&og[(r1 + 8) * kH + col]) = v1;
    }
}

// ---------------------------------------------------------------------------
extern "C" void kernel_launch(void* const* d_in, const int* in_sizes, int n_in,
                              void* d_out, int out_size) {
    (void)in_sizes; (void)n_in; (void)out_size;
    const float* x  = (const float*)d_in[0];
    const float* Wq = (const float*)d_in[1];
    const float* bq = (const float*)d_in[2];
    const float* Wk = (const float*)d_in[3];
    const float* bk = (const float*)d_in[4];
    const float* Wv = (const float*)d_in[5];
    const float* bv = (const float*)d_in[6];
    float* out = (float*)d_out;

    wprep_kernel<<<384, 256>>>(Wq, Wk, Wv);

    cudaFuncSetAttribute(qkv_mma_kernel, cudaFuncAttributeMaxDynamicSharedMemorySize,
                         QKV_SMEM);
    qkv_mma_kernel<<<kRows / 128, 512, QKV_SMEM>>>(x, bq, bk, bv);

    vtrans_kernel<<<kB * 32, 256>>>();

    cudaFuncSetAttribute(attn_mma_kernel, cudaFuncAttributeMaxDynamicSharedMemorySize,
                         ATTN_SMEM);
    attn_mma_kernel<<<kB * kQT, 128, ATTN_SMEM>>>(out);
}

// round 10
// speedup vs baseline: 1.4855x; 1.2451x over previous
#include <cuda_runtime.h>
#include <cuda_fp16.h>
#include <cstdint>

// ---------------------------------------------------------------------------
// Problem constants
// ---------------------------------------------------------------------------
namespace {
constexpr int kB = 16;
constexpr int kT = 2048;
constexpr int kC = 1024;
constexpr int kH = 64;
constexpr int kRows = kB * kT;     // 32768
constexpr int kQT = kT / 64;       // 32 q-tiles per batch

// QKV GEMM smem (bytes): fragment-major, K-chunk 64, double buffer
constexpr int G_AH = 0;            // 32 A-frags x 512B (X hi)
constexpr int G_AL = 16384;        // X lo
constexpr int G_BH = 32768;        // 96 B-frags x 256B (W, single)
constexpr int G_BUF = 57344;
constexpr int QKV_SMEM = 2 * G_BUF;          // 114688

// Attention smem (bytes): fragment-major contiguous tiles
constexpr int BK_KH = 0;           // K single
constexpr int BK_VH = 8192;        // V hi
constexpr int BK_VL = 16384;       // V lo
constexpr int ABUFSZ = 24576;
constexpr int ATTN_SMEM = 2 * ABUFSZ;        // 49152
}

// Scratch (__device__ globals: allocation-free)
__device__ float g_V[kRows * kH];
__device__ __half g_Qh[kRows * kH], g_Ql[kRows * kH];
// K (single fp16) and V^T (fp16 hi/lo) in FRAGMENT-MAJOR order
__device__ __half g_KFh[kRows * kH];
__device__ __half g_VFh[kB * kH * kT], g_VFl[kB * kH * kT];
// W single fp16, FRAGMENT-MAJOR: 32 chunks x 96 frags x 256B
__device__ __half g_WFh[192 * 1024];

// ---------------------------------------------------------------------------
// PTX helpers (baseline sm_80+ — survive compute_103 lowering)
// ---------------------------------------------------------------------------
__device__ __forceinline__ void mma16816(float* d, const uint32_t* a,
                                         const uint32_t* b) {
    asm volatile(
        "mma.sync.aligned.m16n8k16.row.col.f32.f16.f16.f32 "
        "{%0,%1,%2,%3}, {%4,%5,%6,%7}, {%8,%9}, {%0,%1,%2,%3};"
        : "+f"(d[0]), "+f"(d[1]), "+f"(d[2]), "+f"(d[3])
        : "r"(a[0]), "r"(a[1]), "r"(a[2]), "r"(a[3]), "r"(b[0]), "r"(b[1]));
}
// pack {lo, hi} floats into f16x2 (RN)
__device__ __forceinline__ uint32_t f2pack(float lo, float hi) {
    uint32_t r;
    asm("cvt.rn.f16x2.f32 %0, %1, %2;" : "=r"(r) : "f"(hi), "f"(lo));
    return r;
}
// residual pair given originals and their hi-pack
__device__ __forceinline__ uint32_t f2pack_lo(float lo, float hi, uint32_t hp) {
    const __half2 h = *reinterpret_cast<const __half2*>(&hp);
    const float rl = lo - __low2float(h);
    const float rh = hi - __high2float(h);
    return f2pack(rl, rh);
}
__device__ __forceinline__ uint32_t smem_addr(const void* p) {
    return (uint32_t)__cvta_generic_to_shared(p);
}
#define CP_ASYNC16(dst, src) \
    asm volatile("cp.async.cg.shared.global [%0], [%1], 16;" \
                 :: "r"(dst), "l"(src))
#define CP_COMMIT() asm volatile("cp.async.commit_group;" ::: "memory")
#define CP_WAIT0()  asm volatile("cp.async.wait_group 0;" ::: "memory")
#define CP_WAIT1()  asm volatile("cp.async.wait_group 1;" ::: "memory")

// Fragment-major u32-word index for attention K (B-operand view)
__device__ __forceinline__ int bfrag_idx(int batch, int tok, int h) {
    const int jt = tok >> 6, nf = (tok >> 3) & 7, r = tok & 7;
    const int ks = h >> 4, sel = (h >> 3) & 1, q2 = (h >> 1) & 3;
    return (((batch * 32 + jt) * 32) + nf * 4 + ks) * 64 + (r * 4 + q2) * 2 + sel;
}

// ---------------------------------------------------------------------------
// Prep: W -> fragment-major single fp16.
// ---------------------------------------------------------------------------
__global__ void wprep_kernel(const float* __restrict__ Wq,
                             const float* __restrict__ Wk,
                             const float* __restrict__ Wv) {
    const int idx = blockIdx.x * 256 + threadIdx.x;   // < 98304
    const int frag = idx >> 6, ww = idx & 63;
    const int r = ww >> 3, q2 = (ww >> 1) & 3, sel = ww & 1;
    const int ks_g = frag / 24, nb = frag % 24;
    const int n = nb * 8 + r;
    const int k = ks_g * 16 + sel * 8 + q2 * 2;
    const int mat = n >> 6, col = n & 63;
    const float* W = (mat == 0) ? Wq : (mat == 1) ? Wk : Wv;
    const float v0 = W[k * 64 + col];
    const float v1 = W[(k + 1) * 64 + col];
    reinterpret_cast<uint32_t*>(g_WFh)[idx] = f2pack(v0, v1);
}

// ---------------------------------------------------------------------------
// QKV GEMM: fp16 HMMA, X 2-term split x W single (2 MMAs per frag-pair).
// Fragment-major smem, K-chunk 64, double buffer. Epilogue:
//   Q -> row-major fp16 hi/lo (pre-scaled 0.125*log2e)
//   K -> fragment-major single fp16
//   V -> fp32 row-major
// ---------------------------------------------------------------------------
__global__ __launch_bounds__(512, 1)
void qkv_mma_kernel(const float* __restrict__ x,
                    const float* __restrict__ bq,
                    const float* __restrict__ bk,
                    const float* __restrict__ bv) {
    extern __shared__ __align__(16) char sm[];
    const int tid  = threadIdx.x;
    const int lane = tid & 31;
    const int w    = tid >> 5;
    const int m0   = (w >> 2) * 32;
    const int n0   = (w & 3) * 48;
    const int mb0  = (w >> 2) * 2;
    const int nb0  = (w & 3) * 6;
    const int r1   = lane >> 2;
    const int kq   = lane & 3;
    const int row0 = blockIdx.x * 128;

    float acc[2][6][4];
#pragma unroll
    for (int mf = 0; mf < 2; ++mf)
#pragma unroll
        for (int nf = 0; nf < 6; ++nf)
#pragma unroll
            for (int i = 0; i < 4; ++i) acc[mf][nf][i] = 0.f;

    float4 xr[4];

    auto ldg_x = [&](int k0) {
#pragma unroll
        for (int it = 0; it < 4; ++it) {
            const int e4 = tid + it * 512;
            const int m = e4 >> 4, k4 = (e4 & 15) * 4;
            xr[it] = *reinterpret_cast<const float4*>(
                &x[(size_t)(row0 + m) * kC + k0 + k4]);
        }
    };
    auto cp_w = [&](int ch, char* buf) {
        const char* wh = (const char*)g_WFh + (size_t)ch * 24576;
#pragma unroll
        for (int it = 0; it < 3; ++it) {
            const int off = (tid + it * 512) * 16;
            CP_ASYNC16(smem_addr(buf + G_BH + off), wh + off);
        }
    };
    auto sts_x = [&](char* buf) {
        uint32_t* A = reinterpret_cast<uint32_t*>(buf + G_AH);
        uint32_t* L = reinterpret_cast<uint32_t*>(buf + G_AL);
#pragma unroll
        for (int it = 0; it < 4; ++it) {
            const int e4 = tid + it * 512;
            const int m = e4 >> 4, k4 = (e4 & 15) * 4;
            const float4 v = xr[it];
            const int mb = m >> 4;
            const int ks = k4 >> 4;
            const int j  = ((k4 >> 3) & 1) * 2 + ((m >> 3) & 1);
            const int l0 = (m & 7) * 4 + ((k4 >> 1) & 3);
            const int base = (mb * 4 + ks) * 128 + j;
            const uint32_t h0 = f2pack(v.x, v.y);
            const uint32_t h1 = f2pack(v.z, v.w);
            A[base + l0 * 4]       = h0;
            A[base + (l0 + 1) * 4] = h1;
            L[base + l0 * 4]       = f2pack_lo(v.x, v.y, h0);
            L[base + (l0 + 1) * 4] = f2pack_lo(v.z, v.w, h1);
        }
    };

    ldg_x(0);
    cp_w(0, sm);
    CP_COMMIT();
    sts_x(sm);
    CP_WAIT0();
    __syncthreads();

    for (int ch = 0; ch < 16; ++ch) {
        char* buf = sm + (ch & 1) * G_BUF;
        if (ch + 1 < 16) {
            ldg_x((ch + 1) * 64);
            cp_w(ch + 1, sm + ((ch + 1) & 1) * G_BUF);
        }
        CP_COMMIT();

        const char* Ab = buf + G_AH + mb0 * 2048 + lane * 16;
        const char* Lb = buf + G_AL + mb0 * 2048 + lane * 16;
        const char* Bh = buf + G_BH + nb0 * 256 + lane * 8;

#pragma unroll
        for (int ks = 0; ks < 4; ++ks) {
            uint4 ah4[2], al4[2];
#pragma unroll
            for (int mf = 0; mf < 2; ++mf) {
                const int aoff = (mf * 4 + ks) * 512;
                ah4[mf] = *reinterpret_cast<const uint4*>(Ab + aoff);
                al4[mf] = *reinterpret_cast<const uint4*>(Lb + aoff);
            }
#pragma unroll
            for (int nf = 0; nf < 6; ++nf) {
                const int boff = (ks * 24 + nf) * 256;
                uint2 bh = *reinterpret_cast<const uint2*>(Bh + boff);
#pragma unroll
                for (int mf = 0; mf < 2; ++mf) {
                    mma16816(acc[mf][nf], reinterpret_cast<uint32_t*>(&ah4[mf]),
                             reinterpret_cast<uint32_t*>(&bh));
                    mma16816(acc[mf][nf], reinterpret_cast<uint32_t*>(&al4[mf]),
                             reinterpret_cast<uint32_t*>(&bh));
                }
            }
        }

        if (ch + 1 < 16) {
            __syncthreads();
            sts_x(sm + ((ch + 1) & 1) * G_BUF);
            CP_WAIT0();
            __syncthreads();
        }
    }

    // ---- epilogue ----
    uint32_t* KFh = reinterpret_cast<uint32_t*>(g_KFh);
#pragma unroll
    for (int mf = 0; mf < 2; ++mf) {
        const int rg = row0 + m0 + mf * 16 + r1;
#pragma unroll
        for (int nf = 0; nf < 6; ++nf) {
            const int col = n0 + nf * 8 + kq * 2;
            const int mat = col >> 6, h = col & 63;
            const float* bias = (mat == 0) ? bq : (mat == 1) ? bk : bv;
            const float b0 = bias[h], b1 = bias[h + 1];
            const float v00 = acc[mf][nf][0] + b0;
            const float v01 = acc[mf][nf][1] + b1;
            const float v10 = acc[mf][nf][2] + b0;
            const float v11 = acc[mf][nf][3] + b1;
            if (mat == 2) {
                float2 a = {v00, v01}, bvv = {v10, v11};
                *reinterpret_cast<float2*>(g_V + (size_t)rg * kH + h) = a;
                *reinterpret_cast<float2*>(g_V + (size_t)(rg + 8) * kH + h) = bvv;
            } else if (mat == 1) {
                const int batch = rg >> 11, tok = rg & 2047;
                KFh[bfrag_idx(batch, tok, h)]     = f2pack(v00, v01);
                KFh[bfrag_idx(batch, tok + 8, h)] = f2pack(v10, v11);
            } else {
                const float scl = 0.125f * 1.44269504f;
                const uint32_t h0 = f2pack(v00 * scl, v01 * scl);
                const uint32_t h1 = f2pack(v10 * scl, v11 * scl);
                *reinterpret_cast<uint32_t*>(g_Qh + (size_t)rg * kH + h) = h0;
                *reinterpret_cast<uint32_t*>(g_Ql + (size_t)rg * kH + h) =
                    f2pack_lo(v00 * scl, v01 * scl, h0);
                *reinterpret_cast<uint32_t*>(g_Qh + (size_t)(rg + 8) * kH + h) = h1;
                *reinterpret_cast<uint32_t*>(g_Ql + (size_t)(rg + 8) * kH + h) =
                    f2pack_lo(v10 * scl, v11 * scl, h1);
            }
        }
    }
}

// ---------------------------------------------------------------------------
// V transpose + fp16 hi/lo split -> FRAGMENT-MAJOR g_VFh/g_VFl
// ---------------------------------------------------------------------------
__global__ __launch_bounds__(256)
void vtrans_kernel() {
    __shared__ float tile[64][65];
    const int blk = blockIdx.x;            // kB * 32
    const int b = blk >> 5, jt = blk & 31;
    const int t0 = jt * 64;
    const int tid = threadIdx.x;
    const float* src = g_V + ((size_t)b * kT + t0) * kH;
    uint32_t* VFh = reinterpret_cast<uint32_t*>(g_VFh);
    uint32_t* VFl = reinterpret_cast<uint32_t*>(g_VFl);
#pragma unroll
    for (int i = 0; i < 16; ++i) {
        const int idx = tid + i * 256;
        tile[idx >> 6][idx & 63] = src[idx];
    }
    __syncthreads();
#pragma unroll
    for (int i = 0; i < 8; ++i) {
        const int idx = tid + i * 256;     // 2048 pairs
        const int h = idx >> 5, tp = (idx & 31) * 2;
        const float v0 = tile[tp][h], v1 = tile[tp + 1][h];
        const int ks = tp >> 4, sel = (tp >> 3) & 1;
        const int lane2 = (h & 7) * 4 + ((tp >> 1) & 3);
        const int widx = (((b * 32 + jt) * 32) + (h >> 3) * 4 + ks) * 64
                         + lane2 * 2 + sel;
        const uint32_t hp = f2pack(v0, v1);
        VFh[widx] = hp;
        VFl[widx] = f2pack_lo(v0, v1, hp);
    }
}

// ---------------------------------------------------------------------------
// Causal flash attention: BM=64, 4 warps, occ 3, fragment-major smem,
// Q (hi/lo fp16) in registers. QK = 2 MMAs (Q split x K single);
// PV = 3 MMAs (P split x V split, minus lo*lo). exp2 softmax.
// ---------------------------------------------------------------------------
__global__ __launch_bounds__(128, 3)
void attn_mma_kernel(float* __restrict__ out) {
    extern __shared__ __align__(16) char sma[];

    const int tid  = threadIdx.x;
    const int lane = tid & 31;
    const int w    = tid >> 5;
    const int b    = blockIdx.x & 15;
    const int qt   = (kQT - 1) - (blockIdx.x >> 4);
    const int q0   = qt * 64;
    const int m0w  = w * 16;
    const int r1   = lane >> 2;
    const int kq   = lane & 3;

    uint32_t qhi[4][4], qlo[4][4];
    {
        const uint32_t* qh =
            reinterpret_cast<const uint32_t*>(g_Qh + ((size_t)b * kT + q0) * kH);
        const uint32_t* ql =
            reinterpret_cast<const uint32_t*>(g_Ql + ((size_t)b * kT + q0) * kH);
        const int rA = (m0w + r1) * 32, rB = rA + 8 * 32;
#pragma unroll
        for (int ks = 0; ks < 4; ++ks) {
            const int c0 = ks * 8 + kq;
            qhi[ks][0] = qh[rA + c0];
            qhi[ks][1] = qh[rB + c0];
            qhi[ks][2] = qh[rA + c0 + 4];
            qhi[ks][3] = qh[rB + c0 + 4];
            qlo[ks][0] = ql[rA + c0];
            qlo[ks][1] = ql[rB + c0];
            qlo[ks][2] = ql[rA + c0 + 4];
            qlo[ks][3] = ql[rB + c0 + 4];
        }
    }

    auto stage = [&](int jt, char* buf) {
        const size_t base = ((size_t)b * 32 + jt) * 8192;
        const char* kh = (const char*)g_KFh + base;
        const char* vh = (const char*)g_VFh + base;
        const char* vl = (const char*)g_VFl + base;
#pragma unroll
        for (int i = 0; i < 4; ++i) {
            const int off = (tid + i * 128) * 16;
            CP_ASYNC16(smem_addr(buf + BK_KH + off), kh + off);
            CP_ASYNC16(smem_addr(buf + BK_VH + off), vh + off);
            CP_ASYNC16(smem_addr(buf + BK_VL + off), vl + off);
        }
    };

    float o[8][4];
#pragma unroll
    for (int nf = 0; nf < 8; ++nf)
#pragma unroll
        for (int c = 0; c < 4; ++c) o[nf][c] = 0.f;
    float mrow[2] = {-1e30f, -1e30f};
    float lrow[2] = {0.f, 0.f};

    stage(0, sma);
    CP_COMMIT();

    for (int jt = 0; jt <= qt; ++jt) {
        if (jt + 1 <= qt) stage(jt + 1, sma + ((jt + 1) & 1) * ABUFSZ);
        CP_COMMIT();
        CP_WAIT1();
        __syncthreads();

        char* buf = sma + (jt & 1) * ABUFSZ;
        const char* Kh = buf + BK_KH + lane * 8;
        const char* Vh = buf + BK_VH + lane * 8;
        const char* Vl = buf + BK_VL + lane * 8;

        // ---- S = Q K^T (Q 2-term split x K single) ----
        float s[8][4];
#pragma unroll
        for (int nf = 0; nf < 8; ++nf)
#pragma unroll
            for (int c = 0; c < 4; ++c) s[nf][c] = 0.f;

#pragma unroll
        for (int ks = 0; ks < 4; ++ks) {
#pragma unroll
            for (int nf = 0; nf < 8; ++nf) {
                const int boff = (nf * 4 + ks) * 256;
                uint2 bh = *reinterpret_cast<const uint2*>(Kh + boff);
                mma16816(s[nf], qhi[ks], reinterpret_cast<uint32_t*>(&bh));
                mma16816(s[nf], qlo[ks], reinterpret_cast<uint32_t*>(&bh));
            }
        }

        // ---- causal mask (diagonal tile only) + online softmax (exp2) ----
        float mx1 = -1e30f, mx2 = -1e30f;
        if (jt == qt) {
            const int qg1 = q0 + m0w + r1;
            const int qg2 = qg1 + 8;
#pragma unroll
            for (int nf = 0; nf < 8; ++nf) {
                const int kg0 = jt * 64 + nf * 8 + kq * 2;
                s[nf][0] = (kg0     <= qg1) ? s[nf][0] : -1e30f;
                s[nf][1] = (kg0 + 1 <= qg1) ? s[nf][1] : -1e30f;
                s[nf][2] = (kg0     <= qg2) ? s[nf][2] : -1e30f;
                s[nf][3] = (kg0 + 1 <= qg2) ? s[nf][3] : -1e30f;
            }
        }
#pragma unroll
        for (int nf = 0; nf < 8; ++nf) {
            mx1 = fmaxf(mx1, fmaxf(s[nf][0], s[nf][1]));
            mx2 = fmaxf(mx2, fmaxf(s[nf][2], s[nf][3]));
        }
        mx1 = fmaxf(mx1, __shfl_xor_sync(0xffffffffu, mx1, 1));
        mx1 = fmaxf(mx1, __shfl_xor_sync(0xffffffffu, mx1, 2));
        mx2 = fmaxf(mx2, __shfl_xor_sync(0xffffffffu, mx2, 1));
        mx2 = fmaxf(mx2, __shfl_xor_sync(0xffffffffu, mx2, 2));

        const float mn1 = fmaxf(mrow[0], mx1);
        const float mn2 = fmaxf(mrow[1], mx2);
        const float a1 = exp2f(mrow[0] - mn1);
        const float a2 = exp2f(mrow[1] - mn2);
        mrow[0] = mn1; mrow[1] = mn2;

        float rs1 = 0.f, rs2 = 0.f;
#pragma unroll
        for (int nf = 0; nf < 8; ++nf) {
            s[nf][0] = exp2f(s[nf][0] - mn1);
            s[nf][1] = exp2f(s[nf][1] - mn1);
            s[nf][2] = exp2f(s[nf][2] - mn2);
            s[nf][3] = exp2f(s[nf][3] - mn2);
            rs1 += s[nf][0] + s[nf][1];
            rs2 += s[nf][2] + s[nf][3];
        }
        rs1 += __shfl_xor_sync(0xffffffffu, rs1, 1);
        rs1 += __shfl_xor_sync(0xffffffffu, rs1, 2);
        rs2 += __shfl_xor_sync(0xffffffffu, rs2, 1);
        rs2 += __shfl_xor_sync(0xffffffffu, rs2, 2);
        lrow[0] = lrow[0] * a1 + rs1;
        lrow[1] = lrow[1] * a2 + rs2;
#pragma unroll
        for (int nf = 0; nf < 8; ++nf) {
            o[nf][0] *= a1; o[nf][1] *= a1;
            o[nf][2] *= a2; o[nf][3] *= a2;
        }

        // ---- O += P V (P split x V split, 3 terms) ----
#pragma unroll
        for (int ks = 0; ks < 4; ++ks) {
            uint32_t pah[4], pal[4];
            const float* s0 = s[2 * ks];
            const float* s1 = s[2 * ks + 1];
            pah[0] = f2pack(s0[0], s0[1]);
            pah[1] = f2pack(s0[2], s0[3]);
            pah[2] = f2pack(s1[0], s1[1]);
            pah[3] = f2pack(s1[2], s1[3]);
            pal[0] = f2pack_lo(s0[0], s0[1], pah[0]);
            pal[1] = f2pack_lo(s0[2], s0[3], pah[1]);
            pal[2] = f2pack_lo(s1[0], s1[1], pah[2]);
            pal[3] = f2pack_lo(s1[2], s1[3], pah[3]);
#pragma unroll
            for (int nf = 0; nf < 8; ++nf) {
                const int boff = (nf * 4 + ks) * 256;
                uint2 vh = *reinterpret_cast<const uint2*>(Vh + boff);
                uint2 vl = *reinterpret_cast<const uint2*>(Vl + boff);
                mma16816(o[nf], pah, reinterpret_cast<uint32_t*>(&vh));
                mma16816(o[nf], pah, reinterpret_cast<uint32_t*>(&vl));
                mma16816(o[nf], pal, reinterpret_cast<uint32_t*>(&vh));
            }
        }
        __syncthreads();
    }

    const float inv1 = 1.0f / lrow[0];
    const float inv2 = 1.0f / lrow[1];
    float* og = out + ((size_t)b * kT + q0 + m0w) * kH;
#pragma unroll
    for (int nf = 0; nf < 8; ++nf) {
        const int col = nf * 8 + kq * 2;
        float2 v0, v1;
        v0.x = o[nf][0] * inv1; v0.y = o[nf][1] * inv1;
        v1.x = o[nf][2] * inv2; v1.y = o[nf][3] * inv2;
        *reinterpret_cast<float2*>(&og[r1 * kH + col]) = v0;
        *reinterpret_cast<float2*>(&og[(r1 + 8) * kH + col]) = v1;
    }
}

// ---------------------------------------------------------------------------
extern "C" void kernel_launch(void* const* d_in, const int* in_sizes, int n_in,
                              void* d_out, int out_size) {
    (void)in_sizes; (void)n_in; (void)out_size;
    const float* x  = (const float*)d_in[0];
    const float* Wq = (const float*)d_in[1];
    const float* bq = (const float*)d_in[2];
    const float* Wk = (const float*)d_in[3];
    const float* bk = (const float*)d_in[4];
    const float* Wv = (const float*)d_in[5];
    const float* bv = (const float*)d_in[6];
    float* out = (float*)d_out;

    wprep_kernel<<<384, 256>>>(Wq, Wk, Wv);

    cudaFuncSetAttribute(qkv_mma_kernel, cudaFuncAttributeMaxDynamicSharedMemorySize,
                         QKV_SMEM);
    qkv_mma_kernel<<<kRows / 128, 512, QKV_SMEM>>>(x, bq, bk, bv);

    vtrans_kernel<<<kB * 32, 256>>>();

    cudaFuncSetAttribute(attn_mma_kernel, cudaFuncAttributeMaxDynamicSharedMemorySize,
                         ATTN_SMEM);
    attn_mma_kernel<<<kB * kQT, 128, ATTN_SMEM>>>(out);
}

// round 11
// speedup vs baseline: 1.7312x; 1.1654x over previous
#include <cuda_runtime.h>
#include <cuda_fp16.h>
#include <cstdint>

// ---------------------------------------------------------------------------
// Problem constants
// ---------------------------------------------------------------------------
namespace {
constexpr int kB = 16;
constexpr int kT = 2048;
constexpr int kC = 1024;
constexpr int kH = 64;
constexpr int kRows = kB * kT;     // 32768
constexpr int kQT = kT / 64;       // 32 q-tiles per batch

// QKV GEMM smem (bytes): fragment-major, K-chunk 64, double buffer
constexpr int G_AH = 0;            // 32 A-frags x 512B (X hi)
constexpr int G_AL = 16384;        // X lo
constexpr int G_BH = 32768;        // 96 B-frags x 256B (W, single)
constexpr int G_BUF = 57344;
constexpr int QKV_SMEM = 2 * G_BUF;          // 114688

// Attention smem (bytes): fragment-major contiguous tiles, all single fp16
constexpr int BK_KH = 0;           // K single (8KB)
constexpr int BK_VH = 8192;        // V single (8KB)
constexpr int ABUFSZ = 16384;
constexpr int ATTN_SMEM = 2 * ABUFSZ;        // 32768
}

// Scratch (__device__ globals: allocation-free)
__device__ float g_V[kRows * kH];
__device__ __half g_Qh[kRows * kH];                 // Q single fp16 (pre-scaled)
__device__ __half g_KFh[kRows * kH];                // K single, fragment-major
__device__ __half g_VFh[kB * kH * kT];              // V^T single, fragment-major
__device__ __half g_WFh[192 * 1024];                // W single, fragment-major

// ---------------------------------------------------------------------------
// PTX helpers (baseline sm_80+ — survive compute_103 lowering)
// ---------------------------------------------------------------------------
__device__ __forceinline__ void mma16816(float* d, const uint32_t* a,
                                         const uint32_t* b) {
    asm volatile(
        "mma.sync.aligned.m16n8k16.row.col.f32.f16.f16.f32 "
        "{%0,%1,%2,%3}, {%4,%5,%6,%7}, {%8,%9}, {%0,%1,%2,%3};"
        : "+f"(d[0]), "+f"(d[1]), "+f"(d[2]), "+f"(d[3])
        : "r"(a[0]), "r"(a[1]), "r"(a[2]), "r"(a[3]), "r"(b[0]), "r"(b[1]));
}
__device__ __forceinline__ uint32_t f2pack(float lo, float hi) {
    uint32_t r;
    asm("cvt.rn.f16x2.f32 %0, %1, %2;" : "=r"(r) : "f"(hi), "f"(lo));
    return r;
}
__device__ __forceinline__ uint32_t f2pack_lo(float lo, float hi, uint32_t hp) {
    const __half2 h = *reinterpret_cast<const __half2*>(&hp);
    const float rl = lo - __low2float(h);
    const float rh = hi - __high2float(h);
    return f2pack(rl, rh);
}
__device__ __forceinline__ uint32_t smem_addr(const void* p) {
    return (uint32_t)__cvta_generic_to_shared(p);
}
#define CP_ASYNC16(dst, src) \
    asm volatile("cp.async.cg.shared.global [%0], [%1], 16;" \
                 :: "r"(dst), "l"(src))
#define CP_COMMIT() asm volatile("cp.async.commit_group;" ::: "memory")
#define CP_WAIT0()  asm volatile("cp.async.wait_group 0;" ::: "memory")
#define CP_WAIT1()  asm volatile("cp.async.wait_group 1;" ::: "memory")

// Fragment-major u32-word index for attention K (B-operand view)
__device__ __forceinline__ int bfrag_idx(int batch, int tok, int h) {
    const int jt = tok >> 6, nf = (tok >> 3) & 7, r = tok & 7;
    const int ks = h >> 4, sel = (h >> 3) & 1, q2 = (h >> 1) & 3;
    return (((batch * 32 + jt) * 32) + nf * 4 + ks) * 64 + (r * 4 + q2) * 2 + sel;
}

// ---------------------------------------------------------------------------
// Prep: W -> fragment-major single fp16.
// ---------------------------------------------------------------------------
__global__ void wprep_kernel(const float* __restrict__ Wq,
                             const float* __restrict__ Wk,
                             const float* __restrict__ Wv) {
    const int idx = blockIdx.x * 256 + threadIdx.x;   // < 98304
    const int frag = idx >> 6, ww = idx & 63;
    const int r = ww >> 3, q2 = (ww >> 1) & 3, sel = ww & 1;
    const int ks_g = frag / 24, nb = frag % 24;
    const int n = nb * 8 + r;
    const int k = ks_g * 16 + sel * 8 + q2 * 2;
    const int mat = n >> 6, col = n & 63;
    const float* W = (mat == 0) ? Wq : (mat == 1) ? Wk : Wv;
    const float v0 = W[k * 64 + col];
    const float v1 = W[(k + 1) * 64 + col];
    reinterpret_cast<uint32_t*>(g_WFh)[idx] = f2pack(v0, v1);
}

// ---------------------------------------------------------------------------
// QKV GEMM (R10-validated, ~67us): fp16 HMMA, X 2-term split x W single.
// Epilogue: Q single fp16 (pre-scaled 0.125*log2e), K fragment-major single,
// V fp32 row-major.
// ---------------------------------------------------------------------------
__global__ __launch_bounds__(512, 1)
void qkv_mma_kernel(const float* __restrict__ x,
                    const float* __restrict__ bq,
                    const float* __restrict__ bk,
                    const float* __restrict__ bv) {
    extern __shared__ __align__(16) char sm[];
    const int tid  = threadIdx.x;
    const int lane = tid & 31;
    const int w    = tid >> 5;
    const int m0   = (w >> 2) * 32;
    const int n0   = (w & 3) * 48;
    const int mb0  = (w >> 2) * 2;
    const int nb0  = (w & 3) * 6;
    const int r1   = lane >> 2;
    const int kq   = lane & 3;
    const int row0 = blockIdx.x * 128;

    float acc[2][6][4];
#pragma unroll
    for (int mf = 0; mf < 2; ++mf)
#pragma unroll
        for (int nf = 0; nf < 6; ++nf)
#pragma unroll
            for (int i = 0; i < 4; ++i) acc[mf][nf][i] = 0.f;

    float4 xr[4];

    auto ldg_x = [&](int k0) {
#pragma unroll
        for (int it = 0; it < 4; ++it) {
            const int e4 = tid + it * 512;
            const int m = e4 >> 4, k4 = (e4 & 15) * 4;
            xr[it] = *reinterpret_cast<const float4*>(
                &x[(size_t)(row0 + m) * kC + k0 + k4]);
        }
    };
    auto cp_w = [&](int ch, char* buf) {
        const char* wh = (const char*)g_WFh + (size_t)ch * 24576;
#pragma unroll
        for (int it = 0; it < 3; ++it) {
            const int off = (tid + it * 512) * 16;
            CP_ASYNC16(smem_addr(buf + G_BH + off), wh + off);
        }
    };
    auto sts_x = [&](char* buf) {
        uint32_t* A = reinterpret_cast<uint32_t*>(buf + G_AH);
        uint32_t* L = reinterpret_cast<uint32_t*>(buf + G_AL);
#pragma unroll
        for (int it = 0; it < 4; ++it) {
            const int e4 = tid + it * 512;
            const int m = e4 >> 4, k4 = (e4 & 15) * 4;
            const float4 v = xr[it];
            const int mb = m >> 4;
            const int ks = k4 >> 4;
            const int j  = ((k4 >> 3) & 1) * 2 + ((m >> 3) & 1);
            const int l0 = (m & 7) * 4 + ((k4 >> 1) & 3);
            const int base = (mb * 4 + ks) * 128 + j;
            const uint32_t h0 = f2pack(v.x, v.y);
            const uint32_t h1 = f2pack(v.z, v.w);
            A[base + l0 * 4]       = h0;
            A[base + (l0 + 1) * 4] = h1;
            L[base + l0 * 4]       = f2pack_lo(v.x, v.y, h0);
            L[base + (l0 + 1) * 4] = f2pack_lo(v.z, v.w, h1);
        }
    };

    ldg_x(0);
    cp_w(0, sm);
    CP_COMMIT();
    sts_x(sm);
    CP_WAIT0();
    __syncthreads();

    for (int ch = 0; ch < 16; ++ch) {
        char* buf = sm + (ch & 1) * G_BUF;
        if (ch + 1 < 16) {
            ldg_x((ch + 1) * 64);
            cp_w(ch + 1, sm + ((ch + 1) & 1) * G_BUF);
        }
        CP_COMMIT();

        const char* Ab = buf + G_AH + mb0 * 2048 + lane * 16;
        const char* Lb = buf + G_AL + mb0 * 2048 + lane * 16;
        const char* Bh = buf + G_BH + nb0 * 256 + lane * 8;

#pragma unroll
        for (int ks = 0; ks < 4; ++ks) {
            uint4 ah4[2], al4[2];
#pragma unroll
            for (int mf = 0; mf < 2; ++mf) {
                const int aoff = (mf * 4 + ks) * 512;
                ah4[mf] = *reinterpret_cast<const uint4*>(Ab + aoff);
                al4[mf] = *reinterpret_cast<const uint4*>(Lb + aoff);
            }
#pragma unroll
            for (int nf = 0; nf < 6; ++nf) {
                const int boff = (ks * 24 + nf) * 256;
                uint2 bh = *reinterpret_cast<const uint2*>(Bh + boff);
#pragma unroll
                for (int mf = 0; mf < 2; ++mf) {
                    mma16816(acc[mf][nf], reinterpret_cast<uint32_t*>(&ah4[mf]),
                             reinterpret_cast<uint32_t*>(&bh));
                    mma16816(acc[mf][nf], reinterpret_cast<uint32_t*>(&al4[mf]),
                             reinterpret_cast<uint32_t*>(&bh));
                }
            }
        }

        if (ch + 1 < 16) {
            __syncthreads();
            sts_x(sm + ((ch + 1) & 1) * G_BUF);
            CP_WAIT0();
            __syncthreads();
        }
    }

    // ---- epilogue ----
    uint32_t* KFh = reinterpret_cast<uint32_t*>(g_KFh);
#pragma unroll
    for (int mf = 0; mf < 2; ++mf) {
        const int rg = row0 + m0 + mf * 16 + r1;
#pragma unroll
        for (int nf = 0; nf < 6; ++nf) {
            const int col = n0 + nf * 8 + kq * 2;
            const int mat = col >> 6, h = col & 63;
            const float* bias = (mat == 0) ? bq : (mat == 1) ? bk : bv;
            const float b0 = bias[h], b1 = bias[h + 1];
            const float v00 = acc[mf][nf][0] + b0;
            const float v01 = acc[mf][nf][1] + b1;
            const float v10 = acc[mf][nf][2] + b0;
            const float v11 = acc[mf][nf][3] + b1;
            if (mat == 2) {
                float2 a = {v00, v01}, bvv = {v10, v11};
                *reinterpret_cast<float2*>(g_V + (size_t)rg * kH + h) = a;
                *reinterpret_cast<float2*>(g_V + (size_t)(rg + 8) * kH + h) = bvv;
            } else if (mat == 1) {
                const int batch = rg >> 11, tok = rg & 2047;
                KFh[bfrag_idx(batch, tok, h)]     = f2pack(v00, v01);
                KFh[bfrag_idx(batch, tok + 8, h)] = f2pack(v10, v11);
            } else {
                const float scl = 0.125f * 1.44269504f;
                *reinterpret_cast<uint32_t*>(g_Qh + (size_t)rg * kH + h) =
                    f2pack(v00 * scl, v01 * scl);
                *reinterpret_cast<uint32_t*>(g_Qh + (size_t)(rg + 8) * kH + h) =
                    f2pack(v10 * scl, v11 * scl);
            }
        }
    }
}

// ---------------------------------------------------------------------------
// V transpose -> FRAGMENT-MAJOR single fp16 g_VFh
// ---------------------------------------------------------------------------
__global__ __launch_bounds__(256)
void vtrans_kernel() {
    __shared__ float tile[64][65];
    const int blk = blockIdx.x;            // kB * 32
    const int b = blk >> 5, jt = blk & 31;
    const int t0 = jt * 64;
    const int tid = threadIdx.x;
    const float* src = g_V + ((size_t)b * kT + t0) * kH;
    uint32_t* VFh = reinterpret_cast<uint32_t*>(g_VFh);
#pragma unroll
    for (int i = 0; i < 16; ++i) {
        const int idx = tid + i * 256;
        tile[idx >> 6][idx & 63] = src[idx];
    }
    __syncthreads();
#pragma unroll
    for (int i = 0; i < 8; ++i) {
        const int idx = tid + i * 256;     // 2048 pairs
        const int h = idx >> 5, tp = (idx & 31) * 2;
        const float v0 = tile[tp][h], v1 = tile[tp + 1][h];
        const int ks = tp >> 4, sel = (tp >> 3) & 1;
        const int lane2 = (h & 7) * 4 + ((tp >> 1) & 3);
        const int widx = (((b * 32 + jt) * 32) + (h >> 3) * 4 + ks) * 64
                         + lane2 * 2 + sel;
        VFh[widx] = f2pack(v0, v1);
    }
}

// ---------------------------------------------------------------------------
// Causal flash attention: BM=64, 4 warps, occ 3, fragment-major smem.
// QK = 1 MMA (Q single x K single); PV = 2 MMAs (P hi/lo x V single).
// exp2-domain softmax; Q in registers; cp.async double buffer.
// ---------------------------------------------------------------------------
__global__ __launch_bounds__(128, 3)
void attn_mma_kernel(float* __restrict__ out) {
    extern __shared__ __align__(16) char sma[];

    const int tid  = threadIdx.x;
    const int lane = tid & 31;
    const int w    = tid >> 5;
    const int b    = blockIdx.x & 15;
    const int qt   = (kQT - 1) - (blockIdx.x >> 4);
    const int q0   = qt * 64;
    const int m0w  = w * 16;
    const int r1   = lane >> 2;
    const int kq   = lane & 3;

    uint32_t qhi[4][4];
    {
        const uint32_t* qh =
            reinterpret_cast<const uint32_t*>(g_Qh + ((size_t)b * kT + q0) * kH);
        const int rA = (m0w + r1) * 32, rB = rA + 8 * 32;
#pragma unroll
        for (int ks = 0; ks < 4; ++ks) {
            const int c0 = ks * 8 + kq;
            qhi[ks][0] = qh[rA + c0];
            qhi[ks][1] = qh[rB + c0];
            qhi[ks][2] = qh[rA + c0 + 4];
            qhi[ks][3] = qh[rB + c0 + 4];
        }
    }

    auto stage = [&](int jt, char* buf) {
        const size_t base = ((size_t)b * 32 + jt) * 8192;
        const char* kh = (const char*)g_KFh + base;
        const char* vh = (const char*)g_VFh + base;
#pragma unroll
        for (int i = 0; i < 4; ++i) {
            const int off = (tid + i * 128) * 16;
            CP_ASYNC16(smem_addr(buf + BK_KH + off), kh + off);
            CP_ASYNC16(smem_addr(buf + BK_VH + off), vh + off);
        }
    };

    float o[8][4];
#pragma unroll
    for (int nf = 0; nf < 8; ++nf)
#pragma unroll
        for (int c = 0; c < 4; ++c) o[nf][c] = 0.f;
    float mrow[2] = {-1e30f, -1e30f};
    float lrow[2] = {0.f, 0.f};

    stage(0, sma);
    CP_COMMIT();

    for (int jt = 0; jt <= qt; ++jt) {
        if (jt + 1 <= qt) stage(jt + 1, sma + ((jt + 1) & 1) * ABUFSZ);
        CP_COMMIT();
        CP_WAIT1();
        __syncthreads();

        char* buf = sma + (jt & 1) * ABUFSZ;
        const char* Kh = buf + BK_KH + lane * 8;
        const char* Vh = buf + BK_VH + lane * 8;

        // ---- S = Q K^T (single x single) ----
        float s[8][4];
#pragma unroll
        for (int nf = 0; nf < 8; ++nf)
#pragma unroll
            for (int c = 0; c < 4; ++c) s[nf][c] = 0.f;

#pragma unroll
        for (int ks = 0; ks < 4; ++ks) {
#pragma unroll
            for (int nf = 0; nf < 8; ++nf) {
                const int boff = (nf * 4 + ks) * 256;
                uint2 bh = *reinterpret_cast<const uint2*>(Kh + boff);
                mma16816(s[nf], qhi[ks], reinterpret_cast<uint32_t*>(&bh));
            }
        }

        // ---- causal mask (diagonal tile only) + online softmax (exp2) ----
        float mx1 = -1e30f, mx2 = -1e30f;
        if (jt == qt) {
            const int qg1 = q0 + m0w + r1;
            const int qg2 = qg1 + 8;
#pragma unroll
            for (int nf = 0; nf < 8; ++nf) {
                const int kg0 = jt * 64 + nf * 8 + kq * 2;
                s[nf][0] = (kg0     <= qg1) ? s[nf][0] : -1e30f;
                s[nf][1] = (kg0 + 1 <= qg1) ? s[nf][1] : -1e30f;
                s[nf][2] = (kg0     <= qg2) ? s[nf][2] : -1e30f;
                s[nf][3] = (kg0 + 1 <= qg2) ? s[nf][3] : -1e30f;
            }
        }
#pragma unroll
        for (int nf = 0; nf < 8; ++nf) {
            mx1 = fmaxf(mx1, fmaxf(s[nf][0], s[nf][1]));
            mx2 = fmaxf(mx2, fmaxf(s[nf][2], s[nf][3]));
        }
        mx1 = fmaxf(mx1, __shfl_xor_sync(0xffffffffu, mx1, 1));
        mx1 = fmaxf(mx1, __shfl_xor_sync(0xffffffffu, mx1, 2));
        mx2 = fmaxf(mx2, __shfl_xor_sync(0xffffffffu, mx2, 1));
        mx2 = fmaxf(mx2, __shfl_xor_sync(0xffffffffu, mx2, 2));

        const float mn1 = fmaxf(mrow[0], mx1);
        const float mn2 = fmaxf(mrow[1], mx2);
        const float a1 = exp2f(mrow[0] - mn1);
        const float a2 = exp2f(mrow[1] - mn2);
        mrow[0] = mn1; mrow[1] = mn2;

        float rs1 = 0.f, rs2 = 0.f;
#pragma unroll
        for (int nf = 0; nf < 8; ++nf) {
            s[nf][0] = exp2f(s[nf][0] - mn1);
            s[nf][1] = exp2f(s[nf][1] - mn1);
            s[nf][2] = exp2f(s[nf][2] - mn2);
            s[nf][3] = exp2f(s[nf][3] - mn2);
            rs1 += s[nf][0] + s[nf][1];
            rs2 += s[nf][2] + s[nf][3];
        }
        rs1 += __shfl_xor_sync(0xffffffffu, rs1, 1);
        rs1 += __shfl_xor_sync(0xffffffffu, rs1, 2);
        rs2 += __shfl_xor_sync(0xffffffffu, rs2, 1);
        rs2 += __shfl_xor_sync(0xffffffffu, rs2, 2);
        lrow[0] = lrow[0] * a1 + rs1;
        lrow[1] = lrow[1] * a2 + rs2;
#pragma unroll
        for (int nf = 0; nf < 8; ++nf) {
            o[nf][0] *= a1; o[nf][1] *= a1;
            o[nf][2] *= a2; o[nf][3] *= a2;
        }

        // ---- O += P V (P hi/lo x V single) ----
#pragma unroll
        for (int ks = 0; ks < 4; ++ks) {
            uint32_t pah[4], pal[4];
            const float* s0 = s[2 * ks];
            const float* s1 = s[2 * ks + 1];
            pah[0] = f2pack(s0[0], s0[1]);
            pah[1] = f2pack(s0[2], s0[3]);
            pah[2] = f2pack(s1[0], s1[1]);
            pah[3] = f2pack(s1[2], s1[3]);
            pal[0] = f2pack_lo(s0[0], s0[1], pah[0]);
            pal[1] = f2pack_lo(s0[2], s0[3], pah[1]);
            pal[2] = f2pack_lo(s1[0], s1[1], pah[2]);
            pal[3] = f2pack_lo(s1[2], s1[3], pah[3]);
#pragma unroll
            for (int nf = 0; nf < 8; ++nf) {
                const int boff = (nf * 4 + ks) * 256;
                uint2 vh = *reinterpret_cast<const uint2*>(Vh + boff);
                mma16816(o[nf], pah, reinterpret_cast<uint32_t*>(&vh));
                mma16816(o[nf], pal, reinterpret_cast<uint32_t*>(&vh));
            }
        }
        __syncthreads();
    }

    const float inv1 = 1.0f / lrow[0];
    const float inv2 = 1.0f / lrow[1];
    float* og = out + ((size_t)b * kT + q0 + m0w) * kH;
#pragma unroll
    for (int nf = 0; nf < 8; ++nf) {
        const int col = nf * 8 + kq * 2;
        float2 v0, v1;
        v0.x = o[nf][0] * inv1; v0.y = o[nf][1] * inv1;
        v1.x = o[nf][2] * inv2; v1.y = o[nf][3] * inv2;
        *reinterpret_cast<float2*>(&og[r1 * kH + col]) = v0;
        *reinterpret_cast<float2*>(&og[(r1 + 8) * kH + col]) = v1;
    }
}

// ---------------------------------------------------------------------------
extern "C" void kernel_launch(void* const* d_in, const int* in_sizes, int n_in,
                              void* d_out, int out_size) {
    (void)in_sizes; (void)n_in; (void)out_size;
    const float* x  = (const float*)d_in[0];
    const float* Wq = (const float*)d_in[1];
    const float* bq = (const float*)d_in[2];
    const float* Wk = (const float*)d_in[3];
    const float* bk = (const float*)d_in[4];
    const float* Wv = (const float*)d_in[5];
    const float* bv = (const float*)d_in[6];
    float* out = (float*)d_out;

    wprep_kernel<<<384, 256>>>(Wq, Wk, Wv);

    cudaFuncSetAttribute(qkv_mma_kernel, cudaFuncAttributeMaxDynamicSharedMemorySize,
                         QKV_SMEM);
    qkv_mma_kernel<<<kRows / 128, 512, QKV_SMEM>>>(x, bq, bk, bv);

    vtrans_kernel<<<kB * 32, 256>>>();

    cudaFuncSetAttribute(attn_mma_kernel, cudaFuncAttributeMaxDynamicSharedMemorySize,
                         ATTN_SMEM);
    attn_mma_kernel<<<kB * kQT, 128, ATTN_SMEM>>>(out);
}

// round 12
// speedup vs baseline: 2.1944x; 1.2676x over previous
#include <cuda_runtime.h>
#include <cuda_fp16.h>
#include <cstdint>

// ---------------------------------------------------------------------------
// Problem constants
// ---------------------------------------------------------------------------
namespace {
constexpr int kB = 16;
constexpr int kT = 2048;
constexpr int kC = 1024;
constexpr int kH = 64;
constexpr int kRows = kB * kT;     // 32768
constexpr int kQT = kT / 64;       // 32 q-tiles per batch

// QKV GEMM smem (bytes): fragment-major, K-chunk 64, double buffer
constexpr int G_AH = 0;            // 32 A-frags x 512B (X single)
constexpr int G_BH = 16384;        // 96 B-frags x 256B (W single)
constexpr int G_BUF = 40960;
constexpr int QKV_SMEM = 2 * G_BUF;          // 81920

// Attention smem (bytes): fragment-major contiguous tiles, all single fp16
constexpr int BK_KH = 0;           // K single (8KB)
constexpr int BK_VH = 8192;        // V single (8KB)
constexpr int ABUFSZ = 16384;
constexpr int ATTN_SMEM = 2 * ABUFSZ;        // 32768
}

// Scratch (__device__ globals: allocation-free)
__device__ float g_V[kRows * kH];
__device__ __half g_Qh[kRows * kH];                 // Q single fp16 (pre-scaled)
__device__ __half g_KFh[kRows * kH];                // K single, fragment-major
__device__ __half g_VFh[kB * kH * kT];              // V^T single, fragment-major
__device__ __half g_WFh[192 * 1024];                // W single, fragment-major

// ---------------------------------------------------------------------------
// PTX helpers (baseline sm_80+ — survive compute_103 lowering)
// ---------------------------------------------------------------------------
__device__ __forceinline__ void mma16816(float* d, const uint32_t* a,
                                         const uint32_t* b) {
    asm volatile(
        "mma.sync.aligned.m16n8k16.row.col.f32.f16.f16.f32 "
        "{%0,%1,%2,%3}, {%4,%5,%6,%7}, {%8,%9}, {%0,%1,%2,%3};"
        : "+f"(d[0]), "+f"(d[1]), "+f"(d[2]), "+f"(d[3])
        : "r"(a[0]), "r"(a[1]), "r"(a[2]), "r"(a[3]), "r"(b[0]), "r"(b[1]));
}
__device__ __forceinline__ uint32_t f2pack(float lo, float hi) {
    uint32_t r;
    asm("cvt.rn.f16x2.f32 %0, %1, %2;" : "=r"(r) : "f"(hi), "f"(lo));
    return r;
}
__device__ __forceinline__ uint32_t f2pack_lo(float lo, float hi, uint32_t hp) {
    const __half2 h = *reinterpret_cast<const __half2*>(&hp);
    const float rl = lo - __low2float(h);
    const float rh = hi - __high2float(h);
    return f2pack(rl, rh);
}
__device__ __forceinline__ uint32_t smem_addr(const void* p) {
    return (uint32_t)__cvta_generic_to_shared(p);
}
#define CP_ASYNC16(dst, src) \
    asm volatile("cp.async.cg.shared.global [%0], [%1], 16;" \
                 :: "r"(dst), "l"(src))
#define CP_COMMIT() asm volatile("cp.async.commit_group;" ::: "memory")
#define CP_WAIT0()  asm volatile("cp.async.wait_group 0;" ::: "memory")
#define CP_WAIT1()  asm volatile("cp.async.wait_group 1;" ::: "memory")

// Fragment-major u32-word index for attention K (B-operand view)
__device__ __forceinline__ int bfrag_idx(int batch, int tok, int h) {
    const int jt = tok >> 6, nf = (tok >> 3) & 7, r = tok & 7;
    const int ks = h >> 4, sel = (h >> 3) & 1, q2 = (h >> 1) & 3;
    return (((batch * 32 + jt) * 32) + nf * 4 + ks) * 64 + (r * 4 + q2) * 2 + sel;
}

// ---------------------------------------------------------------------------
// Prep: W -> fragment-major single fp16.
// ---------------------------------------------------------------------------
__global__ void wprep_kernel(const float* __restrict__ Wq,
                             const float* __restrict__ Wk,
                             const float* __restrict__ Wv) {
    const int idx = blockIdx.x * 256 + threadIdx.x;   // < 98304
    const int frag = idx >> 6, ww = idx & 63;
    const int r = ww >> 3, q2 = (ww >> 1) & 3, sel = ww & 1;
    const int ks_g = frag / 24, nb = frag % 24;
    const int n = nb * 8 + r;
    const int k = ks_g * 16 + sel * 8 + q2 * 2;
    const int mat = n >> 6, col = n & 63;
    const float* W = (mat == 0) ? Wq : (mat == 1) ? Wk : Wv;
    const float v0 = W[k * 64 + col];
    const float v1 = W[(k + 1) * 64 + col];
    reinterpret_cast<uint32_t*>(g_WFh)[idx] = f2pack(v0, v1);
}

// ---------------------------------------------------------------------------
// QKV GEMM: fp16 HMMA, X single x W single (1 MMA per frag-triple).
// Fragment-major smem, K-chunk 64, double buffer. Epilogue:
//   Q -> row-major single fp16 (pre-scaled 0.125*log2e)
//   K -> fragment-major single fp16
//   V -> fp32 row-major
// ---------------------------------------------------------------------------
__global__ __launch_bounds__(512, 1)
void qkv_mma_kernel(const float* __restrict__ x,
                    const float* __restrict__ bq,
                    const float* __restrict__ bk,
                    const float* __restrict__ bv) {
    extern __shared__ __align__(16) char sm[];
    const int tid  = threadIdx.x;
    const int lane = tid & 31;
    const int w    = tid >> 5;
    const int m0   = (w >> 2) * 32;
    const int n0   = (w & 3) * 48;
    const int mb0  = (w >> 2) * 2;
    const int nb0  = (w & 3) * 6;
    const int r1   = lane >> 2;
    const int kq   = lane & 3;
    const int row0 = blockIdx.x * 128;

    float acc[2][6][4];
#pragma unroll
    for (int mf = 0; mf < 2; ++mf)
#pragma unroll
        for (int nf = 0; nf < 6; ++nf)
#pragma unroll
            for (int i = 0; i < 4; ++i) acc[mf][nf][i] = 0.f;

    float4 xr[4];

    auto ldg_x = [&](int k0) {
#pragma unroll
        for (int it = 0; it < 4; ++it) {
            const int e4 = tid + it * 512;
            const int m = e4 >> 4, k4 = (e4 & 15) * 4;
            xr[it] = *reinterpret_cast<const float4*>(
                &x[(size_t)(row0 + m) * kC + k0 + k4]);
        }
    };
    auto cp_w = [&](int ch, char* buf) {
        const char* wh = (const char*)g_WFh + (size_t)ch * 24576;
#pragma unroll
        for (int it = 0; it < 3; ++it) {
            const int off = (tid + it * 512) * 16;
            CP_ASYNC16(smem_addr(buf + G_BH + off), wh + off);
        }
    };
    auto sts_x = [&](char* buf) {
        uint32_t* A = reinterpret_cast<uint32_t*>(buf + G_AH);
#pragma unroll
        for (int it = 0; it < 4; ++it) {
            const int e4 = tid + it * 512;
            const int m = e4 >> 4, k4 = (e4 & 15) * 4;
            const float4 v = xr[it];
            const int mb = m >> 4;
            const int ks = k4 >> 4;
            const int j  = ((k4 >> 3) & 1) * 2 + ((m >> 3) & 1);
            const int l0 = (m & 7) * 4 + ((k4 >> 1) & 3);
            const int base = (mb * 4 + ks) * 128 + j;
            A[base + l0 * 4]       = f2pack(v.x, v.y);
            A[base + (l0 + 1) * 4] = f2pack(v.z, v.w);
        }
    };

    ldg_x(0);
    cp_w(0, sm);
    CP_COMMIT();
    sts_x(sm);
    CP_WAIT0();
    __syncthreads();

    for (int ch = 0; ch < 16; ++ch) {
        char* buf = sm + (ch & 1) * G_BUF;
        if (ch + 1 < 16) {
            ldg_x((ch + 1) * 64);
            cp_w(ch + 1, sm + ((ch + 1) & 1) * G_BUF);
        }
        CP_COMMIT();

        const char* Ab = buf + G_AH + mb0 * 2048 + lane * 16;
        const char* Bh = buf + G_BH + nb0 * 256 + lane * 8;

#pragma unroll
        for (int ks = 0; ks < 4; ++ks) {
            uint4 ah4[2];
#pragma unroll
            for (int mf = 0; mf < 2; ++mf) {
                const int aoff = (mf * 4 + ks) * 512;
                ah4[mf] = *reinterpret_cast<const uint4*>(Ab + aoff);
            }
#pragma unroll
            for (int nf = 0; nf < 6; ++nf) {
                const int boff = (ks * 24 + nf) * 256;
                uint2 bh = *reinterpret_cast<const uint2*>(Bh + boff);
#pragma unroll
                for (int mf = 0; mf < 2; ++mf) {
                    mma16816(acc[mf][nf], reinterpret_cast<uint32_t*>(&ah4[mf]),
                             reinterpret_cast<uint32_t*>(&bh));
                }
            }
        }

        if (ch + 1 < 16) {
            __syncthreads();
            sts_x(sm + ((ch + 1) & 1) * G_BUF);
            CP_WAIT0();
            __syncthreads();
        }
    }

    // ---- epilogue ----
    uint32_t* KFh = reinterpret_cast<uint32_t*>(g_KFh);
#pragma unroll
    for (int mf = 0; mf < 2; ++mf) {
        const int rg = row0 + m0 + mf * 16 + r1;
#pragma unroll
        for (int nf = 0; nf < 6; ++nf) {
            const int col = n0 + nf * 8 + kq * 2;
            const int mat = col >> 6, h = col & 63;
            const float* bias = (mat == 0) ? bq : (mat == 1) ? bk : bv;
            const float b0 = bias[h], b1 = bias[h + 1];
            const float v00 = acc[mf][nf][0] + b0;
            const float v01 = acc[mf][nf][1] + b1;
            const float v10 = acc[mf][nf][2] + b0;
            const float v11 = acc[mf][nf][3] + b1;
            if (mat == 2) {
                float2 a = {v00, v01}, bvv = {v10, v11};
                *reinterpret_cast<float2*>(g_V + (size_t)rg * kH + h) = a;
                *reinterpret_cast<float2*>(g_V + (size_t)(rg + 8) * kH + h) = bvv;
            } else if (mat == 1) {
                const int batch = rg >> 11, tok = rg & 2047;
                KFh[bfrag_idx(batch, tok, h)]     = f2pack(v00, v01);
                KFh[bfrag_idx(batch, tok + 8, h)] = f2pack(v10, v11);
            } else {
                const float scl = 0.125f * 1.44269504f;
                *reinterpret_cast<uint32_t*>(g_Qh + (size_t)rg * kH + h) =
                    f2pack(v00 * scl, v01 * scl);
                *reinterpret_cast<uint32_t*>(g_Qh + (size_t)(rg + 8) * kH + h) =
                    f2pack(v10 * scl, v11 * scl);
            }
        }
    }
}

// ---------------------------------------------------------------------------
// V transpose -> FRAGMENT-MAJOR single fp16 g_VFh
// ---------------------------------------------------------------------------
__global__ __launch_bounds__(256)
void vtrans_kernel() {
    __shared__ float tile[64][65];
    const int blk = blockIdx.x;            // kB * 32
    const int b = blk >> 5, jt = blk & 31;
    const int t0 = jt * 64;
    const int tid = threadIdx.x;
    const float* src = g_V + ((size_t)b * kT + t0) * kH;
    uint32_t* VFh = reinterpret_cast<uint32_t*>(g_VFh);
#pragma unroll
    for (int i = 0; i < 16; ++i) {
        const int idx = tid + i * 256;
        tile[idx >> 6][idx & 63] = src[idx];
    }
    __syncthreads();
#pragma unroll
    for (int i = 0; i < 8; ++i) {
        const int idx = tid + i * 256;     // 2048 pairs
        const int h = idx >> 5, tp = (idx & 31) * 2;
        const float v0 = tile[tp][h], v1 = tile[tp + 1][h];
        const int ks = tp >> 4, sel = (tp >> 3) & 1;
        const int lane2 = (h & 7) * 4 + ((tp >> 1) & 3);
        const int widx = (((b * 32 + jt) * 32) + (h >> 3) * 4 + ks) * 64
                         + lane2 * 2 + sel;
        VFh[widx] = f2pack(v0, v1);
    }
}

// ---------------------------------------------------------------------------
// Causal flash attention (R11-validated, 55us): BM=64, 4 warps, occ 3,
// fragment-major smem, QK single x single, PV = P hi/lo x V single,
// exp2 softmax, Q in registers, cp.async double buffer.
// ---------------------------------------------------------------------------
__global__ __launch_bounds__(128, 3)
void attn_mma_kernel(float* __restrict__ out) {
    extern __shared__ __align__(16) char sma[];

    const int tid  = threadIdx.x;
    const int lane = tid & 31;
    const int w    = tid >> 5;
    const int b    = blockIdx.x & 15;
    const int qt   = (kQT - 1) - (blockIdx.x >> 4);
    const int q0   = qt * 64;
    const int m0w  = w * 16;
    const int r1   = lane >> 2;
    const int kq   = lane & 3;

    uint32_t qhi[4][4];
    {
        const uint32_t* qh =
            reinterpret_cast<const uint32_t*>(g_Qh + ((size_t)b * kT + q0) * kH);
        const int rA = (m0w + r1) * 32, rB = rA + 8 * 32;
#pragma unroll
        for (int ks = 0; ks < 4; ++ks) {
            const int c0 = ks * 8 + kq;
            qhi[ks][0] = qh[rA + c0];
            qhi[ks][1] = qh[rB + c0];
            qhi[ks][2] = qh[rA + c0 + 4];
            qhi[ks][3] = qh[rB + c0 + 4];
        }
    }

    auto stage = [&](int jt, char* buf) {
        const size_t base = ((size_t)b * 32 + jt) * 8192;
        const char* kh = (const char*)g_KFh + base;
        const char* vh = (const char*)g_VFh + base;
#pragma unroll
        for (int i = 0; i < 4; ++i) {
            const int off = (tid + i * 128) * 16;
            CP_ASYNC16(smem_addr(buf + BK_KH + off), kh + off);
            CP_ASYNC16(smem_addr(buf + BK_VH + off), vh + off);
        }
    };

    float o[8][4];
#pragma unroll
    for (int nf = 0; nf < 8; ++nf)
#pragma unroll
        for (int c = 0; c < 4; ++c) o[nf][c] = 0.f;
    float mrow[2] = {-1e30f, -1e30f};
    float lrow[2] = {0.f, 0.f};

    stage(0, sma);
    CP_COMMIT();

    for (int jt = 0; jt <= qt; ++jt) {
        if (jt + 1 <= qt) stage(jt + 1, sma + ((jt + 1) & 1) * ABUFSZ);
        CP_COMMIT();
        CP_WAIT1();
        __syncthreads();

        char* buf = sma + (jt & 1) * ABUFSZ;
        const char* Kh = buf + BK_KH + lane * 8;
        const char* Vh = buf + BK_VH + lane * 8;

        // ---- S = Q K^T (single x single) ----
        float s[8][4];
#pragma unroll
        for (int nf = 0; nf < 8; ++nf)
#pragma unroll
            for (int c = 0; c < 4; ++c) s[nf][c] = 0.f;

#pragma unroll
        for (int ks = 0; ks < 4; ++ks) {
#pragma unroll
            for (int nf = 0; nf < 8; ++nf) {
                const int boff = (nf * 4 + ks) * 256;
                uint2 bh = *reinterpret_cast<const uint2*>(Kh + boff);
                mma16816(s[nf], qhi[ks], reinterpret_cast<uint32_t*>(&bh));
            }
        }

        // ---- causal mask (diagonal tile only) + online softmax (exp2) ----
        float mx1 = -1e30f, mx2 = -1e30f;
        if (jt == qt) {
            const int qg1 = q0 + m0w + r1;
            const int qg2 = qg1 + 8;
#pragma unroll
            for (int nf = 0; nf < 8; ++nf) {
                const int kg0 = jt * 64 + nf * 8 + kq * 2;
                s[nf][0] = (kg0     <= qg1) ? s[nf][0] : -1e30f;
                s[nf][1] = (kg0 + 1 <= qg1) ? s[nf][1] : -1e30f;
                s[nf][2] = (kg0     <= qg2) ? s[nf][2] : -1e30f;
                s[nf][3] = (kg0 + 1 <= qg2) ? s[nf][3] : -1e30f;
            }
        }
#pragma unroll
        for (int nf = 0; nf < 8; ++nf) {
            mx1 = fmaxf(mx1, fmaxf(s[nf][0], s[nf][1]));
            mx2 = fmaxf(mx2, fmaxf(s[nf][2], s[nf][3]));
        }
        mx1 = fmaxf(mx1, __shfl_xor_sync(0xffffffffu, mx1, 1));
        mx1 = fmaxf(mx1, __shfl_xor_sync(0xffffffffu, mx1, 2));
        mx2 = fmaxf(mx2, __shfl_xor_sync(0xffffffffu, mx2, 1));
        mx2 = fmaxf(mx2, __shfl_xor_sync(0xffffffffu, mx2, 2));

        const float mn1 = fmaxf(mrow[0], mx1);
        const float mn2 = fmaxf(mrow[1], mx2);
        const float a1 = exp2f(mrow[0] - mn1);
        const float a2 = exp2f(mrow[1] - mn2);
        mrow[0] = mn1; mrow[1] = mn2;

        float rs1 = 0.f, rs2 = 0.f;
#pragma unroll
        for (int nf = 0; nf < 8; ++nf) {
            s[nf][0] = exp2f(s[nf][0] - mn1);
            s[nf][1] = exp2f(s[nf][1] - mn1);
            s[nf][2] = exp2f(s[nf][2] - mn2);
            s[nf][3] = exp2f(s[nf][3] - mn2);
            rs1 += s[nf][0] + s[nf][1];
            rs2 += s[nf][2] + s[nf][3];
        }
        rs1 += __shfl_xor_sync(0xffffffffu, rs1, 1);
        rs1 += __shfl_xor_sync(0xffffffffu, rs1, 2);
        rs2 += __shfl_xor_sync(0xffffffffu, rs2, 1);
        rs2 += __shfl_xor_sync(0xffffffffu, rs2, 2);
        lrow[0] = lrow[0] * a1 + rs1;
        lrow[1] = lrow[1] * a2 + rs2;
#pragma unroll
        for (int nf = 0; nf < 8; ++nf) {
            o[nf][0] *= a1; o[nf][1] *= a1;
            o[nf][2] *= a2; o[nf][3] *= a2;
        }

        // ---- O += P V (P hi/lo x V single) ----
#pragma unroll
        for (int ks = 0; ks < 4; ++ks) {
            uint32_t pah[4], pal[4];
            const float* s0 = s[2 * ks];
            const float* s1 = s[2 * ks + 1];
            pah[0] = f2pack(s0[0], s0[1]);
            pah[1] = f2pack(s0[2], s0[3]);
            pah[2] = f2pack(s1[0], s1[1]);
            pah[3] = f2pack(s1[2], s1[3]);
            pal[0] = f2pack_lo(s0[0], s0[1], pah[0]);
            pal[1] = f2pack_lo(s0[2], s0[3], pah[1]);
            pal[2] = f2pack_lo(s1[0], s1[1], pah[2]);
            pal[3] = f2pack_lo(s1[2], s1[3], pah[3]);
#pragma unroll
            for (int nf = 0; nf < 8; ++nf) {
                const int boff = (nf * 4 + ks) * 256;
                uint2 vh = *reinterpret_cast<const uint2*>(Vh + boff);
                mma16816(o[nf], pah, reinterpret_cast<uint32_t*>(&vh));
                mma16816(o[nf], pal, reinterpret_cast<uint32_t*>(&vh));
            }
        }
        __syncthreads();
    }

    const float inv1 = 1.0f / lrow[0];
    const float inv2 = 1.0f / lrow[1];
    float* og = out + ((size_t)b * kT + q0 + m0w) * kH;
#pragma unroll
    for (int nf = 0; nf < 8; ++nf) {
        const int col = nf * 8 + kq * 2;
        float2 v0, v1;
        v0.x = o[nf][0] * inv1; v0.y = o[nf][1] * inv1;
        v1.x = o[nf][2] * inv2; v1.y = o[nf][3] * inv2;
        *reinterpret_cast<float2*>(&og[r1 * kH + col]) = v0;
        *reinterpret_cast<float2*>(&og[(r1 + 8) * kH + col]) = v1;
    }
}

// ---------------------------------------------------------------------------
extern "C" void kernel_launch(void* const* d_in, const int* in_sizes, int n_in,
                              void* d_out, int out_size) {
    (void)in_sizes; (void)n_in; (void)out_size;
    const float* x  = (const float*)d_in[0];
    const float* Wq = (const float*)d_in[1];
    const float* bq = (const float*)d_in[2];
    const float* Wk = (const float*)d_in[3];
    const float* bk = (const float*)d_in[4];
    const float* Wv = (const float*)d_in[5];
    const float* bv = (const float*)d_in[6];
    float* out = (float*)d_out;

    wprep_kernel<<<384, 256>>>(Wq, Wk, Wv);

    cudaFuncSetAttribute(qkv_mma_kernel, cudaFuncAttributeMaxDynamicSharedMemorySize,
                         QKV_SMEM);
    qkv_mma_kernel<<<kRows / 128, 512, QKV_SMEM>>>(x, bq, bk, bv);

    vtrans_kernel<<<kB * 32, 256>>>();

    cudaFuncSetAttribute(attn_mma_kernel, cudaFuncAttributeMaxDynamicSharedMemorySize,
                         ATTN_SMEM);
    attn_mma_kernel<<<kB * kQT, 128, ATTN_SMEM>>>(out);
}

// round 13
// speedup vs baseline: 2.3371x; 1.0650x over previous
#include <cuda_runtime.h>
#include <cuda_fp16.h>
#include <cstdint>

// ---------------------------------------------------------------------------
// Problem constants
// ---------------------------------------------------------------------------
namespace {
constexpr int kB = 16;
constexpr int kT = 2048;
constexpr int kC = 1024;
constexpr int kH = 64;
constexpr int kRows = kB * kT;     // 32768
constexpr int kQT = kT / 64;       // 32 q-tiles per batch

// QKV GEMM smem (bytes): fragment-major, K-chunk 64, double buffer
constexpr int G_AH = 0;            // 32 A-frags x 512B (X single)
constexpr int G_BH = 16384;        // 96 B-frags x 256B (W single)
constexpr int G_BUF = 40960;
constexpr int QKV_SMEM = 2 * G_BUF;          // 81920

// Attention smem (bytes): fragment-major contiguous tiles, all single fp16
constexpr int BK_KH = 0;           // K single (8KB)
constexpr int BK_VH = 8192;        // V single (8KB)
constexpr int ABUFSZ = 16384;
constexpr int ATTN_SMEM = 2 * ABUFSZ;        // 32768
}

// Scratch (__device__ globals: allocation-free)
__device__ float g_V[kRows * kH];
__device__ __half g_Qh[kRows * kH];                 // Q single fp16 (pre-scaled)
__device__ __half g_KFh[kRows * kH];                // K single, fragment-major
__device__ __half g_VFh[kB * kH * kT];              // V^T single, fragment-major
__device__ __half g_WFh[192 * 1024];                // W single, fragment-major

// ---------------------------------------------------------------------------
// PTX helpers (baseline sm_80+ — survive compute_103 lowering)
// ---------------------------------------------------------------------------
__device__ __forceinline__ void mma16816(float* d, const uint32_t* a,
                                         const uint32_t* b) {
    asm volatile(
        "mma.sync.aligned.m16n8k16.row.col.f32.f16.f16.f32 "
        "{%0,%1,%2,%3}, {%4,%5,%6,%7}, {%8,%9}, {%0,%1,%2,%3};"
        : "+f"(d[0]), "+f"(d[1]), "+f"(d[2]), "+f"(d[3])
        : "r"(a[0]), "r"(a[1]), "r"(a[2]), "r"(a[3]), "r"(b[0]), "r"(b[1]));
}
__device__ __forceinline__ uint32_t f2pack(float lo, float hi) {
    uint32_t r;
    asm("cvt.rn.f16x2.f32 %0, %1, %2;" : "=r"(r) : "f"(hi), "f"(lo));
    return r;
}
__device__ __forceinline__ uint32_t smem_addr(const void* p) {
    return (uint32_t)__cvta_generic_to_shared(p);
}
#define CP_ASYNC16(dst, src) \
    asm volatile("cp.async.cg.shared.global [%0], [%1], 16;" \
                 :: "r"(dst), "l"(src))
#define CP_COMMIT() asm volatile("cp.async.commit_group;" ::: "memory")
#define CP_WAIT0()  asm volatile("cp.async.wait_group 0;" ::: "memory")
#define CP_WAIT1()  asm volatile("cp.async.wait_group 1;" ::: "memory")

// Fragment-major u32-word index for attention K (B-operand view)
__device__ __forceinline__ int bfrag_idx(int batch, int tok, int h) {
    const int jt = tok >> 6, nf = (tok >> 3) & 7, r = tok & 7;
    const int ks = h >> 4, sel = (h >> 3) & 1, q2 = (h >> 1) & 3;
    return (((batch * 32 + jt) * 32) + nf * 4 + ks) * 64 + (r * 4 + q2) * 2 + sel;
}

// ---------------------------------------------------------------------------
// Prep: W -> fragment-major single fp16.
// ---------------------------------------------------------------------------
__global__ void wprep_kernel(const float* __restrict__ Wq,
                             const float* __restrict__ Wk,
                             const float* __restrict__ Wv) {
    const int idx = blockIdx.x * 256 + threadIdx.x;   // < 98304
    const int frag = idx >> 6, ww = idx & 63;
    const int r = ww >> 3, q2 = (ww >> 1) & 3, sel = ww & 1;
    const int ks_g = frag / 24, nb = frag % 24;
    const int n = nb * 8 + r;
    const int k = ks_g * 16 + sel * 8 + q2 * 2;
    const int mat = n >> 6, col = n & 63;
    const float* W = (mat == 0) ? Wq : (mat == 1) ? Wk : Wv;
    const float v0 = W[k * 64 + col];
    const float v1 = W[(k + 1) * 64 + col];
    reinterpret_cast<uint32_t*>(g_WFh)[idx] = f2pack(v0, v1);
}

// ---------------------------------------------------------------------------
// QKV GEMM (R12-validated, ~37us): fp16 HMMA, X single x W single.
// Epilogue: Q single fp16 (pre-scaled 0.125*log2e), K fragment-major single,
// V fp32 row-major.
// ---------------------------------------------------------------------------
__global__ __launch_bounds__(512, 1)
void qkv_mma_kernel(const float* __restrict__ x,
                    const float* __restrict__ bq,
                    const float* __restrict__ bk,
                    const float* __restrict__ bv) {
    extern __shared__ __align__(16) char sm[];
    const int tid  = threadIdx.x;
    const int lane = tid & 31;
    const int w    = tid >> 5;
    const int m0   = (w >> 2) * 32;
    const int n0   = (w & 3) * 48;
    const int mb0  = (w >> 2) * 2;
    const int nb0  = (w & 3) * 6;
    const int r1   = lane >> 2;
    const int kq   = lane & 3;
    const int row0 = blockIdx.x * 128;

    float acc[2][6][4];
#pragma unroll
    for (int mf = 0; mf < 2; ++mf)
#pragma unroll
        for (int nf = 0; nf < 6; ++nf)
#pragma unroll
            for (int i = 0; i < 4; ++i) acc[mf][nf][i] = 0.f;

    float4 xr[4];

    auto ldg_x = [&](int k0) {
#pragma unroll
        for (int it = 0; it < 4; ++it) {
            const int e4 = tid + it * 512;
            const int m = e4 >> 4, k4 = (e4 & 15) * 4;
            xr[it] = *reinterpret_cast<const float4*>(
                &x[(size_t)(row0 + m) * kC + k0 + k4]);
        }
    };
    auto cp_w = [&](int ch, char* buf) {
        const char* wh = (const char*)g_WFh + (size_t)ch * 24576;
#pragma unroll
        for (int it = 0; it < 3; ++it) {
            const int off = (tid + it * 512) * 16;
            CP_ASYNC16(smem_addr(buf + G_BH + off), wh + off);
        }
    };
    auto sts_x = [&](char* buf) {
        uint32_t* A = reinterpret_cast<uint32_t*>(buf + G_AH);
#pragma unroll
        for (int it = 0; it < 4; ++it) {
            const int e4 = tid + it * 512;
            const int m = e4 >> 4, k4 = (e4 & 15) * 4;
            const float4 v = xr[it];
            const int mb = m >> 4;
            const int ks = k4 >> 4;
            const int j  = ((k4 >> 3) & 1) * 2 + ((m >> 3) & 1);
            const int l0 = (m & 7) * 4 + ((k4 >> 1) & 3);
            const int base = (mb * 4 + ks) * 128 + j;
            A[base + l0 * 4]       = f2pack(v.x, v.y);
            A[base + (l0 + 1) * 4] = f2pack(v.z, v.w);
        }
    };

    ldg_x(0);
    cp_w(0, sm);
    CP_COMMIT();
    sts_x(sm);
    CP_WAIT0();
    __syncthreads();

    for (int ch = 0; ch < 16; ++ch) {
        char* buf = sm + (ch & 1) * G_BUF;
        if (ch + 1 < 16) {
            ldg_x((ch + 1) * 64);
            cp_w(ch + 1, sm + ((ch + 1) & 1) * G_BUF);
        }
        CP_COMMIT();

        const char* Ab = buf + G_AH + mb0 * 2048 + lane * 16;
        const char* Bh = buf + G_BH + nb0 * 256 + lane * 8;

#pragma unroll
        for (int ks = 0; ks < 4; ++ks) {
            uint4 ah4[2];
#pragma unroll
            for (int mf = 0; mf < 2; ++mf) {
                const int aoff = (mf * 4 + ks) * 512;
                ah4[mf] = *reinterpret_cast<const uint4*>(Ab + aoff);
            }
#pragma unroll
            for (int nf = 0; nf < 6; ++nf) {
                const int boff = (ks * 24 + nf) * 256;
                uint2 bh = *reinterpret_cast<const uint2*>(Bh + boff);
#pragma unroll
                for (int mf = 0; mf < 2; ++mf) {
                    mma16816(acc[mf][nf], reinterpret_cast<uint32_t*>(&ah4[mf]),
                             reinterpret_cast<uint32_t*>(&bh));
                }
            }
        }

        if (ch + 1 < 16) {
            __syncthreads();
            sts_x(sm + ((ch + 1) & 1) * G_BUF);
            CP_WAIT0();
            __syncthreads();
        }
    }

    // ---- epilogue ----
    uint32_t* KFh = reinterpret_cast<uint32_t*>(g_KFh);
#pragma unroll
    for (int mf = 0; mf < 2; ++mf) {
        const int rg = row0 + m0 + mf * 16 + r1;
#pragma unroll
        for (int nf = 0; nf < 6; ++nf) {
            const int col = n0 + nf * 8 + kq * 2;
            const int mat = col >> 6, h = col & 63;
            const float* bias = (mat == 0) ? bq : (mat == 1) ? bk : bv;
            const float b0 = bias[h], b1 = bias[h + 1];
            const float v00 = acc[mf][nf][0] + b0;
            const float v01 = acc[mf][nf][1] + b1;
            const float v10 = acc[mf][nf][2] + b0;
            const float v11 = acc[mf][nf][3] + b1;
            if (mat == 2) {
                float2 a = {v00, v01}, bvv = {v10, v11};
                *reinterpret_cast<float2*>(g_V + (size_t)rg * kH + h) = a;
                *reinterpret_cast<float2*>(g_V + (size_t)(rg + 8) * kH + h) = bvv;
            } else if (mat == 1) {
                const int batch = rg >> 11, tok = rg & 2047;
                KFh[bfrag_idx(batch, tok, h)]     = f2pack(v00, v01);
                KFh[bfrag_idx(batch, tok + 8, h)] = f2pack(v10, v11);
            } else {
                const float scl = 0.125f * 1.44269504f;
                *reinterpret_cast<uint32_t*>(g_Qh + (size_t)rg * kH + h) =
                    f2pack(v00 * scl, v01 * scl);
                *reinterpret_cast<uint32_t*>(g_Qh + (size_t)(rg + 8) * kH + h) =
                    f2pack(v10 * scl, v11 * scl);
            }
        }
    }
}

// ---------------------------------------------------------------------------
// V transpose -> FRAGMENT-MAJOR single fp16 g_VFh
// ---------------------------------------------------------------------------
__global__ __launch_bounds__(256)
void vtrans_kernel() {
    __shared__ float tile[64][65];
    const int blk = blockIdx.x;            // kB * 32
    const int b = blk >> 5, jt = blk & 31;
    const int t0 = jt * 64;
    const int tid = threadIdx.x;
    const float* src = g_V + ((size_t)b * kT + t0) * kH;
    uint32_t* VFh = reinterpret_cast<uint32_t*>(g_VFh);
#pragma unroll
    for (int i = 0; i < 16; ++i) {
        const int idx = tid + i * 256;
        tile[idx >> 6][idx & 63] = src[idx];
    }
    __syncthreads();
#pragma unroll
    for (int i = 0; i < 8; ++i) {
        const int idx = tid + i * 256;     // 2048 pairs
        const int h = idx >> 5, tp = (idx & 31) * 2;
        const float v0 = tile[tp][h], v1 = tile[tp + 1][h];
        const int ks = tp >> 4, sel = (tp >> 3) & 1;
        const int lane2 = (h & 7) * 4 + ((tp >> 1) & 3);
        const int widx = (((b * 32 + jt) * 32) + (h >> 3) * 4 + ks) * 64
                         + lane2 * 2 + sel;
        VFh[widx] = f2pack(v0, v1);
    }
}

// ---------------------------------------------------------------------------
// Causal flash attention: BM=64, 4 warps, occ 4 target, fragment-major smem.
// QK = 1 MMA (single x single); PV = 1 MMA (P single x V single).
// exp2-domain softmax; Q in registers; cp.async double buffer.
// ---------------------------------------------------------------------------
__global__ __launch_bounds__(128, 4)
void attn_mma_kernel(float* __restrict__ out) {
    extern __shared__ __align__(16) char sma[];

    const int tid  = threadIdx.x;
    const int lane = tid & 31;
    const int w    = tid >> 5;
    const int b    = blockIdx.x & 15;
    const int qt   = (kQT - 1) - (blockIdx.x >> 4);
    const int q0   = qt * 64;
    const int m0w  = w * 16;
    const int r1   = lane >> 2;
    const int kq   = lane & 3;

    uint32_t qhi[4][4];
    {
        const uint32_t* qh =
            reinterpret_cast<const uint32_t*>(g_Qh + ((size_t)b * kT + q0) * kH);
        const int rA = (m0w + r1) * 32, rB = rA + 8 * 32;
#pragma unroll
        for (int ks = 0; ks < 4; ++ks) {
            const int c0 = ks * 8 + kq;
            qhi[ks][0] = qh[rA + c0];
            qhi[ks][1] = qh[rB + c0];
            qhi[ks][2] = qh[rA + c0 + 4];
            qhi[ks][3] = qh[rB + c0 + 4];
        }
    }

    auto stage = [&](int jt, char* buf) {
        const size_t base = ((size_t)b * 32 + jt) * 8192;
        const char* kh = (const char*)g_KFh + base;
        const char* vh = (const char*)g_VFh + base;
#pragma unroll
        for (int i = 0; i < 4; ++i) {
            const int off = (tid + i * 128) * 16;
            CP_ASYNC16(smem_addr(buf + BK_KH + off), kh + off);
            CP_ASYNC16(smem_addr(buf + BK_VH + off), vh + off);
        }
    };

    float o[8][4];
#pragma unroll
    for (int nf = 0; nf < 8; ++nf)
#pragma unroll
        for (int c = 0; c < 4; ++c) o[nf][c] = 0.f;
    float mrow[2] = {-1e30f, -1e30f};
    float lrow[2] = {0.f, 0.f};

    stage(0, sma);
    CP_COMMIT();

    for (int jt = 0; jt <= qt; ++jt) {
        if (jt + 1 <= qt) stage(jt + 1, sma + ((jt + 1) & 1) * ABUFSZ);
        CP_COMMIT();
        CP_WAIT1();
        __syncthreads();

        char* buf = sma + (jt & 1) * ABUFSZ;
        const char* Kh = buf + BK_KH + lane * 8;
        const char* Vh = buf + BK_VH + lane * 8;

        // ---- S = Q K^T (single x single) ----
        float s[8][4];
#pragma unroll
        for (int nf = 0; nf < 8; ++nf)
#pragma unroll
            for (int c = 0; c < 4; ++c) s[nf][c] = 0.f;

#pragma unroll
        for (int ks = 0; ks < 4; ++ks) {
#pragma unroll
            for (int nf = 0; nf < 8; ++nf) {
                const int boff = (nf * 4 + ks) * 256;
                uint2 bh = *reinterpret_cast<const uint2*>(Kh + boff);
                mma16816(s[nf], qhi[ks], reinterpret_cast<uint32_t*>(&bh));
            }
        }

        // ---- causal mask (diagonal tile only) + online softmax (exp2) ----
        float mx1 = -1e30f, mx2 = -1e30f;
        if (jt == qt) {
            const int qg1 = q0 + m0w + r1;
            const int qg2 = qg1 + 8;
#pragma unroll
            for (int nf = 0; nf < 8; ++nf) {
                const int kg0 = jt * 64 + nf * 8 + kq * 2;
                s[nf][0] = (kg0     <= qg1) ? s[nf][0] : -1e30f;
                s[nf][1] = (kg0 + 1 <= qg1) ? s[nf][1] : -1e30f;
                s[nf][2] = (kg0     <= qg2) ? s[nf][2] : -1e30f;
                s[nf][3] = (kg0 + 1 <= qg2) ? s[nf][3] : -1e30f;
            }
        }
#pragma unroll
        for (int nf = 0; nf < 8; ++nf) {
            mx1 = fmaxf(mx1, fmaxf(s[nf][0], s[nf][1]));
            mx2 = fmaxf(mx2, fmaxf(s[nf][2], s[nf][3]));
        }
        mx1 = fmaxf(mx1, __shfl_xor_sync(0xffffffffu, mx1, 1));
        mx1 = fmaxf(mx1, __shfl_xor_sync(0xffffffffu, mx1, 2));
        mx2 = fmaxf(mx2, __shfl_xor_sync(0xffffffffu, mx2, 1));
        mx2 = fmaxf(mx2, __shfl_xor_sync(0xffffffffu, mx2, 2));

        const float mn1 = fmaxf(mrow[0], mx1);
        const float mn2 = fmaxf(mrow[1], mx2);
        const float a1 = exp2f(mrow[0] - mn1);
        const float a2 = exp2f(mrow[1] - mn2);
        mrow[0] = mn1; mrow[1] = mn2;

        float rs1 = 0.f, rs2 = 0.f;
#pragma unroll
        for (int nf = 0; nf < 8; ++nf) {
            s[nf][0] = exp2f(s[nf][0] - mn1);
            s[nf][1] = exp2f(s[nf][1] - mn1);
            s[nf][2] = exp2f(s[nf][2] - mn2);
            s[nf][3] = exp2f(s[nf][3] - mn2);
            rs1 += s[nf][0] + s[nf][1];
            rs2 += s[nf][2] + s[nf][3];
        }
        rs1 += __shfl_xor_sync(0xffffffffu, rs1, 1);
        rs1 += __shfl_xor_sync(0xffffffffu, rs1, 2);
        rs2 += __shfl_xor_sync(0xffffffffu, rs2, 1);
        rs2 += __shfl_xor_sync(0xffffffffu, rs2, 2);
        lrow[0] = lrow[0] * a1 + rs1;
        lrow[1] = lrow[1] * a2 + rs2;
#pragma unroll
        for (int nf = 0; nf < 8; ++nf) {
            o[nf][0] *= a1; o[nf][1] *= a1;
            o[nf][2] *= a2; o[nf][3] *= a2;
        }

        // ---- O += P V (P single x V single) ----
#pragma unroll
        for (int ks = 0; ks < 4; ++ks) {
            uint32_t pah[4];
            const float* s0 = s[2 * ks];
            const float* s1 = s[2 * ks + 1];
            pah[0] = f2pack(s0[0], s0[1]);
            pah[1] = f2pack(s0[2], s0[3]);
            pah[2] = f2pack(s1[0], s1[1]);
            pah[3] = f2pack(s1[2], s1[3]);
#pragma unroll
            for (int nf = 0; nf < 8; ++nf) {
                const int boff = (nf * 4 + ks) * 256;
                uint2 vh = *reinterpret_cast<const uint2*>(Vh + boff);
                mma16816(o[nf], pah, reinterpret_cast<uint32_t*>(&vh));
            }
        }
        __syncthreads();
    }

    const float inv1 = 1.0f / lrow[0];
    const float inv2 = 1.0f / lrow[1];
    float* og = out + ((size_t)b * kT + q0 + m0w) * kH;
#pragma unroll
    for (int nf = 0; nf < 8; ++nf) {
        const int col = nf * 8 + kq * 2;
        float2 v0, v1;
        v0.x = o[nf][0] * inv1; v0.y = o[nf][1] * inv1;
        v1.x = o[nf][2] * inv2; v1.y = o[nf][3] * inv2;
        *reinterpret_cast<float2*>(&og[r1 * kH + col]) = v0;
        *reinterpret_cast<float2*>(&og[(r1 + 8) * kH + col]) = v1;
    }
}

// ---------------------------------------------------------------------------
extern "C" void kernel_launch(void* const* d_in, const int* in_sizes, int n_in,
                              void* d_out, int out_size) {
    (void)in_sizes; (void)n_in; (void)out_size;
    const float* x  = (const float*)d_in[0];
    const float* Wq = (const float*)d_in[1];
    const float* bq = (const float*)d_in[2];
    const float* Wk = (const float*)d_in[3];
    const float* bk = (const float*)d_in[4];
    const float* Wv = (const float*)d_in[5];
    const float* bv = (const float*)d_in[6];
    float* out = (float*)d_out;

    wprep_kernel<<<384, 256>>>(Wq, Wk, Wv);

    cudaFuncSetAttribute(qkv_mma_kernel, cudaFuncAttributeMaxDynamicSharedMemorySize,
                         QKV_SMEM);
    qkv_mma_kernel<<<kRows / 128, 512, QKV_SMEM>>>(x, bq, bk, bv);

    vtrans_kernel<<<kB * 32, 256>>>();

    cudaFuncSetAttribute(attn_mma_kernel, cudaFuncAttributeMaxDynamicSharedMemorySize,
                         ATTN_SMEM);
    attn_mma_kernel<<<kB * kQT, 128, ATTN_SMEM>>>(out);
}

// round 14
// speedup vs baseline: 2.5137x; 1.0756x over previous
#include <cuda_runtime.h>
#include <cuda_fp16.h>
#include <cstdint>

// ---------------------------------------------------------------------------
// Problem constants
// ---------------------------------------------------------------------------
namespace {
constexpr int kB = 16;
constexpr int kT = 2048;
constexpr int kC = 1024;
constexpr int kH = 64;
constexpr int kRows = kB * kT;     // 32768
constexpr int kQT = kT / 64;       // 32 q-tiles per batch

// QKV GEMM smem (bytes): fragment-major, K-chunk 64, double buffer
constexpr int G_AH = 0;            // 32 A-frags x 512B (X single)
constexpr int G_BH = 16384;        // 96 B-frags x 256B (W single)
constexpr int G_BUF = 40960;
constexpr int QKV_SMEM = 2 * G_BUF;          // 81920

// Attention smem (bytes): BN=128 (two 64-token fragment blobs per buffer)
constexpr int BK_KH = 0;           // K: 16KB
constexpr int BK_VH = 16384;       // V: 16KB
constexpr int ABUFSZ = 32768;
constexpr int ATTN_SMEM = 2 * ABUFSZ;        // 65536 -> occ 3 (grid-limited)
}

// Scratch (__device__ globals: allocation-free)
__device__ __half g_Qh[kRows * kH];                 // Q single fp16 (pre-scaled)
__device__ __half g_KFh[kRows * kH];                // K single, fragment-major
__device__ __half g_VFh[kB * kH * kT];              // V^T single, fragment-major
__device__ __half g_WFh[192 * 1024];                // W single, fragment-major

// ---------------------------------------------------------------------------
// PTX helpers (baseline sm_80+ — survive compute_103 lowering)
// ---------------------------------------------------------------------------
__device__ __forceinline__ void mma16816(float* d, const uint32_t* a,
                                         const uint32_t* b) {
    asm volatile(
        "mma.sync.aligned.m16n8k16.row.col.f32.f16.f16.f32 "
        "{%0,%1,%2,%3}, {%4,%5,%6,%7}, {%8,%9}, {%0,%1,%2,%3};"
        : "+f"(d[0]), "+f"(d[1]), "+f"(d[2]), "+f"(d[3])
        : "r"(a[0]), "r"(a[1]), "r"(a[2]), "r"(a[3]), "r"(b[0]), "r"(b[1]));
}
__device__ __forceinline__ uint32_t f2pack(float lo, float hi) {
    uint32_t r;
    asm("cvt.rn.f16x2.f32 %0, %1, %2;" : "=r"(r) : "f"(hi), "f"(lo));
    return r;
}
__device__ __forceinline__ uint32_t smem_addr(const void* p) {
    return (uint32_t)__cvta_generic_to_shared(p);
}
#define CP_ASYNC16(dst, src) \
    asm volatile("cp.async.cg.shared.global [%0], [%1], 16;" \
                 :: "r"(dst), "l"(src))
#define CP_COMMIT() asm volatile("cp.async.commit_group;" ::: "memory")
#define CP_WAIT0()  asm volatile("cp.async.wait_group 0;" ::: "memory")
#define CP_WAIT1()  asm volatile("cp.async.wait_group 1;" ::: "memory")

// Fragment-major u32-word index for attention K (B-operand view)
__device__ __forceinline__ int bfrag_idx(int batch, int tok, int h) {
    const int jt = tok >> 6, nf = (tok >> 3) & 7, r = tok & 7;
    const int ks = h >> 4, sel = (h >> 3) & 1, q2 = (h >> 1) & 3;
    return (((batch * 32 + jt) * 32) + nf * 4 + ks) * 64 + (r * 4 + q2) * 2 + sel;
}

// ---------------------------------------------------------------------------
// Prep: W -> fragment-major single fp16.
// ---------------------------------------------------------------------------
__global__ void wprep_kernel(const float* __restrict__ Wq,
                             const float* __restrict__ Wk,
                             const float* __restrict__ Wv) {
    const int idx = blockIdx.x * 256 + threadIdx.x;   // < 98304
    const int frag = idx >> 6, ww = idx & 63;
    const int r = ww >> 3, q2 = (ww >> 1) & 3, sel = ww & 1;
    const int ks_g = frag / 24, nb = frag % 24;
    const int n = nb * 8 + r;
    const int k = ks_g * 16 + sel * 8 + q2 * 2;
    const int mat = n >> 6, col = n & 63;
    const float* W = (mat == 0) ? Wq : (mat == 1) ? Wk : Wv;
    const float v0 = W[k * 64 + col];
    const float v1 = W[(k + 1) * 64 + col];
    reinterpret_cast<uint32_t*>(g_WFh)[idx] = f2pack(v0, v1);
}

// ---------------------------------------------------------------------------
// QKV GEMM (R12-validated mainloop, ~37us): fp16 HMMA, X single x W single.
// Epilogue: Q single fp16 (pre-scaled 0.125*log2e), K fragment-major single,
// V^T fragment-major single fp16 (DIRECT scatter — vtrans fused away).
// ---------------------------------------------------------------------------
__global__ __launch_bounds__(512, 1)
void qkv_mma_kernel(const float* __restrict__ x,
                    const float* __restrict__ bq,
                    const float* __restrict__ bk,
                    const float* __restrict__ bv) {
    extern __shared__ __align__(16) char sm[];
    const int tid  = threadIdx.x;
    const int lane = tid & 31;
    const int w    = tid >> 5;
    const int m0   = (w >> 2) * 32;
    const int n0   = (w & 3) * 48;
    const int mb0  = (w >> 2) * 2;
    const int nb0  = (w & 3) * 6;
    const int r1   = lane >> 2;
    const int kq   = lane & 3;
    const int row0 = blockIdx.x * 128;

    float acc[2][6][4];
#pragma unroll
    for (int mf = 0; mf < 2; ++mf)
#pragma unroll
        for (int nf = 0; nf < 6; ++nf)
#pragma unroll
            for (int i = 0; i < 4; ++i) acc[mf][nf][i] = 0.f;

    float4 xr[4];

    auto ldg_x = [&](int k0) {
#pragma unroll
        for (int it = 0; it < 4; ++it) {
            const int e4 = tid + it * 512;
            const int m = e4 >> 4, k4 = (e4 & 15) * 4;
            xr[it] = *reinterpret_cast<const float4*>(
                &x[(size_t)(row0 + m) * kC + k0 + k4]);
        }
    };
    auto cp_w = [&](int ch, char* buf) {
        const char* wh = (const char*)g_WFh + (size_t)ch * 24576;
#pragma unroll
        for (int it = 0; it < 3; ++it) {
            const int off = (tid + it * 512) * 16;
            CP_ASYNC16(smem_addr(buf + G_BH + off), wh + off);
        }
    };
    auto sts_x = [&](char* buf) {
        uint32_t* A = reinterpret_cast<uint32_t*>(buf + G_AH);
#pragma unroll
        for (int it = 0; it < 4; ++it) {
            const int e4 = tid + it * 512;
            const int m = e4 >> 4, k4 = (e4 & 15) * 4;
            const float4 v = xr[it];
            const int mb = m >> 4;
            const int ks = k4 >> 4;
            const int j  = ((k4 >> 3) & 1) * 2 + ((m >> 3) & 1);
            const int l0 = (m & 7) * 4 + ((k4 >> 1) & 3);
            const int base = (mb * 4 + ks) * 128 + j;
            A[base + l0 * 4]       = f2pack(v.x, v.y);
            A[base + (l0 + 1) * 4] = f2pack(v.z, v.w);
        }
    };

    ldg_x(0);
    cp_w(0, sm);
    CP_COMMIT();
    sts_x(sm);
    CP_WAIT0();
    __syncthreads();

    for (int ch = 0; ch < 16; ++ch) {
        char* buf = sm + (ch & 1) * G_BUF;
        if (ch + 1 < 16) {
            ldg_x((ch + 1) * 64);
            cp_w(ch + 1, sm + ((ch + 1) & 1) * G_BUF);
        }
        CP_COMMIT();

        const char* Ab = buf + G_AH + mb0 * 2048 + lane * 16;
        const char* Bh = buf + G_BH + nb0 * 256 + lane * 8;

#pragma unroll
        for (int ks = 0; ks < 4; ++ks) {
            uint4 ah4[2];
#pragma unroll
            for (int mf = 0; mf < 2; ++mf) {
                const int aoff = (mf * 4 + ks) * 512;
                ah4[mf] = *reinterpret_cast<const uint4*>(Ab + aoff);
            }
#pragma unroll
            for (int nf = 0; nf < 6; ++nf) {
                const int boff = (ks * 24 + nf) * 256;
                uint2 bh = *reinterpret_cast<const uint2*>(Bh + boff);
#pragma unroll
                for (int mf = 0; mf < 2; ++mf) {
                    mma16816(acc[mf][nf], reinterpret_cast<uint32_t*>(&ah4[mf]),
                             reinterpret_cast<uint32_t*>(&bh));
                }
            }
        }

        if (ch + 1 < 16) {
            __syncthreads();
            sts_x(sm + ((ch + 1) & 1) * G_BUF);
            CP_WAIT0();
            __syncthreads();
        }
    }

    // ---- epilogue ----
    uint32_t* KFh = reinterpret_cast<uint32_t*>(g_KFh);
    // V^T fragment-major half-store (same index math as the old vtrans kernel)
    auto vstore = [&](int rga, int hh, float val) {
        const int batch = rga >> 11;
        const int jt = (rga >> 6) & 31;
        const int t = rga & 63;
        const int ks = t >> 4, sel = (t >> 3) & 1;
        const int lane2 = (hh & 7) * 4 + ((t >> 1) & 3);
        const int widx = (((batch * 32 + jt) * 32) + (hh >> 3) * 4 + ks) * 64
                         + lane2 * 2 + sel;
        g_VFh[widx * 2 + (t & 1)] = __float2half(val);
    };
#pragma unroll
    for (int mf = 0; mf < 2; ++mf) {
        const int rg = row0 + m0 + mf * 16 + r1;
#pragma unroll
        for (int nf = 0; nf < 6; ++nf) {
            const int col = n0 + nf * 8 + kq * 2;
            const int mat = col >> 6, h = col & 63;
            const float* bias = (mat == 0) ? bq : (mat == 1) ? bk : bv;
            const float b0 = bias[h], b1 = bias[h + 1];
            const float v00 = acc[mf][nf][0] + b0;
            const float v01 = acc[mf][nf][1] + b1;
            const float v10 = acc[mf][nf][2] + b0;
            const float v11 = acc[mf][nf][3] + b1;
            if (mat == 2) {
                vstore(rg, h, v00);
                vstore(rg, h + 1, v01);
                vstore(rg + 8, h, v10);
                vstore(rg + 8, h + 1, v11);
            } else if (mat == 1) {
                const int batch = rg >> 11, tok = rg & 2047;
                KFh[bfrag_idx(batch, tok, h)]     = f2pack(v00, v01);
                KFh[bfrag_idx(batch, tok + 8, h)] = f2pack(v10, v11);
            } else {
                const float scl = 0.125f * 1.44269504f;
                *reinterpret_cast<uint32_t*>(g_Qh + (size_t)rg * kH + h) =
                    f2pack(v00 * scl, v01 * scl);
                *reinterpret_cast<uint32_t*>(g_Qh + (size_t)(rg + 8) * kH + h) =
                    f2pack(v10 * scl, v11 * scl);
            }
        }
    }
}

// ---------------------------------------------------------------------------
// Causal flash attention: BM=64, BN=128 (2 fragment blobs per iteration),
// 4 warps, fragment-major smem, QK & PV single x single, exp2 softmax,
// Q in registers, cp.async double buffer. Softmax passes halved vs BN=64.
// ---------------------------------------------------------------------------
__global__ __launch_bounds__(128, 3)
void attn_mma_kernel(float* __restrict__ out) {
    extern __shared__ __align__(16) char sma[];

    const int tid  = threadIdx.x;
    const int lane = tid & 31;
    const int w    = tid >> 5;
    const int b    = blockIdx.x & 15;
    const int qt   = (kQT - 1) - (blockIdx.x >> 4);   // heaviest first
    const int q0   = qt * 64;
    const int m0w  = w * 16;
    const int r1   = lane >> 2;
    const int kq   = lane & 3;
    const int njt2 = (qt >> 1) + 1;   // 128-token iterations

    uint32_t qhi[4][4];
    {
        const uint32_t* qh =
            reinterpret_cast<const uint32_t*>(g_Qh + ((size_t)b * kT + q0) * kH);
        const int rA = (m0w + r1) * 32, rB = rA + 8 * 32;
#pragma unroll
        for (int ks = 0; ks < 4; ++ks) {
            const int c0 = ks * 8 + kq;
            qhi[ks][0] = qh[rA + c0];
            qhi[ks][1] = qh[rB + c0];
            qhi[ks][2] = qh[rA + c0 + 4];
            qhi[ks][3] = qh[rB + c0 + 4];
        }
    }

    auto stage = [&](int it, char* buf) {
        const size_t base = ((size_t)b * 32 + it * 2) * 8192;  // two 8KB blobs
        const char* kh = (const char*)g_KFh + base;
        const char* vh = (const char*)g_VFh + base;
#pragma unroll
        for (int i = 0; i < 8; ++i) {
            const int off = (tid + i * 128) * 16;              // 16 KB each
            CP_ASYNC16(smem_addr(buf + BK_KH + off), kh + off);
            CP_ASYNC16(smem_addr(buf + BK_VH + off), vh + off);
        }
    };

    float o[8][4];
#pragma unroll
    for (int nf = 0; nf < 8; ++nf)
#pragma unroll
        for (int c = 0; c < 4; ++c) o[nf][c] = 0.f;
    float mrow[2] = {-1e30f, -1e30f};
    float lrow[2] = {0.f, 0.f};

    stage(0, sma);
    CP_COMMIT();

    for (int it = 0; it < njt2; ++it) {
        if (it + 1 < njt2) stage(it + 1, sma + ((it + 1) & 1) * ABUFSZ);
        CP_COMMIT();
        CP_WAIT1();
        __syncthreads();

        char* buf = sma + (it & 1) * ABUFSZ;
        const char* Kh = buf + BK_KH + lane * 8;
        const char* Vh = buf + BK_VH + lane * 8;

        // ---- S = Q K^T over 128 tokens (16 token-block frags) ----
        float s[16][4];
#pragma unroll
        for (int nf = 0; nf < 16; ++nf)
#pragma unroll
            for (int c = 0; c < 4; ++c) s[nf][c] = 0.f;

#pragma unroll
        for (int ks = 0; ks < 4; ++ks) {
#pragma unroll
            for (int nf = 0; nf < 16; ++nf) {
                const int boff = (nf >> 3) * 8192 + (((nf & 7) * 4 + ks)) * 256;
                uint2 bh = *reinterpret_cast<const uint2*>(Kh + boff);
                mma16816(s[nf], qhi[ks], reinterpret_cast<uint32_t*>(&bh));
            }
        }

        // ---- causal mask (last iteration only) + online softmax (exp2) ----
        if (it == njt2 - 1) {
            const int qg1 = q0 + m0w + r1;
            const int qg2 = qg1 + 8;
#pragma unroll
            for (int nf = 0; nf < 16; ++nf) {
                const int kg0 = it * 128 + nf * 8 + kq * 2;
                s[nf][0] = (kg0     <= qg1) ? s[nf][0] : -1e30f;
                s[nf][1] = (kg0 + 1 <= qg1) ? s[nf][1] : -1e30f;
                s[nf][2] = (kg0     <= qg2) ? s[nf][2] : -1e30f;
                s[nf][3] = (kg0 + 1 <= qg2) ? s[nf][3] : -1e30f;
            }
        }
        float mx1 = -1e30f, mx2 = -1e30f;
#pragma unroll
        for (int nf = 0; nf < 16; ++nf) {
            mx1 = fmaxf(mx1, fmaxf(s[nf][0], s[nf][1]));
            mx2 = fmaxf(mx2, fmaxf(s[nf][2], s[nf][3]));
        }
        mx1 = fmaxf(mx1, __shfl_xor_sync(0xffffffffu, mx1, 1));
        mx1 = fmaxf(mx1, __shfl_xor_sync(0xffffffffu, mx1, 2));
        mx2 = fmaxf(mx2, __shfl_xor_sync(0xffffffffu, mx2, 1));
        mx2 = fmaxf(mx2, __shfl_xor_sync(0xffffffffu, mx2, 2));

        const float mn1 = fmaxf(mrow[0], mx1);
        const float mn2 = fmaxf(mrow[1], mx2);
        const float a1 = exp2f(mrow[0] - mn1);
        const float a2 = exp2f(mrow[1] - mn2);
        mrow[0] = mn1; mrow[1] = mn2;

        float rs1 = 0.f, rs2 = 0.f;
#pragma unroll
        for (int nf = 0; nf < 16; ++nf) {
            s[nf][0] = exp2f(s[nf][0] - mn1);
            s[nf][1] = exp2f(s[nf][1] - mn1);
            s[nf][2] = exp2f(s[nf][2] - mn2);
            s[nf][3] = exp2f(s[nf][3] - mn2);
            rs1 += s[nf][0] + s[nf][1];
            rs2 += s[nf][2] + s[nf][3];
        }
        rs1 += __shfl_xor_sync(0xffffffffu, rs1, 1);
        rs1 += __shfl_xor_sync(0xffffffffu, rs1, 2);
        rs2 += __shfl_xor_sync(0xffffffffu, rs2, 1);
        rs2 += __shfl_xor_sync(0xffffffffu, rs2, 2);
        lrow[0] = lrow[0] * a1 + rs1;
        lrow[1] = lrow[1] * a2 + rs2;
#pragma unroll
        for (int nf = 0; nf < 8; ++nf) {
            o[nf][0] *= a1; o[nf][1] *= a1;
            o[nf][2] *= a2; o[nf][3] *= a2;
        }

        // ---- O += P V over 128 tokens (8 k-steps) ----
#pragma unroll
        for (int ks = 0; ks < 8; ++ks) {
            uint32_t pah[4];
            const float* s0 = s[2 * ks];
            const float* s1 = s[2 * ks + 1];
            pah[0] = f2pack(s0[0], s0[1]);
            pah[1] = f2pack(s0[2], s0[3]);
            pah[2] = f2pack(s1[0], s1[1]);
            pah[3] = f2pack(s1[2], s1[3]);
#pragma unroll
            for (int nfh = 0; nfh < 8; ++nfh) {
                const int boff = (ks >> 2) * 8192 + (nfh * 4 + (ks & 3)) * 256;
                uint2 vh = *reinterpret_cast<const uint2*>(Vh + boff);
                mma16816(o[nfh], pah, reinterpret_cast<uint32_t*>(&vh));
            }
        }
        __syncthreads();   // readers done before buffer re-staged
    }

    // ---- epilogue: normalize + store ----
    const float inv1 = 1.0f / lrow[0];
    const float inv2 = 1.0f / lrow[1];
    float* og = out + ((size_t)b * kT + q0 + m0w) * kH;
#pragma unroll
    for (int nf = 0; nf < 8; ++nf) {
        const int col = nf * 8 + kq * 2;
        float2 v0, v1;
        v0.x = o[nf][0] * inv1; v0.y = o[nf][1] * inv1;
        v1.x = o[nf][2] * inv2; v1.y = o[nf][3] * inv2;
        *reinterpret_cast<float2*>(&og[r1 * kH + col]) = v0;
        *reinterpret_cast<float2*>(&og[(r1 + 8) * kH + col]) = v1;
    }
}

// ---------------------------------------------------------------------------
extern "C" void kernel_launch(void* const* d_in, const int* in_sizes, int n_in,
                              void* d_out, int out_size) {
    (void)in_sizes; (void)n_in; (void)out_size;
    const float* x  = (const float*)d_in[0];
    const float* Wq = (const float*)d_in[1];
    const float* bq = (const float*)d_in[2];
    const float* Wk = (const float*)d_in[3];
    const float* bk = (const float*)d_in[4];
    const float* Wv = (const float*)d_in[5];
    const float* bv = (const float*)d_in[6];
    float* out = (float*)d_out;

    wprep_kernel<<<384, 256>>>(Wq, Wk, Wv);

    cudaFuncSetAttribute(qkv_mma_kernel, cudaFuncAttributeMaxDynamicSharedMemorySize,
                         QKV_SMEM);
    qkv_mma_kernel<<<kRows / 128, 512, QKV_SMEM>>>(x, bq, bk, bv);

    cudaFuncSetAttribute(attn_mma_kernel, cudaFuncAttributeMaxDynamicSharedMemorySize,
                         ATTN_SMEM);
    attn_mma_kernel<<<kB * kQT, 128, ATTN_SMEM>>>(out);
}

// round 15
// speedup vs baseline: 2.5499x; 1.0144x over previous
#include <cuda_runtime.h>
#include <cuda_fp16.h>
#include <cstdint>

// ---------------------------------------------------------------------------
// Problem constants
// ---------------------------------------------------------------------------
namespace {
constexpr int kB = 16;
constexpr int kT = 2048;
constexpr int kC = 1024;
constexpr int kH = 64;
constexpr int kRows = kB * kT;     // 32768
constexpr int kQT = kT / 64;       // 32 q-tiles per batch

// QKV GEMM smem (bytes): fragment-major, K-chunk 64, double buffer.
// CTA tile 64 x 192, 256 threads, occupancy 2.
constexpr int G_AH = 0;            // 16 A-frags x 512B (X single)
constexpr int G_BH = 8192;         // 96 B-frags x 256B (W single)
constexpr int G_BUF = 32768;
constexpr int QKV_SMEM = 2 * G_BUF;          // 65536 -> 2 CTAs/SM

// Attention smem (bytes): BN=128 (two 64-token fragment blobs per buffer)
constexpr int BK_KH = 0;           // K: 16KB
constexpr int BK_VH = 16384;       // V: 16KB
constexpr int ABUFSZ = 32768;
constexpr int ATTN_SMEM = 2 * ABUFSZ;        // 65536
}

// Scratch (__device__ globals: allocation-free)
__device__ __half g_Qh[kRows * kH];                 // Q single fp16 (pre-scaled)
__device__ __half g_KFh[kRows * kH];                // K single, fragment-major
__device__ __half g_VFh[kB * kH * kT];              // V^T single, fragment-major
__device__ __half g_WFh[192 * 1024];                // W single, fragment-major

// ---------------------------------------------------------------------------
// PTX helpers (baseline sm_80+ — survive compute_103 lowering)
// ---------------------------------------------------------------------------
__device__ __forceinline__ void mma16816(float* d, const uint32_t* a,
                                         const uint32_t* b) {
    asm volatile(
        "mma.sync.aligned.m16n8k16.row.col.f32.f16.f16.f32 "
        "{%0,%1,%2,%3}, {%4,%5,%6,%7}, {%8,%9}, {%0,%1,%2,%3};"
        : "+f"(d[0]), "+f"(d[1]), "+f"(d[2]), "+f"(d[3])
        : "r"(a[0]), "r"(a[1]), "r"(a[2]), "r"(a[3]), "r"(b[0]), "r"(b[1]));
}
__device__ __forceinline__ uint32_t f2pack(float lo, float hi) {
    uint32_t r;
    asm("cvt.rn.f16x2.f32 %0, %1, %2;" : "=r"(r) : "f"(hi), "f"(lo));
    return r;
}
__device__ __forceinline__ uint32_t smem_addr(const void* p) {
    return (uint32_t)__cvta_generic_to_shared(p);
}
#define CP_ASYNC16(dst, src) \
    asm volatile("cp.async.cg.shared.global [%0], [%1], 16;" \
                 :: "r"(dst), "l"(src))
#define CP_COMMIT() asm volatile("cp.async.commit_group;" ::: "memory")
#define CP_WAIT0()  asm volatile("cp.async.wait_group 0;" ::: "memory")
#define CP_WAIT1()  asm volatile("cp.async.wait_group 1;" ::: "memory")

// Fragment-major u32-word index for attention K (B-operand view)
__device__ __forceinline__ int bfrag_idx(int batch, int tok, int h) {
    const int jt = tok >> 6, nf = (tok >> 3) & 7, r = tok & 7;
    const int ks = h >> 4, sel = (h >> 3) & 1, q2 = (h >> 1) & 3;
    return (((batch * 32 + jt) * 32) + nf * 4 + ks) * 64 + (r * 4 + q2) * 2 + sel;
}

// ---------------------------------------------------------------------------
// Prep: W -> fragment-major single fp16.
// ---------------------------------------------------------------------------
__global__ void wprep_kernel(const float* __restrict__ Wq,
                             const float* __restrict__ Wk,
                             const float* __restrict__ Wv) {
    const int idx = blockIdx.x * 256 + threadIdx.x;   // < 98304
    const int frag = idx >> 6, ww = idx & 63;
    const int r = ww >> 3, q2 = (ww >> 1) & 3, sel = ww & 1;
    const int ks_g = frag / 24, nb = frag % 24;
    const int n = nb * 8 + r;
    const int k = ks_g * 16 + sel * 8 + q2 * 2;
    const int mat = n >> 6, col = n & 63;
    const float* W = (mat == 0) ? Wq : (mat == 1) ? Wk : Wv;
    const float v0 = W[k * 64 + col];
    const float v1 = W[(k + 1) * 64 + col];
    reinterpret_cast<uint32_t*>(g_WFh)[idx] = f2pack(v0, v1);
}

// ---------------------------------------------------------------------------
// QKV GEMM: fp16 HMMA, X single x W single, CTA 64x192, 256 threads, occ 2.
// Fragment-major smem, K-chunk 64, double buffer. Epilogue:
//   Q single fp16 (pre-scaled 0.125*log2e), K fragment-major single,
//   V^T fragment-major single fp16 (direct scatter).
// ---------------------------------------------------------------------------
__global__ __launch_bounds__(256, 2)
void qkv_mma_kernel(const float* __restrict__ x,
                    const float* __restrict__ bq,
                    const float* __restrict__ bk,
                    const float* __restrict__ bv) {
    extern __shared__ __align__(16) char sm[];
    const int tid  = threadIdx.x;
    const int lane = tid & 31;
    const int w    = tid >> 5;
    const int m0   = (w >> 2) * 32;   // 2 warp-rows
    const int n0   = (w & 3) * 48;    // 4 warp-cols
    const int mb0  = (w >> 2) * 2;
    const int nb0  = (w & 3) * 6;
    const int r1   = lane >> 2;
    const int kq   = lane & 3;
    const int row0 = blockIdx.x * 64;

    float acc[2][6][4];
#pragma unroll
    for (int mf = 0; mf < 2; ++mf)
#pragma unroll
        for (int nf = 0; nf < 6; ++nf)
#pragma unroll
            for (int i = 0; i < 4; ++i) acc[mf][nf][i] = 0.f;

    float4 xr[4];

    auto ldg_x = [&](int k0) {
#pragma unroll
        for (int it = 0; it < 4; ++it) {
            const int e4 = tid + it * 256;          // 1024 float4 = 64 x 16
            const int m = e4 >> 4, k4 = (e4 & 15) * 4;
            xr[it] = *reinterpret_cast<const float4*>(
                &x[(size_t)(row0 + m) * kC + k0 + k4]);
        }
    };
    auto cp_w = [&](int ch, char* buf) {
        const char* wh = (const char*)g_WFh + (size_t)ch * 24576;
#pragma unroll
        for (int it = 0; it < 6; ++it) {
            const int off = (tid + it * 256) * 16;
            CP_ASYNC16(smem_addr(buf + G_BH + off), wh + off);
        }
    };
    auto sts_x = [&](char* buf) {
        uint32_t* A = reinterpret_cast<uint32_t*>(buf + G_AH);
#pragma unroll
        for (int it = 0; it < 4; ++it) {
            const int e4 = tid + it * 256;
            const int m = e4 >> 4, k4 = (e4 & 15) * 4;
            const float4 v = xr[it];
            const int mb = m >> 4;                  // 0..3
            const int ks = k4 >> 4;
            const int j  = ((k4 >> 3) & 1) * 2 + ((m >> 3) & 1);
            const int l0 = (m & 7) * 4 + ((k4 >> 1) & 3);
            const int base = (mb * 4 + ks) * 128 + j;
            A[base + l0 * 4]       = f2pack(v.x, v.y);
            A[base + (l0 + 1) * 4] = f2pack(v.z, v.w);
        }
    };

    ldg_x(0);
    cp_w(0, sm);
    CP_COMMIT();
    sts_x(sm);
    CP_WAIT0();
    __syncthreads();

    for (int ch = 0; ch < 16; ++ch) {
        char* buf = sm + (ch & 1) * G_BUF;
        if (ch + 1 < 16) {
            ldg_x((ch + 1) * 64);
            cp_w(ch + 1, sm + ((ch + 1) & 1) * G_BUF);
        }
        CP_COMMIT();

        const char* Ab = buf + G_AH + mb0 * 2048 + lane * 16;
        const char* Bh = buf + G_BH + nb0 * 256 + lane * 8;

#pragma unroll
        for (int ks = 0; ks < 4; ++ks) {
            uint4 ah4[2];
#pragma unroll
            for (int mf = 0; mf < 2; ++mf) {
                const int aoff = (mf * 4 + ks) * 512;
                ah4[mf] = *reinterpret_cast<const uint4*>(Ab + aoff);
            }
#pragma unroll
            for (int nf = 0; nf < 6; ++nf) {
                const int boff = (ks * 24 + nf) * 256;
                uint2 bh = *reinterpret_cast<const uint2*>(Bh + boff);
#pragma unroll
                for (int mf = 0; mf < 2; ++mf) {
                    mma16816(acc[mf][nf], reinterpret_cast<uint32_t*>(&ah4[mf]),
                             reinterpret_cast<uint32_t*>(&bh));
                }
            }
        }

        if (ch + 1 < 16) {
            __syncthreads();
            sts_x(sm + ((ch + 1) & 1) * G_BUF);
            CP_WAIT0();
            __syncthreads();
        }
    }

    // ---- epilogue ----
    uint32_t* KFh = reinterpret_cast<uint32_t*>(g_KFh);
    auto vstore = [&](int rga, int hh, float val) {
        const int batch = rga >> 11;
        const int jt = (rga >> 6) & 31;
        const int t = rga & 63;
        const int ks = t >> 4, sel = (t >> 3) & 1;
        const int lane2 = (hh & 7) * 4 + ((t >> 1) & 3);
        const int widx = (((batch * 32 + jt) * 32) + (hh >> 3) * 4 + ks) * 64
                         + lane2 * 2 + sel;
        g_VFh[widx * 2 + (t & 1)] = __float2half(val);
    };
#pragma unroll
    for (int mf = 0; mf < 2; ++mf) {
        const int rg = row0 + m0 + mf * 16 + r1;
#pragma unroll
        for (int nf = 0; nf < 6; ++nf) {
            const int col = n0 + nf * 8 + kq * 2;
            const int mat = col >> 6, h = col & 63;
            const float* bias = (mat == 0) ? bq : (mat == 1) ? bk : bv;
            const float b0 = bias[h], b1 = bias[h + 1];
            const float v00 = acc[mf][nf][0] + b0;
            const float v01 = acc[mf][nf][1] + b1;
            const float v10 = acc[mf][nf][2] + b0;
            const float v11 = acc[mf][nf][3] + b1;
            if (mat == 2) {
                vstore(rg, h, v00);
                vstore(rg, h + 1, v01);
                vstore(rg + 8, h, v10);
                vstore(rg + 8, h + 1, v11);
            } else if (mat == 1) {
                const int batch = rg >> 11, tok = rg & 2047;
                KFh[bfrag_idx(batch, tok, h)]     = f2pack(v00, v01);
                KFh[bfrag_idx(batch, tok + 8, h)] = f2pack(v10, v11);
            } else {
                const float scl = 0.125f * 1.44269504f;
                *reinterpret_cast<uint32_t*>(g_Qh + (size_t)rg * kH + h) =
                    f2pack(v00 * scl, v01 * scl);
                *reinterpret_cast<uint32_t*>(g_Qh + (size_t)(rg + 8) * kH + h) =
                    f2pack(v10 * scl, v11 * scl);
            }
        }
    }
}

// ---------------------------------------------------------------------------
// Causal flash attention (R14-validated, ~44us): BM=64, BN=128, 4 warps,
// fragment-major smem, QK & PV single x single, exp2 softmax, Q in regs,
// cp.async double buffer.
// ---------------------------------------------------------------------------
__global__ __launch_bounds__(128, 3)
void attn_mma_kernel(float* __restrict__ out) {
    extern __shared__ __align__(16) char sma[];

    const int tid  = threadIdx.x;
    const int lane = tid & 31;
    const int w    = tid >> 5;
    const int b    = blockIdx.x & 15;
    const int qt   = (kQT - 1) - (blockIdx.x >> 4);   // heaviest first
    const int q0   = qt * 64;
    const int m0w  = w * 16;
    const int r1   = lane >> 2;
    const int kq   = lane & 3;
    const int njt2 = (qt >> 1) + 1;   // 128-token iterations

    uint32_t qhi[4][4];
    {
        const uint32_t* qh =
            reinterpret_cast<const uint32_t*>(g_Qh + ((size_t)b * kT + q0) * kH);
        const int rA = (m0w + r1) * 32, rB = rA + 8 * 32;
#pragma unroll
        for (int ks = 0; ks < 4; ++ks) {
            const int c0 = ks * 8 + kq;
            qhi[ks][0] = qh[rA + c0];
            qhi[ks][1] = qh[rB + c0];
            qhi[ks][2] = qh[rA + c0 + 4];
            qhi[ks][3] = qh[rB + c0 + 4];
        }
    }

    auto stage = [&](int it, char* buf) {
        const size_t base = ((size_t)b * 32 + it * 2) * 8192;  // two 8KB blobs
        const char* kh = (const char*)g_KFh + base;
        const char* vh = (const char*)g_VFh + base;
#pragma unroll
        for (int i = 0; i < 8; ++i) {
            const int off = (tid + i * 128) * 16;              // 16 KB each
            CP_ASYNC16(smem_addr(buf + BK_KH + off), kh + off);
            CP_ASYNC16(smem_addr(buf + BK_VH + off), vh + off);
        }
    };

    float o[8][4];
#pragma unroll
    for (int nf = 0; nf < 8; ++nf)
#pragma unroll
        for (int c = 0; c < 4; ++c) o[nf][c] = 0.f;
    float mrow[2] = {-1e30f, -1e30f};
    float lrow[2] = {0.f, 0.f};

    stage(0, sma);
    CP_COMMIT();

    for (int it = 0; it < njt2; ++it) {
        if (it + 1 < njt2) stage(it + 1, sma + ((it + 1) & 1) * ABUFSZ);
        CP_COMMIT();
        CP_WAIT1();
        __syncthreads();

        char* buf = sma + (it & 1) * ABUFSZ;
        const char* Kh = buf + BK_KH + lane * 8;
        const char* Vh = buf + BK_VH + lane * 8;

        // ---- S = Q K^T over 128 tokens ----
        float s[16][4];
#pragma unroll
        for (int nf = 0; nf < 16; ++nf)
#pragma unroll
            for (int c = 0; c < 4; ++c) s[nf][c] = 0.f;

#pragma unroll
        for (int ks = 0; ks < 4; ++ks) {
#pragma unroll
            for (int nf = 0; nf < 16; ++nf) {
                const int boff = (nf >> 3) * 8192 + (((nf & 7) * 4 + ks)) * 256;
                uint2 bh = *reinterpret_cast<const uint2*>(Kh + boff);
                mma16816(s[nf], qhi[ks], reinterpret_cast<uint32_t*>(&bh));
            }
        }

        // ---- causal mask (last iteration only) + online softmax (exp2) ----
        if (it == njt2 - 1) {
            const int qg1 = q0 + m0w + r1;
            const int qg2 = qg1 + 8;
#pragma unroll
            for (int nf = 0; nf < 16; ++nf) {
                const int kg0 = it * 128 + nf * 8 + kq * 2;
                s[nf][0] = (kg0     <= qg1) ? s[nf][0] : -1e30f;
                s[nf][1] = (kg0 + 1 <= qg1) ? s[nf][1] : -1e30f;
                s[nf][2] = (kg0     <= qg2) ? s[nf][2] : -1e30f;
                s[nf][3] = (kg0 + 1 <= qg2) ? s[nf][3] : -1e30f;
            }
        }
        float mx1 = -1e30f, mx2 = -1e30f;
#pragma unroll
        for (int nf = 0; nf < 16; ++nf) {
            mx1 = fmaxf(mx1, fmaxf(s[nf][0], s[nf][1]));
            mx2 = fmaxf(mx2, fmaxf(s[nf][2], s[nf][3]));
        }
        mx1 = fmaxf(mx1, __shfl_xor_sync(0xffffffffu, mx1, 1));
        mx1 = fmaxf(mx1, __shfl_xor_sync(0xffffffffu, mx1, 2));
        mx2 = fmaxf(mx2, __shfl_xor_sync(0xffffffffu, mx2, 1));
        mx2 = fmaxf(mx2, __shfl_xor_sync(0xffffffffu, mx2, 2));

        const float mn1 = fmaxf(mrow[0], mx1);
        const float mn2 = fmaxf(mrow[1], mx2);
        const float a1 = exp2f(mrow[0] - mn1);
        const float a2 = exp2f(mrow[1] - mn2);
        mrow[0] = mn1; mrow[1] = mn2;

        float rs1 = 0.f, rs2 = 0.f;
#pragma unroll
        for (int nf = 0; nf < 16; ++nf) {
            s[nf][0] = exp2f(s[nf][0] - mn1);
            s[nf][1] = exp2f(s[nf][1] - mn1);
            s[nf][2] = exp2f(s[nf][2] - mn2);
            s[nf][3] = exp2f(s[nf][3] - mn2);
            rs1 += s[nf][0] + s[nf][1];
            rs2 += s[nf][2] + s[nf][3];
        }
        rs1 += __shfl_xor_sync(0xffffffffu, rs1, 1);
        rs1 += __shfl_xor_sync(0xffffffffu, rs1, 2);
        rs2 += __shfl_xor_sync(0xffffffffu, rs2, 1);
        rs2 += __shfl_xor_sync(0xffffffffu, rs2, 2);
        lrow[0] = lrow[0] * a1 + rs1;
        lrow[1] = lrow[1] * a2 + rs2;
#pragma unroll
        for (int nf = 0; nf < 8; ++nf) {
            o[nf][0] *= a1; o[nf][1] *= a1;
            o[nf][2] *= a2; o[nf][3] *= a2;
        }

        // ---- O += P V over 128 tokens (8 k-steps) ----
#pragma unroll
        for (int ks = 0; ks < 8; ++ks) {
            uint32_t pah[4];
            const float* s0 = s[2 * ks];
            const float* s1 = s[2 * ks + 1];
            pah[0] = f2pack(s0[0], s0[1]);
            pah[1] = f2pack(s0[2], s0[3]);
            pah[2] = f2pack(s1[0], s1[1]);
            pah[3] = f2pack(s1[2], s1[3]);
#pragma unroll
            for (int nfh = 0; nfh < 8; ++nfh) {
                const int boff = (ks >> 2) * 8192 + (nfh * 4 + (ks & 3)) * 256;
                uint2 vh = *reinterpret_cast<const uint2*>(Vh + boff);
                mma16816(o[nfh], pah, reinterpret_cast<uint32_t*>(&vh));
            }
        }
        __syncthreads();
    }

    // ---- epilogue: normalize + store ----
    const float inv1 = 1.0f / lrow[0];
    const float inv2 = 1.0f / lrow[1];
    float* og = out + ((size_t)b * kT + q0 + m0w) * kH;
#pragma unroll
    for (int nf = 0; nf < 8; ++nf) {
        const int col = nf * 8 + kq * 2;
        float2 v0, v1;
        v0.x = o[nf][0] * inv1; v0.y = o[nf][1] * inv1;
        v1.x = o[nf][2] * inv2; v1.y = o[nf][3] * inv2;
        *reinterpret_cast<float2*>(&og[r1 * kH + col]) = v0;
        *reinterpret_cast<float2*>(&og[(r1 + 8) * kH + col]) = v1;
    }
}

// ---------------------------------------------------------------------------
extern "C" void kernel_launch(void* const* d_in, const int* in_sizes, int n_in,
                              void* d_out, int out_size) {
    (void)in_sizes; (void)n_in; (void)out_size;
    const float* x  = (const float*)d_in[0];
    const float* Wq = (const float*)d_in[1];
    const float* bq = (const float*)d_in[2];
    const float* Wk = (const float*)d_in[3];
    const float* bk = (const float*)d_in[4];
    const float* Wv = (const float*)d_in[5];
    const float* bv = (const float*)d_in[6];
    float* out = (float*)d_out;

    wprep_kernel<<<384, 256>>>(Wq, Wk, Wv);

    cudaFuncSetAttribute(qkv_mma_kernel, cudaFuncAttributeMaxDynamicSharedMemorySize,
                         QKV_SMEM);
    qkv_mma_kernel<<<kRows / 64, 256, QKV_SMEM>>>(x, bq, bk, bv);

    cudaFuncSetAttribute(attn_mma_kernel, cudaFuncAttributeMaxDynamicSharedMemorySize,
                         ATTN_SMEM);
    attn_mma_kernel<<<kB * kQT, 128, ATTN_SMEM>>>(out);
}